// round 5
// baseline (speedup 1.0000x reference)
#include <cuda_runtime.h>
#include <cuda_bf16.h>
#include <cstdint>
#include <math.h>

// Problem constants
#define NTOK  65536
#define EFULL 512
#define HIDC  256
#define NGR   4096
#define GSZ   16
#define KPAD1 544          // 514 padded to %32

// ---------------- scratch (__device__ globals) ----------------
__device__ __nv_bfloat16 g_peAh[(size_t)NTOK * KPAD1];
__device__ __nv_bfloat16 g_peAl[(size_t)NTOK * KPAD1];
__device__ __nv_bfloat16 g_h1h[(size_t)NTOK * HIDC];
__device__ __nv_bfloat16 g_h1l[(size_t)NTOK * HIDC];
__device__ __nv_bfloat16 g_h2h[(size_t)NTOK * HIDC];
__device__ __nv_bfloat16 g_h2l[(size_t)NTOK * HIDC];
__device__ __nv_bfloat16 g_key1h[(size_t)NTOK * EFULL];
__device__ __nv_bfloat16 g_key1l[(size_t)NTOK * EFULL];
__device__ float         g_qk[(size_t)NTOK * 1024];
__device__ __nv_bfloat16 g_xwh[(size_t)2 * NGR * EFULL];
__device__ __nv_bfloat16 g_xwl[(size_t)2 * NGR * EFULL];
__device__ __nv_bfloat16 g_omh[(size_t)NGR * EFULL];
__device__ __nv_bfloat16 g_oml[(size_t)NGR * EFULL];
__device__ float         g_km[(size_t)NGR * EFULL];
__device__ __nv_bfloat16 g_kmh[(size_t)NGR * EFULL];
__device__ __nv_bfloat16 g_kml[(size_t)NGR * EFULL];
__device__ __nv_bfloat16 g_hgah[(size_t)NGR * HIDC];
__device__ __nv_bfloat16 g_hgal[(size_t)NGR * HIDC];
__device__ __nv_bfloat16 g_hgbh[(size_t)NGR * HIDC];
__device__ __nv_bfloat16 g_hgbl[(size_t)NGR * HIDC];

// weight pool (split bf16). offsets in elements:
#define OW_P1W1 0                 // 256x544
#define OW_P1W2 139264            // 256x256
#define OW_P1W3 204800            // 256x256
#define OW_P1W4 270336            // 512x256
#define OW_WQK  401408            // 1024x512
#define OW_WV0  925696            // 256x512
#define OW_WV1  1056768           // 256x512
#define OW_WOUT 1187840           // 512x512
#define OW_GW1  1449984           // 256x512
#define OW_GW2  1581056           // 256x256
#define OW_GW3  1646592           // 256x256
#define OW_P2W1 1712128           // 256x512
#define OW_P2W2 1843200           // 256x256
#define OW_TOT  1908736
__device__ __nv_bfloat16 g_wph[OW_TOT];
__device__ __nv_bfloat16 g_wpl[OW_TOT];

__device__ __forceinline__ float elu1(float x) {
    return x > 0.f ? x : (expf(x) - 1.f);
}
__device__ __forceinline__ uint32_t smem_u32(const void* p) {
    uint32_t a;
    asm("{ .reg .u64 t; cvta.to.shared.u64 t, %1; cvt.u32.u64 %0, t; }" : "=r"(a) : "l"(p));
    return a;
}
__device__ __forceinline__ void ldsm4(uint32_t& r0, uint32_t& r1, uint32_t& r2, uint32_t& r3,
                                      uint32_t addr) {
    asm volatile("ldmatrix.sync.aligned.m8n8.x4.shared.b16 {%0,%1,%2,%3}, [%4];"
                 : "=r"(r0), "=r"(r1), "=r"(r2), "=r"(r3) : "r"(addr));
}
__device__ __forceinline__ void mma16816(float* c, const uint32_t* a, const uint32_t* b) {
    asm volatile("mma.sync.aligned.m16n8k16.row.col.f32.bf16.bf16.f32 "
                 "{%0,%1,%2,%3}, {%4,%5,%6,%7}, {%8,%9}, {%0,%1,%2,%3};"
                 : "+f"(c[0]), "+f"(c[1]), "+f"(c[2]), "+f"(c[3])
                 : "r"(a[0]), "r"(a[1]), "r"(a[2]), "r"(a[3]), "r"(b[0]), "r"(b[1]));
}
__device__ __forceinline__ void cvt_split2(float a, float b, uint32_t& hi, uint32_t& lo) {
    __nv_bfloat162 h = __floats2bfloat162_rn(a, b);
    float2 hf = __bfloat1622float2(h);
    __nv_bfloat162 l = __floats2bfloat162_rn(a - hf.x, b - hf.y);
    hi = *reinterpret_cast<uint32_t*>(&h);
    lo = *reinterpret_cast<uint32_t*>(&l);
}
__device__ __forceinline__ float2 bf2f2(uint32_t u) {
    return __bfloat1622float2(*reinterpret_cast<__nv_bfloat162*>(&u));
}
__device__ __forceinline__ uint32_t swz(uint32_t x) { return x ^ ((x >> 3) & 0x70); }

#define CP16(dst, src) \
    asm volatile("cp.async.cg.shared.global [%0], [%1], 16;" :: "r"(dst), "l"(src))
#define CP_COMMIT() asm volatile("cp.async.commit_group;" ::: "memory")
#define CP_WAIT1()  asm volatile("cp.async.wait_group 1;" ::: "memory")
#define CP_WAIT0()  asm volatile("cp.async.wait_group 0;" ::: "memory")

// ======== HMMA NT GEMM with pre-split bf16 operands ==========================
#define STAGE 32768
#define SMEM_TOT (3 * STAGE)

template <int EPI, bool WF32, bool WSPLIT>
__global__ __launch_bounds__(256, 2) void gemm_bf16(
    const __nv_bfloat16* __restrict__ Ah, const __nv_bfloat16* __restrict__ Al,
    const __nv_bfloat16* __restrict__ Bh, const __nv_bfloat16* __restrict__ Bl,
    const float* __restrict__ bias, float* __restrict__ C,
    __nv_bfloat16* __restrict__ Ch, __nv_bfloat16* __restrict__ Cl,
    int K, int ldC)
{
    extern __shared__ __align__(1024) char smem[];
    const uint32_t sb = smem_u32(smem);
    const int tid = threadIdx.x;
    const int lane = tid & 31;
    const int wid = tid >> 5;
    const int wm = wid & 3;
    const int wn = wid >> 2;
    const int m0 = blockIdx.y * 128;
    const int n0 = blockIdx.x * 128;

    const int nch = K >> 5;
    float acc[2][8][4] = {};

    const int lr = (tid >> 2);
    const int lc = tid & 3;

    auto issue = [&](int ci, int stg) {
        const int k0 = ci << 5;
        const uint32_t so = sb + stg * STAGE;
#pragma unroll
        for (int j = 0; j < 2; j++) {
            int r = lr + j * 64;
            uint32_t d = swz((uint32_t)(r * 64 + lc * 16));
            size_t ao = (size_t)(m0 + r) * K + k0 + lc * 8;
            size_t bo = (size_t)(n0 + r) * K + k0 + lc * 8;
            CP16(so + d,         Ah + ao);
            CP16(so + 8192 + d,  Al + ao);
            CP16(so + 16384 + d, Bh + bo);
            CP16(so + 24576 + d, Bl + bo);
        }
        CP_COMMIT();
    };

    issue(0, 0);
    if (nch > 1) issue(1, 1);

    int stg = 0;
    for (int ci = 0; ci < nch; ci++) {
        if (ci + 1 < nch) { CP_WAIT1(); } else { CP_WAIT0(); }
        __syncthreads();
        if (ci + 2 < nch) {
            int ns = stg + 2; if (ns >= 3) ns -= 3;
            issue(ci + 2, ns);
        }
        const uint32_t so = sb + stg * STAGE;

#pragma unroll
        for (int kk = 0; kk < 2; kk++) {
            uint32_t ah[2][4], al_[2][4];
            {
                int ar = lane & 15;
                int akb = kk * 32 + ((lane >> 4) * 16);
#pragma unroll
                for (int i = 0; i < 2; i++) {
                    uint32_t off = swz((uint32_t)((wm * 32 + i * 16 + ar) * 64 + akb));
                    ldsm4(ah[i][0], ah[i][1], ah[i][2], ah[i][3], so + off);
                    ldsm4(al_[i][0], al_[i][1], al_[i][2], al_[i][3], so + 8192 + off);
                }
            }
            uint32_t bh[8][2], bl_[8][2];
            {
                int br = (lane & 7) + ((lane >> 4) & 1) * 8;
                int bkb = ((lane >> 3) & 1) * 16 + kk * 32;
#pragma unroll
                for (int jf = 0; jf < 4; jf++) {
                    uint32_t off = swz((uint32_t)((wn * 64 + jf * 16 + br) * 64 + bkb));
                    uint32_t r0, r1, r2, r3;
                    ldsm4(r0, r1, r2, r3, so + 16384 + off);
                    bh[2 * jf][0] = r0; bh[2 * jf][1] = r1;
                    bh[2 * jf + 1][0] = r2; bh[2 * jf + 1][1] = r3;
                    ldsm4(r0, r1, r2, r3, so + 24576 + off);
                    bl_[2 * jf][0] = r0; bl_[2 * jf][1] = r1;
                    bl_[2 * jf + 1][0] = r2; bl_[2 * jf + 1][1] = r3;
                }
            }
#pragma unroll
            for (int i = 0; i < 2; i++)
#pragma unroll
                for (int j = 0; j < 8; j++)
                    mma16816(acc[i][j], ah[i], bh[j]);
#pragma unroll
            for (int i = 0; i < 2; i++)
#pragma unroll
                for (int j = 0; j < 8; j++)
                    mma16816(acc[i][j], ah[i], bl_[j]);
#pragma unroll
            for (int i = 0; i < 2; i++)
#pragma unroll
                for (int j = 0; j < 8; j++)
                    mma16816(acc[i][j], al_[i], bh[j]);
        }
        stg++; if (stg == 3) stg = 0;
        __syncthreads();
    }

    // ---- epilogue ----
#pragma unroll
    for (int i = 0; i < 2; i++) {
        int row = m0 + wm * 32 + i * 16 + (lane >> 2);
#pragma unroll
        for (int j = 0; j < 8; j++) {
            int col = n0 + wn * 64 + j * 8 + (lane & 3) * 2;
            float b0 = bias[col], b1 = bias[col + 1];
            float v0 = acc[i][j][0] + b0, v1 = acc[i][j][1] + b1;
            float v2 = acc[i][j][2] + b0, v3 = acc[i][j][3] + b1;
            if (EPI >= 1) { v0 = elu1(v0); v1 = elu1(v1); v2 = elu1(v2); v3 = elu1(v3); }
            if (EPI == 2) { v0 = elu1(v0); v1 = elu1(v1); v2 = elu1(v2); v3 = elu1(v3); }
            size_t o0 = (size_t)row * ldC + col;
            size_t o1 = (size_t)(row + 8) * ldC + col;
            if (WF32) {
                *reinterpret_cast<float2*>(C + o0) = make_float2(v0, v1);
                *reinterpret_cast<float2*>(C + o1) = make_float2(v2, v3);
            }
            if (WSPLIT) {
                uint32_t hi, lo;
                cvt_split2(v0, v1, hi, lo);
                *reinterpret_cast<uint32_t*>(Ch + o0) = hi;
                *reinterpret_cast<uint32_t*>(Cl + o0) = lo;
                cvt_split2(v2, v3, hi, lo);
                *reinterpret_cast<uint32_t*>(Ch + o1) = hi;
                *reinterpret_cast<uint32_t*>(Cl + o1) = lo;
            }
        }
    }
}

// ======== fused alt-value GEMM: A[r,k] = pe + km[g] - (k1h+k1l)/16 ===========
// M=NTOK, N=256, K=512 fixed. EPI=1, writes split output. SA=40 layout.
#define SA 40
#define FK 512
#define FSM_KM   0
#define FSM_AH   16384
#define FSM_AL   (16384 + 10240)
#define FSM_BH   (16384 + 20480)
#define FSM_BL   (16384 + 30720)
#define FSM_TOT  (16384 + 40960)

__global__ __launch_bounds__(256, 1) void gemm_fused_alt(
    const float* __restrict__ pe,
    const __nv_bfloat16* __restrict__ k1h, const __nv_bfloat16* __restrict__ k1l,
    const float* __restrict__ km,
    const __nv_bfloat16* __restrict__ Bh, const __nv_bfloat16* __restrict__ Bl,
    const float* __restrict__ bias,
    __nv_bfloat16* __restrict__ Ch, __nv_bfloat16* __restrict__ Cl)
{
    extern __shared__ __align__(1024) char smem[];
    float* kmS = reinterpret_cast<float*>(smem);
    const uint32_t sb = smem_u32(smem);
    const int tid = threadIdx.x;
    const int lane = tid & 31;
    const int wid = tid >> 5;
    const int wm = wid & 3;
    const int wn = wid >> 2;
    const int m0 = blockIdx.y * 128;
    const int n0 = blockIdx.x * 128;

    // cache km rows for the 8 groups in this M-tile
    const int g0 = m0 >> 4;
    for (int i = tid; i < 4096; i += 256)
        kmS[i] = km[(size_t)(g0 + (i >> 9)) * EFULL + (i & 511)];
    __syncthreads();

    float acc[2][8][4] = {};
    float4 pe_r[4];
    uint2 kh_r[4], kl_r[4], bh_r[4], bl_r[4];

    auto prefetch = [&](int k0) {
#pragma unroll
        for (int j = 0; j < 4; j++) {
            int idx = tid + j * 256;
            int r = idx >> 3, c4 = idx & 7;
            size_t ao = (size_t)(m0 + r) * FK + k0 + c4 * 4;
            size_t bo = (size_t)(n0 + r) * FK + k0 + c4 * 4;
            pe_r[j] = *reinterpret_cast<const float4*>(pe + ao);
            kh_r[j] = *reinterpret_cast<const uint2*>(k1h + ao);
            kl_r[j] = *reinterpret_cast<const uint2*>(k1l + ao);
            bh_r[j] = *reinterpret_cast<const uint2*>(Bh + bo);
            bl_r[j] = *reinterpret_cast<const uint2*>(Bl + bo);
        }
    };
    prefetch(0);

    for (int ci = 0; ci < 16; ci++) {
        const int k0 = ci << 5;
        __syncthreads();
#pragma unroll
        for (int j = 0; j < 4; j++) {
            int idx = tid + j * 256;
            int r = idx >> 3, c4 = idx & 7;
            const float4 kmv = *reinterpret_cast<const float4*>(
                &kmS[(r >> 4) * FK + k0 + c4 * 4]);
            float2 h01 = bf2f2(kh_r[j].x), h23 = bf2f2(kh_r[j].y);
            float2 l01 = bf2f2(kl_r[j].x), l23 = bf2f2(kl_r[j].y);
            float v0 = pe_r[j].x + kmv.x - (h01.x + l01.x) * 0.0625f;
            float v1 = pe_r[j].y + kmv.y - (h01.y + l01.y) * 0.0625f;
            float v2 = pe_r[j].z + kmv.z - (h23.x + l23.x) * 0.0625f;
            float v3 = pe_r[j].w + kmv.w - (h23.y + l23.y) * 0.0625f;
            uint32_t hh01, ll01, hh23, ll23;
            cvt_split2(v0, v1, hh01, ll01);
            cvt_split2(v2, v3, hh23, ll23);
            uint32_t o = (uint32_t)(r * SA + c4 * 4) * 2;
            *reinterpret_cast<uint2*>(smem + FSM_AH + o) = make_uint2(hh01, hh23);
            *reinterpret_cast<uint2*>(smem + FSM_AL + o) = make_uint2(ll01, ll23);
            *reinterpret_cast<uint2*>(smem + FSM_BH + o) = bh_r[j];
            *reinterpret_cast<uint2*>(smem + FSM_BL + o) = bl_r[j];
        }
        __syncthreads();
        if (ci < 15) prefetch(k0 + 32);

#pragma unroll
        for (int kk = 0; kk < 2; kk++) {
            uint32_t ah[2][4], al_[2][4];
            {
                int ar = lane & 15;
                int akc = ((lane >> 4) << 3) + (kk << 4);
#pragma unroll
                for (int i = 0; i < 2; i++) {
                    uint32_t off = (uint32_t)((wm * 32 + i * 16 + ar) * SA + akc) * 2;
                    ldsm4(ah[i][0], ah[i][1], ah[i][2], ah[i][3], sb + FSM_AH + off);
                    ldsm4(al_[i][0], al_[i][1], al_[i][2], al_[i][3], sb + FSM_AL + off);
                }
            }
            uint32_t bh[8][2], bl_[8][2];
            {
                int br = (lane & 7) + ((lane >> 4) & 1) * 8;
                int bkc = (((lane >> 3) & 1) << 3) + (kk << 4);
#pragma unroll
                for (int jf = 0; jf < 4; jf++) {
                    uint32_t off = (uint32_t)((wn * 64 + jf * 16 + br) * SA + bkc) * 2;
                    uint32_t r0, r1, r2, r3;
                    ldsm4(r0, r1, r2, r3, sb + FSM_BH + off);
                    bh[2 * jf][0] = r0; bh[2 * jf][1] = r1;
                    bh[2 * jf + 1][0] = r2; bh[2 * jf + 1][1] = r3;
                    ldsm4(r0, r1, r2, r3, sb + FSM_BL + off);
                    bl_[2 * jf][0] = r0; bl_[2 * jf][1] = r1;
                    bl_[2 * jf + 1][0] = r2; bl_[2 * jf + 1][1] = r3;
                }
            }
#pragma unroll
            for (int i = 0; i < 2; i++)
#pragma unroll
                for (int j = 0; j < 8; j++)
                    mma16816(acc[i][j], ah[i], bh[j]);
#pragma unroll
            for (int i = 0; i < 2; i++)
#pragma unroll
                for (int j = 0; j < 8; j++)
                    mma16816(acc[i][j], ah[i], bl_[j]);
#pragma unroll
            for (int i = 0; i < 2; i++)
#pragma unroll
                for (int j = 0; j < 8; j++)
                    mma16816(acc[i][j], al_[i], bh[j]);
        }
    }

    // ---- epilogue: elu + split store ----
#pragma unroll
    for (int i = 0; i < 2; i++) {
        int row = m0 + wm * 32 + i * 16 + (lane >> 2);
#pragma unroll
        for (int j = 0; j < 8; j++) {
            int col = n0 + wn * 64 + j * 8 + (lane & 3) * 2;
            float b0 = bias[col], b1 = bias[col + 1];
            float v0 = elu1(acc[i][j][0] + b0), v1 = elu1(acc[i][j][1] + b1);
            float v2 = elu1(acc[i][j][2] + b0), v3 = elu1(acc[i][j][3] + b1);
            size_t o0 = (size_t)row * HIDC + col;
            size_t o1 = (size_t)(row + 8) * HIDC + col;
            uint32_t hi, lo;
            cvt_split2(v0, v1, hi, lo);
            *reinterpret_cast<uint32_t*>(Ch + o0) = hi;
            *reinterpret_cast<uint32_t*>(Cl + o0) = lo;
            cvt_split2(v2, v3, hi, lo);
            *reinterpret_cast<uint32_t*>(Ch + o1) = hi;
            *reinterpret_cast<uint32_t*>(Cl + o1) = lo;
        }
    }
}

// ---------------- split kernels ----------------
__global__ __launch_bounds__(256) void split_same(
    const float* __restrict__ src, __nv_bfloat16* __restrict__ dh,
    __nv_bfloat16* __restrict__ dl, uint32_t total4)
{
    uint32_t i = blockIdx.x * 256u + threadIdx.x;
    if (i >= total4) return;
    float4 v = reinterpret_cast<const float4*>(src)[i];
    uint32_t h01, l01, h23, l23;
    cvt_split2(v.x, v.y, h01, l01);
    cvt_split2(v.z, v.w, h23, l23);
    reinterpret_cast<uint2*>(dh)[i] = make_uint2(h01, h23);
    reinterpret_cast<uint2*>(dl)[i] = make_uint2(l01, l23);
}
__global__ __launch_bounds__(256) void split_pad(
    const float* __restrict__ src, __nv_bfloat16* __restrict__ dh,
    __nv_bfloat16* __restrict__ dl, int C, int Cp, uint32_t total)
{
    uint32_t i = blockIdx.x * 256u + threadIdx.x;
    if (i >= total) return;
    uint32_t r = i / (uint32_t)Cp;
    int c = (int)(i - r * (uint32_t)Cp);
    float v = (c < C) ? src[(size_t)r * C + c] : 0.f;
    __nv_bfloat16 h = __float2bfloat16(v);
    dh[i] = h;
    dl[i] = __float2bfloat16(v - __bfloat162float(h));
}

// ---------------- attention ----------------
__global__ __launch_bounds__(256) void attn2_kernel(
    const float* __restrict__ qk,
    const __nv_bfloat16* __restrict__ xh, const __nv_bfloat16* __restrict__ xl,
    __nv_bfloat16* __restrict__ xwh, __nv_bfloat16* __restrict__ xwl)
{
    const int g = blockIdx.x;
    const int tid = threadIdx.x;
    __shared__ float qs[16][257];
    __shared__ float ks[16][257];
    __shared__ float sc[16][17];
    __shared__ float cw[16];
    const float* base = qk + (size_t)g * GSZ * 1024;
    const __nv_bfloat16* xbh = xh + (size_t)g * GSZ * 512;
    const __nv_bfloat16* xbl = xl + (size_t)g * GSZ * 512;

    for (int h = 0; h < 2; h++) {
        for (int i = tid; i < 16 * 256; i += 256) {
            int t = i >> 8, d = i & 255;
            qs[t][d] = base[t * 1024 + h * 256 + d];
            ks[t][d] = base[t * 1024 + 512 + h * 256 + d];
        }
        __syncthreads();
        {
            int tq = tid >> 4, tk = tid & 15;
            float a = 0.f;
#pragma unroll 8
            for (int d = 0; d < 256; d++) a += qs[tq][d] * ks[tk][d];
            sc[tq][tk] = a * 0.0625f;
        }
        __syncthreads();
        if (tid < 16) {
            int tq = tid;
            float mx = -1e30f;
            for (int tk = 0; tk < 16; tk++) mx = fmaxf(mx, sc[tq][tk]);
            float s = 0.f;
            for (int tk = 0; tk < 16; tk++) {
                float e = expf(sc[tq][tk] - mx);
                sc[tq][tk] = e;
                s += e;
            }
            float inv = 1.f / s;
            for (int tk = 0; tk < 16; tk++) sc[tq][tk] *= inv;
        }
        __syncthreads();
        if (tid < 16) {
            int tk = tid;
            float s = 0.f;
            for (int tq = 0; tq < 16; tq++) s += sc[tq][tk];
            cw[tk] = s * 0.0625f;
        }
        __syncthreads();
        for (int it = 0; it < 2; it++) {
            int d = tid + it * 256;
            float a = 0.f;
#pragma unroll
            for (int tk = 0; tk < 16; tk++)
                a += cw[tk] * (__bfloat162float(xbh[tk * 512 + d]) +
                               __bfloat162float(xbl[tk * 512 + d]));
            size_t o = (size_t)h * NGR * EFULL + (size_t)g * EFULL + d;
            __nv_bfloat16 hb = __float2bfloat16(a);
            xwh[o] = hb;
            xwl[o] = __float2bfloat16(a - __bfloat162float(hb));
        }
        __syncthreads();
    }
}

// ---------------- g head final ----------------
__global__ __launch_bounds__(256) void ghead4_kernel(
    const __nv_bfloat16* __restrict__ hh, const __nv_bfloat16* __restrict__ hl,
    const float* __restrict__ w, const float* __restrict__ b,
    float* __restrict__ out)
{
    int row = blockIdx.x * 8 + (threadIdx.x >> 5);
    int lane = threadIdx.x & 31;
    float acc = 0.f;
    for (int k = lane; k < 256; k += 32)
        acc += (__bfloat162float(hh[(size_t)row * 256 + k]) +
                __bfloat162float(hl[(size_t)row * 256 + k])) * w[k];
#pragma unroll
    for (int o = 16; o > 0; o >>= 1)
        acc += __shfl_xor_sync(0xffffffffu, acc, o);
    if (lane == 0) out[row] = acc + b[0];
}

// ---------------- alt_q = hp @ w3^T + b3 (256 -> 2) ----------------
__global__ __launch_bounds__(256) void altq_kernel(
    const __nv_bfloat16* __restrict__ hh, const __nv_bfloat16* __restrict__ hl,
    const float* __restrict__ w, const float* __restrict__ b,
    float* __restrict__ out)
{
    int row = blockIdx.x * 8 + (threadIdx.x >> 5);
    int lane = threadIdx.x & 31;
    float a0 = 0.f, a1 = 0.f;
    for (int k = lane; k < 256; k += 32) {
        float hv = __bfloat162float(hh[(size_t)row * 256 + k]) +
                   __bfloat162float(hl[(size_t)row * 256 + k]);
        a0 += hv * w[k];
        a1 += hv * w[256 + k];
    }
#pragma unroll
    for (int o = 16; o > 0; o >>= 1) {
        a0 += __shfl_xor_sync(0xffffffffu, a0, o);
        a1 += __shfl_xor_sync(0xffffffffu, a1, o);
    }
    if (lane == 0) {
        out[(size_t)row * 2 + 0] = a0 + b[0];
        out[(size_t)row * 2 + 1] = a1 + b[1];
    }
}

// ================================================================ host launch
extern "C" void kernel_launch(void* const* d_in, const int* in_sizes, int n_in,
                              void* d_out, int out_size)
{
    const float* pe       = (const float*)d_in[0];
    const float* peA      = (const float*)d_in[1];
    const float* attn_in_w  = (const float*)d_in[2];
    const float* attn_in_b  = (const float*)d_in[3];
    const float* attn_out_w = (const float*)d_in[4];
    const float* attn_out_b = (const float*)d_in[5];
    const float* p1w1 = (const float*)d_in[6];  const float* p1b1 = (const float*)d_in[7];
    const float* p1w2 = (const float*)d_in[8];  const float* p1b2 = (const float*)d_in[9];
    const float* p1w3 = (const float*)d_in[10]; const float* p1b3 = (const float*)d_in[11];
    const float* p1w4 = (const float*)d_in[12]; const float* p1b4 = (const float*)d_in[13];
    const float* gw1 = (const float*)d_in[14];  const float* gb1 = (const float*)d_in[15];
    const float* gw2 = (const float*)d_in[16];  const float* gb2 = (const float*)d_in[17];
    const float* gw3 = (const float*)d_in[18];  const float* gb3 = (const float*)d_in[19];
    const float* gw4 = (const float*)d_in[20];  const float* gb4 = (const float*)d_in[21];
    const float* p2w1 = (const float*)d_in[22]; const float* p2b1 = (const float*)d_in[23];
    const float* p2w2 = (const float*)d_in[24]; const float* p2b2 = (const float*)d_in[25];
    const float* p2w3 = (const float*)d_in[26]; const float* p2b3 = (const float*)d_in[27];
    float* out = (float*)d_out;

    #define SYM(T, v, s) T* v; cudaGetSymbolAddress((void**)&v, s)
    SYM(__nv_bfloat16, peAh, g_peAh); SYM(__nv_bfloat16, peAl, g_peAl);
    SYM(__nv_bfloat16, h1h, g_h1h);   SYM(__nv_bfloat16, h1l, g_h1l);
    SYM(__nv_bfloat16, h2h, g_h2h);   SYM(__nv_bfloat16, h2l, g_h2l);
    SYM(__nv_bfloat16, key1h, g_key1h); SYM(__nv_bfloat16, key1l, g_key1l);
    SYM(float, qk, g_qk);
    SYM(__nv_bfloat16, xwh, g_xwh);   SYM(__nv_bfloat16, xwl, g_xwl);
    SYM(__nv_bfloat16, omh, g_omh);   SYM(__nv_bfloat16, oml, g_oml);
    SYM(float, km, g_km);
    SYM(__nv_bfloat16, kmh, g_kmh);   SYM(__nv_bfloat16, kml, g_kml);
    SYM(__nv_bfloat16, hgah, g_hgah); SYM(__nv_bfloat16, hgal, g_hgal);
    SYM(__nv_bfloat16, hgbh, g_hgbh); SYM(__nv_bfloat16, hgbl, g_hgbl);
    SYM(__nv_bfloat16, wph, g_wph);   SYM(__nv_bfloat16, wpl, g_wpl);

    cudaFuncSetAttribute(gemm_bf16<1,false,true>, cudaFuncAttributeMaxDynamicSharedMemorySize, SMEM_TOT);
    cudaFuncSetAttribute(gemm_bf16<2,false,true>, cudaFuncAttributeMaxDynamicSharedMemorySize, SMEM_TOT);
    cudaFuncSetAttribute(gemm_bf16<0,false,true>, cudaFuncAttributeMaxDynamicSharedMemorySize, SMEM_TOT);
    cudaFuncSetAttribute(gemm_bf16<0,true,false>, cudaFuncAttributeMaxDynamicSharedMemorySize, SMEM_TOT);
    cudaFuncSetAttribute(gemm_bf16<0,true,true>,  cudaFuncAttributeMaxDynamicSharedMemorySize, SMEM_TOT);
    cudaFuncSetAttribute(gemm_fused_alt, cudaFuncAttributeMaxDynamicSharedMemorySize, FSM_TOT);

    const int TB = 256;
    #define SPLIT_SQ(src, dsth, dstl, R, C) do {                               \
        uint32_t t4 = (uint32_t)(((size_t)(R) * (C)) / 4);                     \
        split_same<<<(t4 + 255) / 256, TB>>>(src, dsth, dstl, t4);             \
    } while (0)
    #define SPLIT_PD(src, dsth, dstl, R, C, Cp) do {                           \
        uint32_t tot = (uint32_t)((size_t)(R) * (Cp));                         \
        split_pad<<<(tot + 255) / 256, TB>>>(src, dsth, dstl, C, Cp, tot);     \
    } while (0)

    // ---- launches 1-5: the splits phi1-L1 needs (so launch 6 = GEMM for ncu)
    SPLIT_PD(peA, peAh, peAl, NTOK, 514, KPAD1);                         // 1
    SPLIT_PD(p1w1, wph + OW_P1W1, wpl + OW_P1W1, 256, 514, KPAD1);       // 2
    SPLIT_SQ(p1w2, wph + OW_P1W2, wpl + OW_P1W2, 256, 256);              // 3
    SPLIT_SQ(p1w3, wph + OW_P1W3, wpl + OW_P1W3, 256, 256);              // 4
    SPLIT_SQ(p1w4, wph + OW_P1W4, wpl + OW_P1W4, 512, 256);              // 5

    #define GRID(Mv, Nv) dim3((Nv) / 128, (Mv) / 128)

    // ---- launch 6: phi1 L1 (profiled) ----
    gemm_bf16<1,false,true><<<GRID(NTOK, HIDC), TB, SMEM_TOT>>>(
        peAh, peAl, wph + OW_P1W1, wpl + OW_P1W1, p1b1, nullptr, h1h, h1l, KPAD1, HIDC);

    // ---- remaining weight splits ----
    SPLIT_SQ(attn_in_w, wph + OW_WQK, wpl + OW_WQK, 1024, 512);
    SPLIT_SQ(attn_in_w + (size_t)1024 * 512, wph + OW_WV0, wpl + OW_WV0, 256, 512);
    SPLIT_SQ(attn_in_w + (size_t)1280 * 512, wph + OW_WV1, wpl + OW_WV1, 256, 512);
    SPLIT_SQ(attn_out_w, wph + OW_WOUT, wpl + OW_WOUT, 512, 512);
    SPLIT_SQ(gw1, wph + OW_GW1, wpl + OW_GW1, 256, 512);
    SPLIT_SQ(gw2, wph + OW_GW2, wpl + OW_GW2, 256, 256);
    SPLIT_SQ(gw3, wph + OW_GW3, wpl + OW_GW3, 256, 256);
    SPLIT_SQ(p2w1, wph + OW_P2W1, wpl + OW_P2W1, 256, 512);
    SPLIT_SQ(p2w2, wph + OW_P2W2, wpl + OW_P2W2, 256, 256);

    // ---- phi1 chain (cont.) ----
    gemm_bf16<2,false,true><<<GRID(NTOK, HIDC), TB, SMEM_TOT>>>(
        h1h, h1l, wph + OW_P1W2, wpl + OW_P1W2, p1b2, nullptr, h2h, h2l, HIDC, HIDC);
    gemm_bf16<1,false,true><<<GRID(NTOK, HIDC), TB, SMEM_TOT>>>(
        h2h, h2l, wph + OW_P1W3, wpl + OW_P1W3, p1b3, nullptr, h1h, h1l, HIDC, HIDC);
    gemm_bf16<0,false,true><<<GRID(NTOK, EFULL), TB, SMEM_TOT>>>(
        h1h, h1l, wph + OW_P1W4, wpl + OW_P1W4, p1b4, nullptr, key1h, key1l, HIDC, EFULL);

    // ---- q,k projection + attention (v eliminated algebraically) ----
    gemm_bf16<0,true,false><<<GRID(NTOK, 1024), TB, SMEM_TOT>>>(
        key1h, key1l, wph + OW_WQK, wpl + OW_WQK, attn_in_b, qk, nullptr, nullptr, EFULL, 1024);
    attn2_kernel<<<NGR, TB>>>(qk, key1h, key1l, xwh, xwl);
    gemm_bf16<0,false,true><<<GRID(NGR, 256), TB, SMEM_TOT>>>(
        xwh, xwl, wph + OW_WV0, wpl + OW_WV0, attn_in_b + 1024,
        nullptr, omh, oml, EFULL, EFULL);
    gemm_bf16<0,false,true><<<GRID(NGR, 256), TB, SMEM_TOT>>>(
        xwh + (size_t)NGR * EFULL, xwl + (size_t)NGR * EFULL,
        wph + OW_WV1, wpl + OW_WV1, attn_in_b + 1280,
        nullptr, omh + 256, oml + 256, EFULL, EFULL);
    gemm_bf16<0,true,true><<<GRID(NGR, EFULL), TB, SMEM_TOT>>>(
        omh, oml, wph + OW_WOUT, wpl + OW_WOUT, attn_out_b, km, kmh, kml, EFULL, EFULL);

    // ---- g head -> q_jt at out[0 .. 4096) ----
    gemm_bf16<1,false,true><<<GRID(NGR, HIDC), TB, SMEM_TOT>>>(
        kmh, kml, wph + OW_GW1, wpl + OW_GW1, gb1, nullptr, hgah, hgal, EFULL, HIDC);
    gemm_bf16<1,false,true><<<GRID(NGR, HIDC), TB, SMEM_TOT>>>(
        hgah, hgal, wph + OW_GW2, wpl + OW_GW2, gb2, nullptr, hgbh, hgbl, HIDC, HIDC);
    gemm_bf16<1,false,true><<<GRID(NGR, HIDC), TB, SMEM_TOT>>>(
        hgbh, hgbl, wph + OW_GW3, wpl + OW_GW3, gb3, nullptr, hgah, hgal, HIDC, HIDC);
    ghead4_kernel<<<NGR / 8, TB>>>(hgah, hgal, gw4, gb4, out);

    // ---- alt path (altval fused into phi2-L1) -> alt_q at out[4096 ..) ----
    gemm_fused_alt<<<GRID(NTOK, 256), TB, FSM_TOT>>>(
        pe, key1h, key1l, km, wph + OW_P2W1, wpl + OW_P2W1, p2b1, h1h, h1l);
    gemm_bf16<1,false,true><<<GRID(NTOK, HIDC), TB, SMEM_TOT>>>(
        h1h, h1l, wph + OW_P2W2, wpl + OW_P2W2, p2b2, nullptr, h2h, h2l, HIDC, HIDC);
    altq_kernel<<<NTOK / 8, TB>>>(h2h, h2l, p2w3, p2b3, out + NGR);
}

// round 6
// speedup vs baseline: 1.1041x; 1.1041x over previous
#include <cuda_runtime.h>
#include <cuda_bf16.h>
#include <cstdint>
#include <math.h>

// Problem constants
#define NTOK  65536
#define EFULL 512
#define HIDC  256
#define NGR   4096
#define GSZ   16
#define KPAD1 544          // 514 padded to %32

// ---------------- scratch (__device__ globals) ----------------
__device__ __nv_bfloat16 g_h1h[(size_t)NTOK * HIDC];
__device__ __nv_bfloat16 g_h1l[(size_t)NTOK * HIDC];
__device__ __nv_bfloat16 g_h2h[(size_t)NTOK * HIDC];
__device__ __nv_bfloat16 g_h2l[(size_t)NTOK * HIDC];
__device__ __nv_bfloat16 g_key1h[(size_t)NTOK * EFULL];
__device__ __nv_bfloat16 g_key1l[(size_t)NTOK * EFULL];
__device__ float         g_qk[(size_t)NTOK * 1024];
__device__ __nv_bfloat16 g_xwh[(size_t)2 * NGR * EFULL];
__device__ __nv_bfloat16 g_xwl[(size_t)2 * NGR * EFULL];
__device__ __nv_bfloat16 g_omh[(size_t)NGR * EFULL];
__device__ __nv_bfloat16 g_oml[(size_t)NGR * EFULL];
__device__ float         g_km[(size_t)NGR * EFULL];
__device__ __nv_bfloat16 g_kmh[(size_t)NGR * EFULL];
__device__ __nv_bfloat16 g_kml[(size_t)NGR * EFULL];
__device__ __nv_bfloat16 g_hgah[(size_t)NGR * HIDC];
__device__ __nv_bfloat16 g_hgal[(size_t)NGR * HIDC];
__device__ __nv_bfloat16 g_hgbh[(size_t)NGR * HIDC];
__device__ __nv_bfloat16 g_hgbl[(size_t)NGR * HIDC];

// weight pool (split bf16). offsets in elements:
#define OW_P1W1 0                 // 256x544
#define OW_P1W2 139264            // 256x256
#define OW_P1W3 204800            // 256x256
#define OW_P1W4 270336            // 512x256
#define OW_WQK  401408            // 1024x512
#define OW_WV0  925696            // 256x512
#define OW_WV1  1056768           // 256x512
#define OW_WOUT 1187840           // 512x512
#define OW_GW1  1449984           // 256x512
#define OW_GW2  1581056           // 256x256
#define OW_GW3  1646592           // 256x256
#define OW_P2W1 1712128           // 256x512
#define OW_P2W2 1843200           // 256x256
#define OW_TOT  1908736
__device__ __nv_bfloat16 g_wph[OW_TOT];
__device__ __nv_bfloat16 g_wpl[OW_TOT];

__device__ __forceinline__ float elu1(float x) {
    return x > 0.f ? x : (expf(x) - 1.f);
}
__device__ __forceinline__ uint32_t smem_u32(const void* p) {
    uint32_t a;
    asm("{ .reg .u64 t; cvta.to.shared.u64 t, %1; cvt.u32.u64 %0, t; }" : "=r"(a) : "l"(p));
    return a;
}
__device__ __forceinline__ void ldsm4(uint32_t& r0, uint32_t& r1, uint32_t& r2, uint32_t& r3,
                                      uint32_t addr) {
    asm volatile("ldmatrix.sync.aligned.m8n8.x4.shared.b16 {%0,%1,%2,%3}, [%4];"
                 : "=r"(r0), "=r"(r1), "=r"(r2), "=r"(r3) : "r"(addr));
}
__device__ __forceinline__ void mma16816(float* c, const uint32_t* a, const uint32_t* b) {
    asm volatile("mma.sync.aligned.m16n8k16.row.col.f32.bf16.bf16.f32 "
                 "{%0,%1,%2,%3}, {%4,%5,%6,%7}, {%8,%9}, {%0,%1,%2,%3};"
                 : "+f"(c[0]), "+f"(c[1]), "+f"(c[2]), "+f"(c[3])
                 : "r"(a[0]), "r"(a[1]), "r"(a[2]), "r"(a[3]), "r"(b[0]), "r"(b[1]));
}
__device__ __forceinline__ void cvt_split2(float a, float b, uint32_t& hi, uint32_t& lo) {
    __nv_bfloat162 h = __floats2bfloat162_rn(a, b);
    float2 hf = __bfloat1622float2(h);
    __nv_bfloat162 l = __floats2bfloat162_rn(a - hf.x, b - hf.y);
    hi = *reinterpret_cast<uint32_t*>(&h);
    lo = *reinterpret_cast<uint32_t*>(&l);
}
__device__ __forceinline__ float2 bf2f2(uint32_t u) {
    return __bfloat1622float2(*reinterpret_cast<__nv_bfloat162*>(&u));
}
__device__ __forceinline__ uint32_t swz(uint32_t x) { return x ^ ((x >> 3) & 0x70); }

#define CP16(dst, src) \
    asm volatile("cp.async.cg.shared.global [%0], [%1], 16;" :: "r"(dst), "l"(src))
#define CP_COMMIT() asm volatile("cp.async.commit_group;" ::: "memory")
#define CP_WAIT1()  asm volatile("cp.async.wait_group 1;" ::: "memory")
#define CP_WAIT0()  asm volatile("cp.async.wait_group 0;" ::: "memory")

// ======== HMMA NT GEMM with pre-split bf16 operands ==========================
#define STAGE 32768
#define SMEM_TOT (3 * STAGE)

template <int EPI, bool WF32, bool WSPLIT>
__global__ __launch_bounds__(256, 2) void gemm_bf16(
    const __nv_bfloat16* __restrict__ Ah, const __nv_bfloat16* __restrict__ Al,
    const __nv_bfloat16* __restrict__ Bh, const __nv_bfloat16* __restrict__ Bl,
    const float* __restrict__ bias, float* __restrict__ C,
    __nv_bfloat16* __restrict__ Ch, __nv_bfloat16* __restrict__ Cl,
    int K, int ldC)
{
    extern __shared__ __align__(1024) char smem[];
    const uint32_t sb = smem_u32(smem);
    const int tid = threadIdx.x;
    const int lane = tid & 31;
    const int wid = tid >> 5;
    const int wm = wid & 3;
    const int wn = wid >> 2;
    const int m0 = blockIdx.y * 128;
    const int n0 = blockIdx.x * 128;

    const int nch = K >> 5;
    float acc[2][8][4] = {};

    const int lr = (tid >> 2);
    const int lc = tid & 3;

    auto issue = [&](int ci, int stg) {
        const int k0 = ci << 5;
        const uint32_t so = sb + stg * STAGE;
#pragma unroll
        for (int j = 0; j < 2; j++) {
            int r = lr + j * 64;
            uint32_t d = swz((uint32_t)(r * 64 + lc * 16));
            size_t ao = (size_t)(m0 + r) * K + k0 + lc * 8;
            size_t bo = (size_t)(n0 + r) * K + k0 + lc * 8;
            CP16(so + d,         Ah + ao);
            CP16(so + 8192 + d,  Al + ao);
            CP16(so + 16384 + d, Bh + bo);
            CP16(so + 24576 + d, Bl + bo);
        }
        CP_COMMIT();
    };

    issue(0, 0);
    if (nch > 1) issue(1, 1);

    int stg = 0;
    for (int ci = 0; ci < nch; ci++) {
        if (ci + 1 < nch) { CP_WAIT1(); } else { CP_WAIT0(); }
        __syncthreads();
        if (ci + 2 < nch) {
            int ns = stg + 2; if (ns >= 3) ns -= 3;
            issue(ci + 2, ns);
        }
        const uint32_t so = sb + stg * STAGE;

#pragma unroll
        for (int kk = 0; kk < 2; kk++) {
            uint32_t ah[2][4], al_[2][4];
            {
                int ar = lane & 15;
                int akb = kk * 32 + ((lane >> 4) * 16);
#pragma unroll
                for (int i = 0; i < 2; i++) {
                    uint32_t off = swz((uint32_t)((wm * 32 + i * 16 + ar) * 64 + akb));
                    ldsm4(ah[i][0], ah[i][1], ah[i][2], ah[i][3], so + off);
                    ldsm4(al_[i][0], al_[i][1], al_[i][2], al_[i][3], so + 8192 + off);
                }
            }
            uint32_t bh[8][2], bl_[8][2];
            {
                int br = (lane & 7) + ((lane >> 4) & 1) * 8;
                int bkb = ((lane >> 3) & 1) * 16 + kk * 32;
#pragma unroll
                for (int jf = 0; jf < 4; jf++) {
                    uint32_t off = swz((uint32_t)((wn * 64 + jf * 16 + br) * 64 + bkb));
                    uint32_t r0, r1, r2, r3;
                    ldsm4(r0, r1, r2, r3, so + 16384 + off);
                    bh[2 * jf][0] = r0; bh[2 * jf][1] = r1;
                    bh[2 * jf + 1][0] = r2; bh[2 * jf + 1][1] = r3;
                    ldsm4(r0, r1, r2, r3, so + 24576 + off);
                    bl_[2 * jf][0] = r0; bl_[2 * jf][1] = r1;
                    bl_[2 * jf + 1][0] = r2; bl_[2 * jf + 1][1] = r3;
                }
            }
#pragma unroll
            for (int i = 0; i < 2; i++)
#pragma unroll
                for (int j = 0; j < 8; j++)
                    mma16816(acc[i][j], ah[i], bh[j]);
#pragma unroll
            for (int i = 0; i < 2; i++)
#pragma unroll
                for (int j = 0; j < 8; j++)
                    mma16816(acc[i][j], ah[i], bl_[j]);
#pragma unroll
            for (int i = 0; i < 2; i++)
#pragma unroll
                for (int j = 0; j < 8; j++)
                    mma16816(acc[i][j], al_[i], bh[j]);
        }
        stg++; if (stg == 3) stg = 0;
        __syncthreads();
    }

    // ---- epilogue ----
#pragma unroll
    for (int i = 0; i < 2; i++) {
        int row = m0 + wm * 32 + i * 16 + (lane >> 2);
#pragma unroll
        for (int j = 0; j < 8; j++) {
            int col = n0 + wn * 64 + j * 8 + (lane & 3) * 2;
            float b0 = bias[col], b1 = bias[col + 1];
            float v0 = acc[i][j][0] + b0, v1 = acc[i][j][1] + b1;
            float v2 = acc[i][j][2] + b0, v3 = acc[i][j][3] + b1;
            if (EPI >= 1) { v0 = elu1(v0); v1 = elu1(v1); v2 = elu1(v2); v3 = elu1(v3); }
            if (EPI == 2) { v0 = elu1(v0); v1 = elu1(v1); v2 = elu1(v2); v3 = elu1(v3); }
            size_t o0 = (size_t)row * ldC + col;
            size_t o1 = (size_t)(row + 8) * ldC + col;
            if (WF32) {
                *reinterpret_cast<float2*>(C + o0) = make_float2(v0, v1);
                *reinterpret_cast<float2*>(C + o1) = make_float2(v2, v3);
            }
            if (WSPLIT) {
                uint32_t hi, lo;
                cvt_split2(v0, v1, hi, lo);
                *reinterpret_cast<uint32_t*>(Ch + o0) = hi;
                *reinterpret_cast<uint32_t*>(Cl + o0) = lo;
                cvt_split2(v2, v3, hi, lo);
                *reinterpret_cast<uint32_t*>(Ch + o1) = hi;
                *reinterpret_cast<uint32_t*>(Cl + o1) = lo;
            }
        }
    }
}

// ============ shared pieces for fused A-build GEMMs (SA=40 A layout) =========
#define SA 40
// per-stage layout: Ah[10240] Al[10240] Bh[8192] Bl[8192] = 36864
#define FS_AH 0
#define FS_AL 10240
#define FS_BH 20480
#define FS_BL 28672
#define FS_STAGE 36864

// compute one chunk (32 k) given stage base; shared by fused kernels
__device__ __forceinline__ void fused_compute_chunk(
    uint32_t sb_stage, int lane, int wm, int wn, float acc[2][8][4])
{
#pragma unroll
    for (int kk = 0; kk < 2; kk++) {
        uint32_t ah[2][4], al_[2][4];
        {
            int ar = lane & 15;
            int akc = ((lane >> 4) << 3) + (kk << 4);
#pragma unroll
            for (int i = 0; i < 2; i++) {
                uint32_t off = (uint32_t)((wm * 32 + i * 16 + ar) * SA + akc) * 2;
                ldsm4(ah[i][0], ah[i][1], ah[i][2], ah[i][3], sb_stage + FS_AH + off);
                ldsm4(al_[i][0], al_[i][1], al_[i][2], al_[i][3], sb_stage + FS_AL + off);
            }
        }
        uint32_t bh[8][2], bl_[8][2];
        {
            int br = (lane & 7) + ((lane >> 4) & 1) * 8;
            int bkb = ((lane >> 3) & 1) * 16 + kk * 32;
#pragma unroll
            for (int jf = 0; jf < 4; jf++) {
                uint32_t off = swz((uint32_t)((wn * 64 + jf * 16 + br) * 64 + bkb));
                uint32_t r0, r1, r2, r3;
                ldsm4(r0, r1, r2, r3, sb_stage + FS_BH + off);
                bh[2 * jf][0] = r0; bh[2 * jf][1] = r1;
                bh[2 * jf + 1][0] = r2; bh[2 * jf + 1][1] = r3;
                ldsm4(r0, r1, r2, r3, sb_stage + FS_BL + off);
                bl_[2 * jf][0] = r0; bl_[2 * jf][1] = r1;
                bl_[2 * jf + 1][0] = r2; bl_[2 * jf + 1][1] = r3;
            }
        }
#pragma unroll
        for (int i = 0; i < 2; i++)
#pragma unroll
            for (int j = 0; j < 8; j++)
                mma16816(acc[i][j], ah[i], bh[j]);
#pragma unroll
        for (int i = 0; i < 2; i++)
#pragma unroll
            for (int j = 0; j < 8; j++)
                mma16816(acc[i][j], ah[i], bl_[j]);
#pragma unroll
        for (int i = 0; i < 2; i++)
#pragma unroll
            for (int j = 0; j < 8; j++)
                mma16816(acc[i][j], al_[i], bh[j]);
    }
}

__device__ __forceinline__ void fused_epilogue_split(
    const float* bias, __nv_bfloat16* Ch, __nv_bfloat16* Cl,
    int m0, int n0, int lane, int wm, int wn, float acc[2][8][4])
{
#pragma unroll
    for (int i = 0; i < 2; i++) {
        int row = m0 + wm * 32 + i * 16 + (lane >> 2);
#pragma unroll
        for (int j = 0; j < 8; j++) {
            int col = n0 + wn * 64 + j * 8 + (lane & 3) * 2;
            float b0 = bias[col], b1 = bias[col + 1];
            float v0 = elu1(acc[i][j][0] + b0), v1 = elu1(acc[i][j][1] + b1);
            float v2 = elu1(acc[i][j][2] + b0), v3 = elu1(acc[i][j][3] + b1);
            size_t o0 = (size_t)row * HIDC + col;
            size_t o1 = (size_t)(row + 8) * HIDC + col;
            uint32_t hi, lo;
            cvt_split2(v0, v1, hi, lo);
            *reinterpret_cast<uint32_t*>(Ch + o0) = hi;
            *reinterpret_cast<uint32_t*>(Cl + o0) = lo;
            cvt_split2(v2, v3, hi, lo);
            *reinterpret_cast<uint32_t*>(Ch + o1) = hi;
            *reinterpret_cast<uint32_t*>(Cl + o1) = lo;
        }
    }
}

// ======== phi1-L1 GEMM with in-kernel split of fp32 peA ======================
// M=NTOK, N=256, K=544 (source cols 514), B pre-split. EPI=1, split output.
#define P1A_SMEM (2 * FS_STAGE)
__global__ __launch_bounds__(256, 2) void gemm_phi1a(
    const float* __restrict__ peA,
    const __nv_bfloat16* __restrict__ Bh, const __nv_bfloat16* __restrict__ Bl,
    const float* __restrict__ bias,
    __nv_bfloat16* __restrict__ Ch, __nv_bfloat16* __restrict__ Cl)
{
    extern __shared__ __align__(1024) char smem[];
    const uint32_t sb = smem_u32(smem);
    const int tid = threadIdx.x;
    const int lane = tid & 31;
    const int wid = tid >> 5;
    const int wm = wid & 3;
    const int wn = wid >> 2;
    const int m0 = blockIdx.y * 128;
    const int n0 = blockIdx.x * 128;
    const int nch = KPAD1 >> 5;   // 17

    float acc[2][8][4] = {};
    float4 a_r[4];

    const int blr = tid >> 2;
    const int blc = tid & 3;

    auto issueB = [&](int ci, int s) {
        const int k0 = ci << 5;
        const uint32_t so = sb + s * FS_STAGE;
#pragma unroll
        for (int j = 0; j < 2; j++) {
            int r = blr + j * 64;
            uint32_t d = swz((uint32_t)(r * 64 + blc * 16));
            size_t bo = (size_t)(n0 + r) * KPAD1 + k0 + blc * 8;
            CP16(so + FS_BH + d, Bh + bo);
            CP16(so + FS_BL + d, Bl + bo);
        }
        CP_COMMIT();
    };
    auto prefA = [&](int ci) {
        const int k0 = ci << 5;
#pragma unroll
        for (int j = 0; j < 4; j++) {
            int idx = tid + j * 256;
            int r = idx >> 3, c4 = idx & 7;
            int col = k0 + c4 * 4;
            const float* p = peA + (size_t)(m0 + r) * 514 + col;
            float4 v = make_float4(0.f, 0.f, 0.f, 0.f);
            if (col + 3 < 514) {
                float2 x = *reinterpret_cast<const float2*>(p);
                float2 y = *reinterpret_cast<const float2*>(p + 2);
                v = make_float4(x.x, x.y, y.x, y.y);
            } else {
                if (col + 0 < 514) v.x = p[0];
                if (col + 1 < 514) v.y = p[1];
                if (col + 2 < 514) v.z = p[2];
                if (col + 3 < 514) v.w = p[3];
            }
            a_r[j] = v;
        }
    };

    issueB(0, 0);
    issueB(1, 1);
    prefA(0);

    for (int ci = 0; ci < nch; ci++) {
        const int s = ci & 1;
        const uint32_t so = sb + s * FS_STAGE;
        if (ci + 1 < nch) { CP_WAIT1(); } else { CP_WAIT0(); }
        __syncthreads();
        // build A (split) into stage s
#pragma unroll
        for (int j = 0; j < 4; j++) {
            int idx = tid + j * 256;
            int r = idx >> 3, c4 = idx & 7;
            uint32_t hh01, ll01, hh23, ll23;
            cvt_split2(a_r[j].x, a_r[j].y, hh01, ll01);
            cvt_split2(a_r[j].z, a_r[j].w, hh23, ll23);
            uint32_t o = (uint32_t)(r * SA + c4 * 4) * 2;
            *reinterpret_cast<uint2*>(smem + s * FS_STAGE + FS_AH + o) = make_uint2(hh01, hh23);
            *reinterpret_cast<uint2*>(smem + s * FS_STAGE + FS_AL + o) = make_uint2(ll01, ll23);
        }
        if (ci + 1 < nch) prefA(ci + 1);
        __syncthreads();
        fused_compute_chunk(so, lane, wm, wn, acc);
        __syncthreads();
        if (ci + 2 < nch) issueB(ci + 2, s);
    }

    fused_epilogue_split(bias, Ch, Cl, m0, n0, lane, wm, wn, acc);
}

// ======== fused alt-value GEMM: A[r,k] = pe + km[g] - (k1h+k1l)/16 ===========
// M=NTOK, N=256, K=512. EPI=1, split output. km tile cached in smem.
#define FA_SMEM (16384 + 2 * FS_STAGE)
__global__ __launch_bounds__(256, 2) void gemm_fused_alt(
    const float* __restrict__ pe,
    const __nv_bfloat16* __restrict__ k1h, const __nv_bfloat16* __restrict__ k1l,
    const float* __restrict__ km,
    const __nv_bfloat16* __restrict__ Bh, const __nv_bfloat16* __restrict__ Bl,
    const float* __restrict__ bias,
    __nv_bfloat16* __restrict__ Ch, __nv_bfloat16* __restrict__ Cl)
{
    extern __shared__ __align__(1024) char smem[];
    float* kmS = reinterpret_cast<float*>(smem);
    const uint32_t sb = smem_u32(smem) + 16384;
    char* sdata = smem + 16384;
    const int tid = threadIdx.x;
    const int lane = tid & 31;
    const int wid = tid >> 5;
    const int wm = wid & 3;
    const int wn = wid >> 2;
    const int m0 = blockIdx.y * 128;
    const int n0 = blockIdx.x * 128;
    const int nch = 16;

    float acc[2][8][4] = {};
    float4 pe_r[4];
    uint2 kh_r[4], kl_r[4];

    const int blr = tid >> 2;
    const int blc = tid & 3;

    auto issueB = [&](int ci, int s) {
        const int k0 = ci << 5;
        const uint32_t so = sb + s * FS_STAGE;
#pragma unroll
        for (int j = 0; j < 2; j++) {
            int r = blr + j * 64;
            uint32_t d = swz((uint32_t)(r * 64 + blc * 16));
            size_t bo = (size_t)(n0 + r) * EFULL + k0 + blc * 8;
            CP16(so + FS_BH + d, Bh + bo);
            CP16(so + FS_BL + d, Bl + bo);
        }
        CP_COMMIT();
    };
    auto prefA = [&](int ci) {
        const int k0 = ci << 5;
#pragma unroll
        for (int j = 0; j < 4; j++) {
            int idx = tid + j * 256;
            int r = idx >> 3, c4 = idx & 7;
            size_t ao = (size_t)(m0 + r) * EFULL + k0 + c4 * 4;
            pe_r[j] = *reinterpret_cast<const float4*>(pe + ao);
            kh_r[j] = *reinterpret_cast<const uint2*>(k1h + ao);
            kl_r[j] = *reinterpret_cast<const uint2*>(k1l + ao);
        }
    };

    // cache km rows for the 8 groups in this M-tile
    const int g0 = m0 >> 4;
    for (int i = tid; i < 4096; i += 256)
        kmS[i] = km[(size_t)(g0 + (i >> 9)) * EFULL + (i & 511)];

    issueB(0, 0);
    issueB(1, 1);
    prefA(0);
    __syncthreads();   // km visible

    for (int ci = 0; ci < nch; ci++) {
        const int s = ci & 1;
        const int k0 = ci << 5;
        const uint32_t so = sb + s * FS_STAGE;
        if (ci + 1 < nch) { CP_WAIT1(); } else { CP_WAIT0(); }
        __syncthreads();
        // build A (split) into stage s
#pragma unroll
        for (int j = 0; j < 4; j++) {
            int idx = tid + j * 256;
            int r = idx >> 3, c4 = idx & 7;
            const float4 kmv = *reinterpret_cast<const float4*>(
                &kmS[(r >> 4) * EFULL + k0 + c4 * 4]);
            float2 h01 = bf2f2(kh_r[j].x), h23 = bf2f2(kh_r[j].y);
            float2 l01 = bf2f2(kl_r[j].x), l23 = bf2f2(kl_r[j].y);
            float v0 = pe_r[j].x + kmv.x - (h01.x + l01.x) * 0.0625f;
            float v1 = pe_r[j].y + kmv.y - (h01.y + l01.y) * 0.0625f;
            float v2 = pe_r[j].z + kmv.z - (h23.x + l23.x) * 0.0625f;
            float v3 = pe_r[j].w + kmv.w - (h23.y + l23.y) * 0.0625f;
            uint32_t hh01, ll01, hh23, ll23;
            cvt_split2(v0, v1, hh01, ll01);
            cvt_split2(v2, v3, hh23, ll23);
            uint32_t o = (uint32_t)(r * SA + c4 * 4) * 2;
            *reinterpret_cast<uint2*>(sdata + s * FS_STAGE + FS_AH + o) = make_uint2(hh01, hh23);
            *reinterpret_cast<uint2*>(sdata + s * FS_STAGE + FS_AL + o) = make_uint2(ll01, ll23);
        }
        if (ci + 1 < nch) prefA(ci + 1);
        __syncthreads();
        fused_compute_chunk(so, lane, wm, wn, acc);
        __syncthreads();
        if (ci + 2 < nch) issueB(ci + 2, s);
    }

    fused_epilogue_split(bias, Ch, Cl, m0, n0, lane, wm, wn, acc);
}

// ---------------- split kernels ----------------
__global__ __launch_bounds__(256) void split_same(
    const float* __restrict__ src, __nv_bfloat16* __restrict__ dh,
    __nv_bfloat16* __restrict__ dl, uint32_t total4)
{
    uint32_t i = blockIdx.x * 256u + threadIdx.x;
    if (i >= total4) return;
    float4 v = reinterpret_cast<const float4*>(src)[i];
    uint32_t h01, l01, h23, l23;
    cvt_split2(v.x, v.y, h01, l01);
    cvt_split2(v.z, v.w, h23, l23);
    reinterpret_cast<uint2*>(dh)[i] = make_uint2(h01, h23);
    reinterpret_cast<uint2*>(dl)[i] = make_uint2(l01, l23);
}
__global__ __launch_bounds__(256) void split_pad(
    const float* __restrict__ src, __nv_bfloat16* __restrict__ dh,
    __nv_bfloat16* __restrict__ dl, int C, int Cp, uint32_t total)
{
    uint32_t i = blockIdx.x * 256u + threadIdx.x;
    if (i >= total) return;
    uint32_t r = i / (uint32_t)Cp;
    int c = (int)(i - r * (uint32_t)Cp);
    float v = (c < C) ? src[(size_t)r * C + c] : 0.f;
    __nv_bfloat16 h = __float2bfloat16(v);
    dh[i] = h;
    dl[i] = __float2bfloat16(v - __bfloat162float(h));
}

// ---------------- attention ----------------
__global__ __launch_bounds__(256) void attn2_kernel(
    const float* __restrict__ qk,
    const __nv_bfloat16* __restrict__ xh, const __nv_bfloat16* __restrict__ xl,
    __nv_bfloat16* __restrict__ xwh, __nv_bfloat16* __restrict__ xwl)
{
    const int g = blockIdx.x;
    const int tid = threadIdx.x;
    __shared__ float qs[16][257];
    __shared__ float ks[16][257];
    __shared__ float sc[16][17];
    __shared__ float cw[16];
    const float* base = qk + (size_t)g * GSZ * 1024;
    const __nv_bfloat16* xbh = xh + (size_t)g * GSZ * 512;
    const __nv_bfloat16* xbl = xl + (size_t)g * GSZ * 512;

    for (int h = 0; h < 2; h++) {
        for (int i = tid; i < 16 * 256; i += 256) {
            int t = i >> 8, d = i & 255;
            qs[t][d] = base[t * 1024 + h * 256 + d];
            ks[t][d] = base[t * 1024 + 512 + h * 256 + d];
        }
        __syncthreads();
        {
            int tq = tid >> 4, tk = tid & 15;
            float a = 0.f;
#pragma unroll 8
            for (int d = 0; d < 256; d++) a += qs[tq][d] * ks[tk][d];
            sc[tq][tk] = a * 0.0625f;
        }
        __syncthreads();
        if (tid < 16) {
            int tq = tid;
            float mx = -1e30f;
            for (int tk = 0; tk < 16; tk++) mx = fmaxf(mx, sc[tq][tk]);
            float s = 0.f;
            for (int tk = 0; tk < 16; tk++) {
                float e = expf(sc[tq][tk] - mx);
                sc[tq][tk] = e;
                s += e;
            }
            float inv = 1.f / s;
            for (int tk = 0; tk < 16; tk++) sc[tq][tk] *= inv;
        }
        __syncthreads();
        if (tid < 16) {
            int tk = tid;
            float s = 0.f;
            for (int tq = 0; tq < 16; tq++) s += sc[tq][tk];
            cw[tk] = s * 0.0625f;
        }
        __syncthreads();
        for (int it = 0; it < 2; it++) {
            int d = tid + it * 256;
            float a = 0.f;
#pragma unroll
            for (int tk = 0; tk < 16; tk++)
                a += cw[tk] * (__bfloat162float(xbh[tk * 512 + d]) +
                               __bfloat162float(xbl[tk * 512 + d]));
            size_t o = (size_t)h * NGR * EFULL + (size_t)g * EFULL + d;
            __nv_bfloat16 hb = __float2bfloat16(a);
            xwh[o] = hb;
            xwl[o] = __float2bfloat16(a - __bfloat162float(hb));
        }
        __syncthreads();
    }
}

// ---------------- g head final ----------------
__global__ __launch_bounds__(256) void ghead4_kernel(
    const __nv_bfloat16* __restrict__ hh, const __nv_bfloat16* __restrict__ hl,
    const float* __restrict__ w, const float* __restrict__ b,
    float* __restrict__ out)
{
    int row = blockIdx.x * 8 + (threadIdx.x >> 5);
    int lane = threadIdx.x & 31;
    float acc = 0.f;
    for (int k = lane; k < 256; k += 32)
        acc += (__bfloat162float(hh[(size_t)row * 256 + k]) +
                __bfloat162float(hl[(size_t)row * 256 + k])) * w[k];
#pragma unroll
    for (int o = 16; o > 0; o >>= 1)
        acc += __shfl_xor_sync(0xffffffffu, acc, o);
    if (lane == 0) out[row] = acc + b[0];
}

// ---------------- alt_q = hp @ w3^T + b3 (256 -> 2) ----------------
__global__ __launch_bounds__(256) void altq_kernel(
    const __nv_bfloat16* __restrict__ hh, const __nv_bfloat16* __restrict__ hl,
    const float* __restrict__ w, const float* __restrict__ b,
    float* __restrict__ out)
{
    int row = blockIdx.x * 8 + (threadIdx.x >> 5);
    int lane = threadIdx.x & 31;
    float a0 = 0.f, a1 = 0.f;
    for (int k = lane; k < 256; k += 32) {
        float hv = __bfloat162float(hh[(size_t)row * 256 + k]) +
                   __bfloat162float(hl[(size_t)row * 256 + k]);
        a0 += hv * w[k];
        a1 += hv * w[256 + k];
    }
#pragma unroll
    for (int o = 16; o > 0; o >>= 1) {
        a0 += __shfl_xor_sync(0xffffffffu, a0, o);
        a1 += __shfl_xor_sync(0xffffffffu, a1, o);
    }
    if (lane == 0) {
        out[(size_t)row * 2 + 0] = a0 + b[0];
        out[(size_t)row * 2 + 1] = a1 + b[1];
    }
}

// ================================================================ host launch
extern "C" void kernel_launch(void* const* d_in, const int* in_sizes, int n_in,
                              void* d_out, int out_size)
{
    const float* pe       = (const float*)d_in[0];
    const float* peA      = (const float*)d_in[1];
    const float* attn_in_w  = (const float*)d_in[2];
    const float* attn_in_b  = (const float*)d_in[3];
    const float* attn_out_w = (const float*)d_in[4];
    const float* attn_out_b = (const float*)d_in[5];
    const float* p1w1 = (const float*)d_in[6];  const float* p1b1 = (const float*)d_in[7];
    const float* p1w2 = (const float*)d_in[8];  const float* p1b2 = (const float*)d_in[9];
    const float* p1w3 = (const float*)d_in[10]; const float* p1b3 = (const float*)d_in[11];
    const float* p1w4 = (const float*)d_in[12]; const float* p1b4 = (const float*)d_in[13];
    const float* gw1 = (const float*)d_in[14];  const float* gb1 = (const float*)d_in[15];
    const float* gw2 = (const float*)d_in[16];  const float* gb2 = (const float*)d_in[17];
    const float* gw3 = (const float*)d_in[18];  const float* gb3 = (const float*)d_in[19];
    const float* gw4 = (const float*)d_in[20];  const float* gb4 = (const float*)d_in[21];
    const float* p2w1 = (const float*)d_in[22]; const float* p2b1 = (const float*)d_in[23];
    const float* p2w2 = (const float*)d_in[24]; const float* p2b2 = (const float*)d_in[25];
    const float* p2w3 = (const float*)d_in[26]; const float* p2b3 = (const float*)d_in[27];
    float* out = (float*)d_out;

    #define SYM(T, v, s) T* v; cudaGetSymbolAddress((void**)&v, s)
    SYM(__nv_bfloat16, h1h, g_h1h);   SYM(__nv_bfloat16, h1l, g_h1l);
    SYM(__nv_bfloat16, h2h, g_h2h);   SYM(__nv_bfloat16, h2l, g_h2l);
    SYM(__nv_bfloat16, key1h, g_key1h); SYM(__nv_bfloat16, key1l, g_key1l);
    SYM(float, qk, g_qk);
    SYM(__nv_bfloat16, xwh, g_xwh);   SYM(__nv_bfloat16, xwl, g_xwl);
    SYM(__nv_bfloat16, omh, g_omh);   SYM(__nv_bfloat16, oml, g_oml);
    SYM(float, km, g_km);
    SYM(__nv_bfloat16, kmh, g_kmh);   SYM(__nv_bfloat16, kml, g_kml);
    SYM(__nv_bfloat16, hgah, g_hgah); SYM(__nv_bfloat16, hgal, g_hgal);
    SYM(__nv_bfloat16, hgbh, g_hgbh); SYM(__nv_bfloat16, hgbl, g_hgbl);
    SYM(__nv_bfloat16, wph, g_wph);   SYM(__nv_bfloat16, wpl, g_wpl);

    cudaFuncSetAttribute(gemm_bf16<1,false,true>, cudaFuncAttributeMaxDynamicSharedMemorySize, SMEM_TOT);
    cudaFuncSetAttribute(gemm_bf16<2,false,true>, cudaFuncAttributeMaxDynamicSharedMemorySize, SMEM_TOT);
    cudaFuncSetAttribute(gemm_bf16<0,false,true>, cudaFuncAttributeMaxDynamicSharedMemorySize, SMEM_TOT);
    cudaFuncSetAttribute(gemm_bf16<0,true,false>, cudaFuncAttributeMaxDynamicSharedMemorySize, SMEM_TOT);
    cudaFuncSetAttribute(gemm_bf16<0,true,true>,  cudaFuncAttributeMaxDynamicSharedMemorySize, SMEM_TOT);
    cudaFuncSetAttribute(gemm_phi1a, cudaFuncAttributeMaxDynamicSharedMemorySize, P1A_SMEM);
    cudaFuncSetAttribute(gemm_fused_alt, cudaFuncAttributeMaxDynamicSharedMemorySize, FA_SMEM);

    const int TB = 256;
    #define SPLIT_SQ(src, dsth, dstl, R, C) do {                               \
        uint32_t t4 = (uint32_t)(((size_t)(R) * (C)) / 4);                     \
        split_same<<<(t4 + 255) / 256, TB>>>(src, dsth, dstl, t4);             \
    } while (0)
    #define SPLIT_PD(src, dsth, dstl, R, C, Cp) do {                           \
        uint32_t tot = (uint32_t)((size_t)(R) * (Cp));                         \
        split_pad<<<(tot + 255) / 256, TB>>>(src, dsth, dstl, C, Cp, tot);     \
    } while (0)

    #define GRID(Mv, Nv) dim3((Nv) / 128, (Mv) / 128)

    // #1, #2: splits needed by phi1-L1
    SPLIT_PD(p1w1, wph + OW_P1W1, wpl + OW_P1W1, 256, 514, KPAD1);
    SPLIT_SQ(p1w2, wph + OW_P1W2, wpl + OW_P1W2, 256, 256);

    // #3: phi1 L1 (fused peA split; target for ncu)
    gemm_phi1a<<<GRID(NTOK, 256), TB, P1A_SMEM>>>(
        peA, wph + OW_P1W1, wpl + OW_P1W1, p1b1, h1h, h1l);

    // remaining weight splits
    SPLIT_SQ(p1w3, wph + OW_P1W3, wpl + OW_P1W3, 256, 256);
    SPLIT_SQ(p1w4, wph + OW_P1W4, wpl + OW_P1W4, 512, 256);
    SPLIT_SQ(attn_in_w, wph + OW_WQK, wpl + OW_WQK, 1024, 512);
    SPLIT_SQ(attn_in_w + (size_t)1024 * 512, wph + OW_WV0, wpl + OW_WV0, 256, 512);
    SPLIT_SQ(attn_in_w + (size_t)1280 * 512, wph + OW_WV1, wpl + OW_WV1, 256, 512);
    SPLIT_SQ(attn_out_w, wph + OW_WOUT, wpl + OW_WOUT, 512, 512);
    SPLIT_SQ(gw1, wph + OW_GW1, wpl + OW_GW1, 256, 512);
    SPLIT_SQ(gw2, wph + OW_GW2, wpl + OW_GW2, 256, 256);
    SPLIT_SQ(gw3, wph + OW_GW3, wpl + OW_GW3, 256, 256);
    SPLIT_SQ(p2w1, wph + OW_P2W1, wpl + OW_P2W1, 256, 512);
    SPLIT_SQ(p2w2, wph + OW_P2W2, wpl + OW_P2W2, 256, 256);

    // phi1 chain (cont.)
    gemm_bf16<2,false,true><<<GRID(NTOK, HIDC), TB, SMEM_TOT>>>(
        h1h, h1l, wph + OW_P1W2, wpl + OW_P1W2, p1b2, nullptr, h2h, h2l, HIDC, HIDC);
    gemm_bf16<1,false,true><<<GRID(NTOK, HIDC), TB, SMEM_TOT>>>(
        h2h, h2l, wph + OW_P1W3, wpl + OW_P1W3, p1b3, nullptr, h1h, h1l, HIDC, HIDC);
    gemm_bf16<0,false,true><<<GRID(NTOK, EFULL), TB, SMEM_TOT>>>(
        h1h, h1l, wph + OW_P1W4, wpl + OW_P1W4, p1b4, nullptr, key1h, key1l, HIDC, EFULL);

    // q,k projection + attention (v eliminated algebraically)
    gemm_bf16<0,true,false><<<GRID(NTOK, 1024), TB, SMEM_TOT>>>(
        key1h, key1l, wph + OW_WQK, wpl + OW_WQK, attn_in_b, qk, nullptr, nullptr, EFULL, 1024);
    attn2_kernel<<<NGR, TB>>>(qk, key1h, key1l, xwh, xwl);
    gemm_bf16<0,false,true><<<GRID(NGR, 256), TB, SMEM_TOT>>>(
        xwh, xwl, wph + OW_WV0, wpl + OW_WV0, attn_in_b + 1024,
        nullptr, omh, oml, EFULL, EFULL);
    gemm_bf16<0,false,true><<<GRID(NGR, 256), TB, SMEM_TOT>>>(
        xwh + (size_t)NGR * EFULL, xwl + (size_t)NGR * EFULL,
        wph + OW_WV1, wpl + OW_WV1, attn_in_b + 1280,
        nullptr, omh + 256, oml + 256, EFULL, EFULL);
    gemm_bf16<0,true,true><<<GRID(NGR, EFULL), TB, SMEM_TOT>>>(
        omh, oml, wph + OW_WOUT, wpl + OW_WOUT, attn_out_b, km, kmh, kml, EFULL, EFULL);

    // g head -> q_jt at out[0 .. 4096)
    gemm_bf16<1,false,true><<<GRID(NGR, HIDC), TB, SMEM_TOT>>>(
        kmh, kml, wph + OW_GW1, wpl + OW_GW1, gb1, nullptr, hgah, hgal, EFULL, HIDC);
    gemm_bf16<1,false,true><<<GRID(NGR, HIDC), TB, SMEM_TOT>>>(
        hgah, hgal, wph + OW_GW2, wpl + OW_GW2, gb2, nullptr, hgbh, hgbl, HIDC, HIDC);
    gemm_bf16<1,false,true><<<GRID(NGR, HIDC), TB, SMEM_TOT>>>(
        hgbh, hgbl, wph + OW_GW3, wpl + OW_GW3, gb3, nullptr, hgah, hgal, HIDC, HIDC);
    ghead4_kernel<<<NGR / 8, TB>>>(hgah, hgal, gw4, gb4, out);

    // alt path (altval fused into phi2-L1) -> alt_q at out[4096 ..)
    gemm_fused_alt<<<GRID(NTOK, 256), TB, FA_SMEM>>>(
        pe, key1h, key1l, km, wph + OW_P2W1, wpl + OW_P2W1, p2b1, h1h, h1l);
    gemm_bf16<1,false,true><<<GRID(NTOK, HIDC), TB, SMEM_TOT>>>(
        h1h, h1l, wph + OW_P2W2, wpl + OW_P2W2, p2b2, nullptr, h2h, h2l, HIDC, HIDC);
    altq_kernel<<<NTOK / 8, TB>>>(h2h, h2l, p2w3, p2b3, out + NGR);
}

// round 7
// speedup vs baseline: 1.3410x; 1.2145x over previous
#include <cuda_runtime.h>
#include <cuda_bf16.h>
#include <cstdint>
#include <math.h>

// Problem constants
#define NTOK  65536
#define EFULL 512
#define HIDC  256
#define NGR   4096
#define GSZ   16
#define KPAD1 544          // 514 padded to %32

// ---------------- scratch (__device__ globals) ----------------
__device__ __nv_bfloat16 g_h1h[(size_t)NTOK * HIDC];
__device__ __nv_bfloat16 g_h1l[(size_t)NTOK * HIDC];
__device__ __nv_bfloat16 g_h2h[(size_t)NTOK * HIDC];
__device__ __nv_bfloat16 g_h2l[(size_t)NTOK * HIDC];
__device__ __nv_bfloat16 g_key1h[(size_t)NTOK * EFULL];
__device__ __nv_bfloat16 g_key1l[(size_t)NTOK * EFULL];
__device__ __nv_bfloat16 g_qk[(size_t)NTOK * 1024];
__device__ __nv_bfloat16 g_xwh[(size_t)2 * NGR * EFULL];
__device__ __nv_bfloat16 g_xwl[(size_t)2 * NGR * EFULL];
__device__ __nv_bfloat16 g_omh[(size_t)NGR * EFULL];
__device__ __nv_bfloat16 g_oml[(size_t)NGR * EFULL];
__device__ float         g_km[(size_t)NGR * EFULL];
__device__ __nv_bfloat16 g_kmh[(size_t)NGR * EFULL];
__device__ __nv_bfloat16 g_kml[(size_t)NGR * EFULL];
__device__ __nv_bfloat16 g_hgah[(size_t)NGR * HIDC];
__device__ __nv_bfloat16 g_hgal[(size_t)NGR * HIDC];
__device__ __nv_bfloat16 g_hgbh[(size_t)NGR * HIDC];
__device__ __nv_bfloat16 g_hgbl[(size_t)NGR * HIDC];

// weight pool (split bf16). offsets in elements:
#define OW_P1W1 0                 // 256x544
#define OW_P1W2 139264            // 256x256
#define OW_P1W3 204800            // 256x256
#define OW_P1W4 270336            // 512x256
#define OW_WQK  401408            // 1024x512
#define OW_WV0  925696            // 256x512
#define OW_WV1  1056768           // 256x512
#define OW_WOUT 1187840           // 512x512
#define OW_GW1  1449984           // 256x512
#define OW_GW2  1581056           // 256x256
#define OW_GW3  1646592           // 256x256
#define OW_P2W1 1712128           // 256x512
#define OW_P2W2 1843200           // 256x256
#define OW_TOT  1908736
__device__ __nv_bfloat16 g_wph[OW_TOT];
__device__ __nv_bfloat16 g_wpl[OW_TOT];

__device__ __forceinline__ float elu1(float x) {
    return x > 0.f ? x : (expf(x) - 1.f);
}
__device__ __forceinline__ uint32_t smem_u32(const void* p) {
    uint32_t a;
    asm("{ .reg .u64 t; cvta.to.shared.u64 t, %1; cvt.u32.u64 %0, t; }" : "=r"(a) : "l"(p));
    return a;
}
__device__ __forceinline__ void ldsm4(uint32_t& r0, uint32_t& r1, uint32_t& r2, uint32_t& r3,
                                      uint32_t addr) {
    asm volatile("ldmatrix.sync.aligned.m8n8.x4.shared.b16 {%0,%1,%2,%3}, [%4];"
                 : "=r"(r0), "=r"(r1), "=r"(r2), "=r"(r3) : "r"(addr));
}
__device__ __forceinline__ void mma16816(float* c, const uint32_t* a, const uint32_t* b) {
    asm volatile("mma.sync.aligned.m16n8k16.row.col.f32.bf16.bf16.f32 "
                 "{%0,%1,%2,%3}, {%4,%5,%6,%7}, {%8,%9}, {%0,%1,%2,%3};"
                 : "+f"(c[0]), "+f"(c[1]), "+f"(c[2]), "+f"(c[3])
                 : "r"(a[0]), "r"(a[1]), "r"(a[2]), "r"(a[3]), "r"(b[0]), "r"(b[1]));
}
__device__ __forceinline__ void cvt_split2(float a, float b, uint32_t& hi, uint32_t& lo) {
    __nv_bfloat162 h = __floats2bfloat162_rn(a, b);
    float2 hf = __bfloat1622float2(h);
    __nv_bfloat162 l = __floats2bfloat162_rn(a - hf.x, b - hf.y);
    hi = *reinterpret_cast<uint32_t*>(&h);
    lo = *reinterpret_cast<uint32_t*>(&l);
}
__device__ __forceinline__ float2 bf2f2(uint32_t u) {
    return __bfloat1622float2(*reinterpret_cast<__nv_bfloat162*>(&u));
}
__device__ __forceinline__ uint32_t swz(uint32_t x) { return x ^ ((x >> 3) & 0x70); }

#define CP16(dst, src) \
    asm volatile("cp.async.cg.shared.global [%0], [%1], 16;" :: "r"(dst), "l"(src))
#define CP_COMMIT() asm volatile("cp.async.commit_group;" ::: "memory")
#define CP_WAIT1()  asm volatile("cp.async.wait_group 1;" ::: "memory")
#define CP_WAIT0()  asm volatile("cp.async.wait_group 0;" ::: "memory")

// ======== HMMA NT GEMM with pre-split bf16 operands (3-pass) =================
#define STAGE 32768
#define SMEM_TOT (3 * STAGE)

template <int EPI, bool WF32, bool WSPLIT>
__global__ __launch_bounds__(256, 2) void gemm_bf16(
    const __nv_bfloat16* __restrict__ Ah, const __nv_bfloat16* __restrict__ Al,
    const __nv_bfloat16* __restrict__ Bh, const __nv_bfloat16* __restrict__ Bl,
    const float* __restrict__ bias, float* __restrict__ C,
    __nv_bfloat16* __restrict__ Ch, __nv_bfloat16* __restrict__ Cl,
    int K, int ldC)
{
    extern __shared__ __align__(1024) char smem[];
    const uint32_t sb = smem_u32(smem);
    const int tid = threadIdx.x;
    const int lane = tid & 31;
    const int wid = tid >> 5;
    const int wm = wid & 3;
    const int wn = wid >> 2;
    const int m0 = blockIdx.y * 128;
    const int n0 = blockIdx.x * 128;

    const int nch = K >> 5;
    float acc[2][8][4] = {};

    const int lr = (tid >> 2);
    const int lc = tid & 3;

    auto issue = [&](int ci, int stg) {
        const int k0 = ci << 5;
        const uint32_t so = sb + stg * STAGE;
#pragma unroll
        for (int j = 0; j < 2; j++) {
            int r = lr + j * 64;
            uint32_t d = swz((uint32_t)(r * 64 + lc * 16));
            size_t ao = (size_t)(m0 + r) * K + k0 + lc * 8;
            size_t bo = (size_t)(n0 + r) * K + k0 + lc * 8;
            CP16(so + d,         Ah + ao);
            CP16(so + 8192 + d,  Al + ao);
            CP16(so + 16384 + d, Bh + bo);
            CP16(so + 24576 + d, Bl + bo);
        }
        CP_COMMIT();
    };

    issue(0, 0);
    if (nch > 1) issue(1, 1);

    int stg = 0;
    for (int ci = 0; ci < nch; ci++) {
        if (ci + 1 < nch) { CP_WAIT1(); } else { CP_WAIT0(); }
        __syncthreads();
        if (ci + 2 < nch) {
            int ns = stg + 2; if (ns >= 3) ns -= 3;
            issue(ci + 2, ns);
        }
        const uint32_t so = sb + stg * STAGE;

#pragma unroll
        for (int kk = 0; kk < 2; kk++) {
            uint32_t ah[2][4], al_[2][4];
            {
                int ar = lane & 15;
                int akb = kk * 32 + ((lane >> 4) * 16);
#pragma unroll
                for (int i = 0; i < 2; i++) {
                    uint32_t off = swz((uint32_t)((wm * 32 + i * 16 + ar) * 64 + akb));
                    ldsm4(ah[i][0], ah[i][1], ah[i][2], ah[i][3], so + off);
                    ldsm4(al_[i][0], al_[i][1], al_[i][2], al_[i][3], so + 8192 + off);
                }
            }
            uint32_t bh[8][2], bl_[8][2];
            {
                int br = (lane & 7) + ((lane >> 4) & 1) * 8;
                int bkb = ((lane >> 3) & 1) * 16 + kk * 32;
#pragma unroll
                for (int jf = 0; jf < 4; jf++) {
                    uint32_t off = swz((uint32_t)((wn * 64 + jf * 16 + br) * 64 + bkb));
                    uint32_t r0, r1, r2, r3;
                    ldsm4(r0, r1, r2, r3, so + 16384 + off);
                    bh[2 * jf][0] = r0; bh[2 * jf][1] = r1;
                    bh[2 * jf + 1][0] = r2; bh[2 * jf + 1][1] = r3;
                    ldsm4(r0, r1, r2, r3, so + 24576 + off);
                    bl_[2 * jf][0] = r0; bl_[2 * jf][1] = r1;
                    bl_[2 * jf + 1][0] = r2; bl_[2 * jf + 1][1] = r3;
                }
            }
#pragma unroll
            for (int i = 0; i < 2; i++)
#pragma unroll
                for (int j = 0; j < 8; j++)
                    mma16816(acc[i][j], ah[i], bh[j]);
#pragma unroll
            for (int i = 0; i < 2; i++)
#pragma unroll
                for (int j = 0; j < 8; j++)
                    mma16816(acc[i][j], ah[i], bl_[j]);
#pragma unroll
            for (int i = 0; i < 2; i++)
#pragma unroll
                for (int j = 0; j < 8; j++)
                    mma16816(acc[i][j], al_[i], bh[j]);
        }
        stg++; if (stg == 3) stg = 0;
        __syncthreads();
    }

    // ---- epilogue ----
#pragma unroll
    for (int i = 0; i < 2; i++) {
        int row = m0 + wm * 32 + i * 16 + (lane >> 2);
#pragma unroll
        for (int j = 0; j < 8; j++) {
            int col = n0 + wn * 64 + j * 8 + (lane & 3) * 2;
            float b0 = bias[col], b1 = bias[col + 1];
            float v0 = acc[i][j][0] + b0, v1 = acc[i][j][1] + b1;
            float v2 = acc[i][j][2] + b0, v3 = acc[i][j][3] + b1;
            if (EPI >= 1) { v0 = elu1(v0); v1 = elu1(v1); v2 = elu1(v2); v3 = elu1(v3); }
            if (EPI == 2) { v0 = elu1(v0); v1 = elu1(v1); v2 = elu1(v2); v3 = elu1(v3); }
            size_t o0 = (size_t)row * ldC + col;
            size_t o1 = (size_t)(row + 8) * ldC + col;
            if (WF32) {
                *reinterpret_cast<float2*>(C + o0) = make_float2(v0, v1);
                *reinterpret_cast<float2*>(C + o1) = make_float2(v2, v3);
            }
            if (WSPLIT) {
                uint32_t hi, lo;
                cvt_split2(v0, v1, hi, lo);
                *reinterpret_cast<uint32_t*>(Ch + o0) = hi;
                *reinterpret_cast<uint32_t*>(Cl + o0) = lo;
                cvt_split2(v2, v3, hi, lo);
                *reinterpret_cast<uint32_t*>(Ch + o1) = hi;
                *reinterpret_cast<uint32_t*>(Cl + o1) = lo;
            }
        }
    }
}

// ======== single-pass bf16 GEMM for qk (A hi, B hi only, bf16 out) ==========
#define QSTAGE 16384
#define QSMEM (3 * QSTAGE)
__global__ __launch_bounds__(256, 2) void gemm_qk1p(
    const __nv_bfloat16* __restrict__ Ah, const __nv_bfloat16* __restrict__ Bh,
    const float* __restrict__ bias, __nv_bfloat16* __restrict__ Cb,
    int K, int ldC)
{
    extern __shared__ __align__(1024) char smem[];
    const uint32_t sb = smem_u32(smem);
    const int tid = threadIdx.x;
    const int lane = tid & 31;
    const int wid = tid >> 5;
    const int wm = wid & 3;
    const int wn = wid >> 2;
    const int m0 = blockIdx.y * 128;
    const int n0 = blockIdx.x * 128;

    const int nch = K >> 5;
    float acc[2][8][4] = {};
    const int lr = (tid >> 2);
    const int lc = tid & 3;

    auto issue = [&](int ci, int stg) {
        const int k0 = ci << 5;
        const uint32_t so = sb + stg * QSTAGE;
#pragma unroll
        for (int j = 0; j < 2; j++) {
            int r = lr + j * 64;
            uint32_t d = swz((uint32_t)(r * 64 + lc * 16));
            CP16(so + d,        Ah + (size_t)(m0 + r) * K + k0 + lc * 8);
            CP16(so + 8192 + d, Bh + (size_t)(n0 + r) * K + k0 + lc * 8);
        }
        CP_COMMIT();
    };

    issue(0, 0);
    if (nch > 1) issue(1, 1);

    int stg = 0;
    for (int ci = 0; ci < nch; ci++) {
        if (ci + 1 < nch) { CP_WAIT1(); } else { CP_WAIT0(); }
        __syncthreads();
        if (ci + 2 < nch) {
            int ns = stg + 2; if (ns >= 3) ns -= 3;
            issue(ci + 2, ns);
        }
        const uint32_t so = sb + stg * QSTAGE;
#pragma unroll
        for (int kk = 0; kk < 2; kk++) {
            uint32_t ah[2][4];
            {
                int ar = lane & 15;
                int akb = kk * 32 + ((lane >> 4) * 16);
#pragma unroll
                for (int i = 0; i < 2; i++) {
                    uint32_t off = swz((uint32_t)((wm * 32 + i * 16 + ar) * 64 + akb));
                    ldsm4(ah[i][0], ah[i][1], ah[i][2], ah[i][3], so + off);
                }
            }
            uint32_t bh[8][2];
            {
                int br = (lane & 7) + ((lane >> 4) & 1) * 8;
                int bkb = ((lane >> 3) & 1) * 16 + kk * 32;
#pragma unroll
                for (int jf = 0; jf < 4; jf++) {
                    uint32_t off = swz((uint32_t)((wn * 64 + jf * 16 + br) * 64 + bkb));
                    uint32_t r0, r1, r2, r3;
                    ldsm4(r0, r1, r2, r3, so + 8192 + off);
                    bh[2 * jf][0] = r0; bh[2 * jf][1] = r1;
                    bh[2 * jf + 1][0] = r2; bh[2 * jf + 1][1] = r3;
                }
            }
#pragma unroll
            for (int i = 0; i < 2; i++)
#pragma unroll
                for (int j = 0; j < 8; j++)
                    mma16816(acc[i][j], ah[i], bh[j]);
        }
        stg++; if (stg == 3) stg = 0;
        __syncthreads();
    }

#pragma unroll
    for (int i = 0; i < 2; i++) {
        int row = m0 + wm * 32 + i * 16 + (lane >> 2);
#pragma unroll
        for (int j = 0; j < 8; j++) {
            int col = n0 + wn * 64 + j * 8 + (lane & 3) * 2;
            float b0 = bias[col], b1 = bias[col + 1];
            __nv_bfloat162 p0 = __floats2bfloat162_rn(acc[i][j][0] + b0, acc[i][j][1] + b1);
            __nv_bfloat162 p1 = __floats2bfloat162_rn(acc[i][j][2] + b0, acc[i][j][3] + b1);
            *reinterpret_cast<__nv_bfloat162*>(Cb + (size_t)row * ldC + col) = p0;
            *reinterpret_cast<__nv_bfloat162*>(Cb + (size_t)(row + 8) * ldC + col) = p1;
        }
    }
}

// ============ shared pieces for fused A-build GEMMs (SA=40 A layout) =========
#define SA 40
#define FS_AH 0
#define FS_AL 10240
#define FS_BH 20480
#define FS_BL 28672
#define FS_STAGE 36864

__device__ __forceinline__ void fused_compute_chunk(
    uint32_t sb_stage, int lane, int wm, int wn, float acc[2][8][4])
{
#pragma unroll
    for (int kk = 0; kk < 2; kk++) {
        uint32_t ah[2][4], al_[2][4];
        {
            int ar = lane & 15;
            int akc = ((lane >> 4) << 3) + (kk << 4);
#pragma unroll
            for (int i = 0; i < 2; i++) {
                uint32_t off = (uint32_t)((wm * 32 + i * 16 + ar) * SA + akc) * 2;
                ldsm4(ah[i][0], ah[i][1], ah[i][2], ah[i][3], sb_stage + FS_AH + off);
                ldsm4(al_[i][0], al_[i][1], al_[i][2], al_[i][3], sb_stage + FS_AL + off);
            }
        }
        uint32_t bh[8][2], bl_[8][2];
        {
            int br = (lane & 7) + ((lane >> 4) & 1) * 8;
            int bkb = ((lane >> 3) & 1) * 16 + kk * 32;
#pragma unroll
            for (int jf = 0; jf < 4; jf++) {
                uint32_t off = swz((uint32_t)((wn * 64 + jf * 16 + br) * 64 + bkb));
                uint32_t r0, r1, r2, r3;
                ldsm4(r0, r1, r2, r3, sb_stage + FS_BH + off);
                bh[2 * jf][0] = r0; bh[2 * jf][1] = r1;
                bh[2 * jf + 1][0] = r2; bh[2 * jf + 1][1] = r3;
                ldsm4(r0, r1, r2, r3, sb_stage + FS_BL + off);
                bl_[2 * jf][0] = r0; bl_[2 * jf][1] = r1;
                bl_[2 * jf + 1][0] = r2; bl_[2 * jf + 1][1] = r3;
            }
        }
#pragma unroll
        for (int i = 0; i < 2; i++)
#pragma unroll
            for (int j = 0; j < 8; j++)
                mma16816(acc[i][j], ah[i], bh[j]);
#pragma unroll
        for (int i = 0; i < 2; i++)
#pragma unroll
            for (int j = 0; j < 8; j++)
                mma16816(acc[i][j], ah[i], bl_[j]);
#pragma unroll
        for (int i = 0; i < 2; i++)
#pragma unroll
            for (int j = 0; j < 8; j++)
                mma16816(acc[i][j], al_[i], bh[j]);
    }
}

__device__ __forceinline__ void fused_epilogue_split(
    const float* bias, __nv_bfloat16* Ch, __nv_bfloat16* Cl,
    int m0, int n0, int lane, int wm, int wn, float acc[2][8][4])
{
#pragma unroll
    for (int i = 0; i < 2; i++) {
        int row = m0 + wm * 32 + i * 16 + (lane >> 2);
#pragma unroll
        for (int j = 0; j < 8; j++) {
            int col = n0 + wn * 64 + j * 8 + (lane & 3) * 2;
            float b0 = bias[col], b1 = bias[col + 1];
            float v0 = elu1(acc[i][j][0] + b0), v1 = elu1(acc[i][j][1] + b1);
            float v2 = elu1(acc[i][j][2] + b0), v3 = elu1(acc[i][j][3] + b1);
            size_t o0 = (size_t)row * HIDC + col;
            size_t o1 = (size_t)(row + 8) * HIDC + col;
            uint32_t hi, lo;
            cvt_split2(v0, v1, hi, lo);
            *reinterpret_cast<uint32_t*>(Ch + o0) = hi;
            *reinterpret_cast<uint32_t*>(Cl + o0) = lo;
            cvt_split2(v2, v3, hi, lo);
            *reinterpret_cast<uint32_t*>(Ch + o1) = hi;
            *reinterpret_cast<uint32_t*>(Cl + o1) = lo;
        }
    }
}

// ======== phi1-L1 GEMM with in-kernel split of fp32 peA ======================
#define P1A_SMEM (2 * FS_STAGE)
__global__ __launch_bounds__(256, 2) void gemm_phi1a(
    const float* __restrict__ peA,
    const __nv_bfloat16* __restrict__ Bh, const __nv_bfloat16* __restrict__ Bl,
    const float* __restrict__ bias,
    __nv_bfloat16* __restrict__ Ch, __nv_bfloat16* __restrict__ Cl)
{
    extern __shared__ __align__(1024) char smem[];
    const uint32_t sb = smem_u32(smem);
    const int tid = threadIdx.x;
    const int lane = tid & 31;
    const int wid = tid >> 5;
    const int wm = wid & 3;
    const int wn = wid >> 2;
    const int m0 = blockIdx.y * 128;
    const int n0 = blockIdx.x * 128;
    const int nch = KPAD1 >> 5;   // 17

    float acc[2][8][4] = {};
    float4 a_r[4];

    const int blr = tid >> 2;
    const int blc = tid & 3;

    auto issueB = [&](int ci, int s) {
        const int k0 = ci << 5;
        const uint32_t so = sb + s * FS_STAGE;
#pragma unroll
        for (int j = 0; j < 2; j++) {
            int r = blr + j * 64;
            uint32_t d = swz((uint32_t)(r * 64 + blc * 16));
            size_t bo = (size_t)(n0 + r) * KPAD1 + k0 + blc * 8;
            CP16(so + FS_BH + d, Bh + bo);
            CP16(so + FS_BL + d, Bl + bo);
        }
        CP_COMMIT();
    };
    auto prefA = [&](int ci) {
        const int k0 = ci << 5;
#pragma unroll
        for (int j = 0; j < 4; j++) {
            int idx = tid + j * 256;
            int r = idx >> 3, c4 = idx & 7;
            int col = k0 + c4 * 4;
            const float* p = peA + (size_t)(m0 + r) * 514 + col;
            float4 v = make_float4(0.f, 0.f, 0.f, 0.f);
            if (col + 3 < 514) {
                float2 x = *reinterpret_cast<const float2*>(p);
                float2 y = *reinterpret_cast<const float2*>(p + 2);
                v = make_float4(x.x, x.y, y.x, y.y);
            } else {
                if (col + 0 < 514) v.x = p[0];
                if (col + 1 < 514) v.y = p[1];
                if (col + 2 < 514) v.z = p[2];
                if (col + 3 < 514) v.w = p[3];
            }
            a_r[j] = v;
        }
    };

    issueB(0, 0);
    issueB(1, 1);
    prefA(0);

    for (int ci = 0; ci < nch; ci++) {
        const int s = ci & 1;
        const uint32_t so = sb + s * FS_STAGE;
        if (ci + 1 < nch) { CP_WAIT1(); } else { CP_WAIT0(); }
        __syncthreads();
#pragma unroll
        for (int j = 0; j < 4; j++) {
            int idx = tid + j * 256;
            int r = idx >> 3, c4 = idx & 7;
            uint32_t hh01, ll01, hh23, ll23;
            cvt_split2(a_r[j].x, a_r[j].y, hh01, ll01);
            cvt_split2(a_r[j].z, a_r[j].w, hh23, ll23);
            uint32_t o = (uint32_t)(r * SA + c4 * 4) * 2;
            *reinterpret_cast<uint2*>(smem + s * FS_STAGE + FS_AH + o) = make_uint2(hh01, hh23);
            *reinterpret_cast<uint2*>(smem + s * FS_STAGE + FS_AL + o) = make_uint2(ll01, ll23);
        }
        if (ci + 1 < nch) prefA(ci + 1);
        __syncthreads();
        fused_compute_chunk(so, lane, wm, wn, acc);
        __syncthreads();
        if (ci + 2 < nch) issueB(ci + 2, s);
    }

    fused_epilogue_split(bias, Ch, Cl, m0, n0, lane, wm, wn, acc);
}

// ======== fused alt-value GEMM: A[r,k] = pe + km[g] - (k1h+k1l)/16 ===========
#define FA_SMEM (16384 + 2 * FS_STAGE)
__global__ __launch_bounds__(256, 2) void gemm_fused_alt(
    const float* __restrict__ pe,
    const __nv_bfloat16* __restrict__ k1h, const __nv_bfloat16* __restrict__ k1l,
    const float* __restrict__ km,
    const __nv_bfloat16* __restrict__ Bh, const __nv_bfloat16* __restrict__ Bl,
    const float* __restrict__ bias,
    __nv_bfloat16* __restrict__ Ch, __nv_bfloat16* __restrict__ Cl)
{
    extern __shared__ __align__(1024) char smem[];
    float* kmS = reinterpret_cast<float*>(smem);
    const uint32_t sb = smem_u32(smem) + 16384;
    char* sdata = smem + 16384;
    const int tid = threadIdx.x;
    const int lane = tid & 31;
    const int wid = tid >> 5;
    const int wm = wid & 3;
    const int wn = wid >> 2;
    const int m0 = blockIdx.y * 128;
    const int n0 = blockIdx.x * 128;
    const int nch = 16;

    float acc[2][8][4] = {};
    float4 pe_r[4];
    uint2 kh_r[4], kl_r[4];

    const int blr = tid >> 2;
    const int blc = tid & 3;

    auto issueB = [&](int ci, int s) {
        const int k0 = ci << 5;
        const uint32_t so = sb + s * FS_STAGE;
#pragma unroll
        for (int j = 0; j < 2; j++) {
            int r = blr + j * 64;
            uint32_t d = swz((uint32_t)(r * 64 + blc * 16));
            size_t bo = (size_t)(n0 + r) * EFULL + k0 + blc * 8;
            CP16(so + FS_BH + d, Bh + bo);
            CP16(so + FS_BL + d, Bl + bo);
        }
        CP_COMMIT();
    };
    auto prefA = [&](int ci) {
        const int k0 = ci << 5;
#pragma unroll
        for (int j = 0; j < 4; j++) {
            int idx = tid + j * 256;
            int r = idx >> 3, c4 = idx & 7;
            size_t ao = (size_t)(m0 + r) * EFULL + k0 + c4 * 4;
            pe_r[j] = *reinterpret_cast<const float4*>(pe + ao);
            kh_r[j] = *reinterpret_cast<const uint2*>(k1h + ao);
            kl_r[j] = *reinterpret_cast<const uint2*>(k1l + ao);
        }
    };

    const int g0 = m0 >> 4;
    for (int i = tid; i < 4096; i += 256)
        kmS[i] = km[(size_t)(g0 + (i >> 9)) * EFULL + (i & 511)];

    issueB(0, 0);
    issueB(1, 1);
    prefA(0);
    __syncthreads();

    for (int ci = 0; ci < nch; ci++) {
        const int s = ci & 1;
        const int k0 = ci << 5;
        const uint32_t so = sb + s * FS_STAGE;
        if (ci + 1 < nch) { CP_WAIT1(); } else { CP_WAIT0(); }
        __syncthreads();
#pragma unroll
        for (int j = 0; j < 4; j++) {
            int idx = tid + j * 256;
            int r = idx >> 3, c4 = idx & 7;
            const float4 kmv = *reinterpret_cast<const float4*>(
                &kmS[(r >> 4) * EFULL + k0 + c4 * 4]);
            float2 h01 = bf2f2(kh_r[j].x), h23 = bf2f2(kh_r[j].y);
            float2 l01 = bf2f2(kl_r[j].x), l23 = bf2f2(kl_r[j].y);
            float v0 = pe_r[j].x + kmv.x - (h01.x + l01.x) * 0.0625f;
            float v1 = pe_r[j].y + kmv.y - (h01.y + l01.y) * 0.0625f;
            float v2 = pe_r[j].z + kmv.z - (h23.x + l23.x) * 0.0625f;
            float v3 = pe_r[j].w + kmv.w - (h23.y + l23.y) * 0.0625f;
            uint32_t hh01, ll01, hh23, ll23;
            cvt_split2(v0, v1, hh01, ll01);
            cvt_split2(v2, v3, hh23, ll23);
            uint32_t o = (uint32_t)(r * SA + c4 * 4) * 2;
            *reinterpret_cast<uint2*>(sdata + s * FS_STAGE + FS_AH + o) = make_uint2(hh01, hh23);
            *reinterpret_cast<uint2*>(sdata + s * FS_STAGE + FS_AL + o) = make_uint2(ll01, ll23);
        }
        if (ci + 1 < nch) prefA(ci + 1);
        __syncthreads();
        fused_compute_chunk(so, lane, wm, wn, acc);
        __syncthreads();
        if (ci + 2 < nch) issueB(ci + 2, s);
    }

    fused_epilogue_split(bias, Ch, Cl, m0, n0, lane, wm, wn, acc);
}

// ---------------- multi-segment weight split (one launch) ----------------
#define MAXSEG 9
struct SplitSegs {
    const float* src[MAXSEG];
    int dstoff[MAXSEG];
    int C[MAXSEG];
    int Cp[MAXSEG];
    int rows[MAXSEG];
    int n;
};
__global__ __launch_bounds__(256) void split_multi(
    SplitSegs p, __nv_bfloat16* __restrict__ dh, __nv_bfloat16* __restrict__ dl)
{
    const uint32_t stride = gridDim.x * 256u;
    const uint32_t base = blockIdx.x * 256u + threadIdx.x;
    for (int s = 0; s < p.n; s++) {
        const float* src = p.src[s];
        const int C = p.C[s], Cp = p.Cp[s], off = p.dstoff[s];
        const uint32_t tot = (uint32_t)p.rows[s] * Cp;
        for (uint32_t i = base; i < tot; i += stride) {
            uint32_t r = i / (uint32_t)Cp;
            int c = (int)(i - r * (uint32_t)Cp);
            float v = (c < C) ? src[(size_t)r * C + c] : 0.f;
            __nv_bfloat16 h = __float2bfloat16(v);
            dh[off + i] = h;
            dl[off + i] = __float2bfloat16(v - __bfloat162float(h));
        }
    }
}

__global__ void warm_kernel(__nv_bfloat16* p) {
    if (blockIdx.x == 0 && threadIdx.x == 0) {
        volatile __nv_bfloat16* q = p;
        q[0] = q[0];
    }
}

// ---------------- attention (bf16 qk input) ----------------
__global__ __launch_bounds__(256) void attn2_kernel(
    const __nv_bfloat16* __restrict__ qk,
    const __nv_bfloat16* __restrict__ xh, const __nv_bfloat16* __restrict__ xl,
    __nv_bfloat16* __restrict__ xwh, __nv_bfloat16* __restrict__ xwl)
{
    const int g = blockIdx.x;
    const int tid = threadIdx.x;
    __shared__ float qs[16][257];
    __shared__ float ks[16][257];
    __shared__ float sc[16][17];
    __shared__ float cw[16];
    const __nv_bfloat16* base = qk + (size_t)g * GSZ * 1024;
    const __nv_bfloat16* xbh = xh + (size_t)g * GSZ * 512;
    const __nv_bfloat16* xbl = xl + (size_t)g * GSZ * 512;

    for (int h = 0; h < 2; h++) {
        for (int i = tid; i < 16 * 256; i += 256) {
            int t = i >> 8, d = i & 255;
            qs[t][d] = __bfloat162float(base[t * 1024 + h * 256 + d]);
            ks[t][d] = __bfloat162float(base[t * 1024 + 512 + h * 256 + d]);
        }
        __syncthreads();
        {
            int tq = tid >> 4, tk = tid & 15;
            float a = 0.f;
#pragma unroll 8
            for (int d = 0; d < 256; d++) a += qs[tq][d] * ks[tk][d];
            sc[tq][tk] = a * 0.0625f;
        }
        __syncthreads();
        if (tid < 16) {
            int tq = tid;
            float mx = -1e30f;
            for (int tk = 0; tk < 16; tk++) mx = fmaxf(mx, sc[tq][tk]);
            float s = 0.f;
            for (int tk = 0; tk < 16; tk++) {
                float e = expf(sc[tq][tk] - mx);
                sc[tq][tk] = e;
                s += e;
            }
            float inv = 1.f / s;
            for (int tk = 0; tk < 16; tk++) sc[tq][tk] *= inv;
        }
        __syncthreads();
        if (tid < 16) {
            int tk = tid;
            float s = 0.f;
            for (int tq = 0; tq < 16; tq++) s += sc[tq][tk];
            cw[tk] = s * 0.0625f;
        }
        __syncthreads();
        for (int it = 0; it < 2; it++) {
            int d = tid + it * 256;
            float a = 0.f;
#pragma unroll
            for (int tk = 0; tk < 16; tk++)
                a += cw[tk] * (__bfloat162float(xbh[tk * 512 + d]) +
                               __bfloat162float(xbl[tk * 512 + d]));
            size_t o = (size_t)h * NGR * EFULL + (size_t)g * EFULL + d;
            __nv_bfloat16 hb = __float2bfloat16(a);
            xwh[o] = hb;
            xwl[o] = __float2bfloat16(a - __bfloat162float(hb));
        }
        __syncthreads();
    }
}

// ---------------- g head final ----------------
__global__ __launch_bounds__(256) void ghead4_kernel(
    const __nv_bfloat16* __restrict__ hh, const __nv_bfloat16* __restrict__ hl,
    const float* __restrict__ w, const float* __restrict__ b,
    float* __restrict__ out)
{
    int row = blockIdx.x * 8 + (threadIdx.x >> 5);
    int lane = threadIdx.x & 31;
    float acc = 0.f;
    for (int k = lane; k < 256; k += 32)
        acc += (__bfloat162float(hh[(size_t)row * 256 + k]) +
                __bfloat162float(hl[(size_t)row * 256 + k])) * w[k];
#pragma unroll
    for (int o = 16; o > 0; o >>= 1)
        acc += __shfl_xor_sync(0xffffffffu, acc, o);
    if (lane == 0) out[row] = acc + b[0];
}

// ---------------- alt_q = hp @ w3^T + b3 (256 -> 2) ----------------
__global__ __launch_bounds__(256) void altq_kernel(
    const __nv_bfloat16* __restrict__ hh, const __nv_bfloat16* __restrict__ hl,
    const float* __restrict__ w, const float* __restrict__ b,
    float* __restrict__ out)
{
    int row = blockIdx.x * 8 + (threadIdx.x >> 5);
    int lane = threadIdx.x & 31;
    float a0 = 0.f, a1 = 0.f;
    for (int k = lane; k < 256; k += 32) {
        float hv = __bfloat162float(hh[(size_t)row * 256 + k]) +
                   __bfloat162float(hl[(size_t)row * 256 + k]);
        a0 += hv * w[k];
        a1 += hv * w[256 + k];
    }
#pragma unroll
    for (int o = 16; o > 0; o >>= 1) {
        a0 += __shfl_xor_sync(0xffffffffu, a0, o);
        a1 += __shfl_xor_sync(0xffffffffu, a1, o);
    }
    if (lane == 0) {
        out[(size_t)row * 2 + 0] = a0 + b[0];
        out[(size_t)row * 2 + 1] = a1 + b[1];
    }
}

// ================================================================ host launch
extern "C" void kernel_launch(void* const* d_in, const int* in_sizes, int n_in,
                              void* d_out, int out_size)
{
    const float* pe       = (const float*)d_in[0];
    const float* peA      = (const float*)d_in[1];
    const float* attn_in_w  = (const float*)d_in[2];
    const float* attn_in_b  = (const float*)d_in[3];
    const float* attn_out_w = (const float*)d_in[4];
    const float* attn_out_b = (const float*)d_in[5];
    const float* p1w1 = (const float*)d_in[6];  const float* p1b1 = (const float*)d_in[7];
    const float* p1w2 = (const float*)d_in[8];  const float* p1b2 = (const float*)d_in[9];
    const float* p1w3 = (const float*)d_in[10]; const float* p1b3 = (const float*)d_in[11];
    const float* p1w4 = (const float*)d_in[12]; const float* p1b4 = (const float*)d_in[13];
    const float* gw1 = (const float*)d_in[14];  const float* gb1 = (const float*)d_in[15];
    const float* gw2 = (const float*)d_in[16];  const float* gb2 = (const float*)d_in[17];
    const float* gw3 = (const float*)d_in[18];  const float* gb3 = (const float*)d_in[19];
    const float* gw4 = (const float*)d_in[20];  const float* gb4 = (const float*)d_in[21];
    const float* p2w1 = (const float*)d_in[22]; const float* p2b1 = (const float*)d_in[23];
    const float* p2w2 = (const float*)d_in[24]; const float* p2b2 = (const float*)d_in[25];
    const float* p2w3 = (const float*)d_in[26]; const float* p2b3 = (const float*)d_in[27];
    float* out = (float*)d_out;

    #define SYM(T, v, s) T* v; cudaGetSymbolAddress((void**)&v, s)
    SYM(__nv_bfloat16, h1h, g_h1h);   SYM(__nv_bfloat16, h1l, g_h1l);
    SYM(__nv_bfloat16, h2h, g_h2h);   SYM(__nv_bfloat16, h2l, g_h2l);
    SYM(__nv_bfloat16, key1h, g_key1h); SYM(__nv_bfloat16, key1l, g_key1l);
    SYM(__nv_bfloat16, qk, g_qk);
    SYM(__nv_bfloat16, xwh, g_xwh);   SYM(__nv_bfloat16, xwl, g_xwl);
    SYM(__nv_bfloat16, omh, g_omh);   SYM(__nv_bfloat16, oml, g_oml);
    SYM(float, km, g_km);
    SYM(__nv_bfloat16, kmh, g_kmh);   SYM(__nv_bfloat16, kml, g_kml);
    SYM(__nv_bfloat16, hgah, g_hgah); SYM(__nv_bfloat16, hgal, g_hgal);
    SYM(__nv_bfloat16, hgbh, g_hgbh); SYM(__nv_bfloat16, hgbl, g_hgbl);
    SYM(__nv_bfloat16, wph, g_wph);   SYM(__nv_bfloat16, wpl, g_wpl);

    cudaFuncSetAttribute(gemm_bf16<1,false,true>, cudaFuncAttributeMaxDynamicSharedMemorySize, SMEM_TOT);
    cudaFuncSetAttribute(gemm_bf16<2,false,true>, cudaFuncAttributeMaxDynamicSharedMemorySize, SMEM_TOT);
    cudaFuncSetAttribute(gemm_bf16<0,false,true>, cudaFuncAttributeMaxDynamicSharedMemorySize, SMEM_TOT);
    cudaFuncSetAttribute(gemm_bf16<0,true,true>,  cudaFuncAttributeMaxDynamicSharedMemorySize, SMEM_TOT);
    cudaFuncSetAttribute(gemm_qk1p, cudaFuncAttributeMaxDynamicSharedMemorySize, QSMEM);
    cudaFuncSetAttribute(gemm_phi1a, cudaFuncAttributeMaxDynamicSharedMemorySize, P1A_SMEM);
    cudaFuncSetAttribute(gemm_fused_alt, cudaFuncAttributeMaxDynamicSharedMemorySize, FA_SMEM);

    const int TB = 256;
    #define GRID(Mv, Nv) dim3((Nv) / 128, (Mv) / 128)

    // ---- launch #1: phi1 weight splits (one kernel) ----
    {
        SplitSegs s = {};
        int n = 0;
        auto add = [&](const float* src, int off, int R, int C, int Cp) {
            s.src[n] = src; s.dstoff[n] = off; s.rows[n] = R; s.C[n] = C; s.Cp[n] = Cp; n++;
        };
        add(p1w1, OW_P1W1, 256, 514, KPAD1);
        add(p1w2, OW_P1W2, 256, 256, 256);
        add(p1w3, OW_P1W3, 256, 256, 256);
        add(p1w4, OW_P1W4, 512, 256, 256);
        s.n = n;
        split_multi<<<512, TB>>>(s, wph, wpl);
    }
    // ---- launch #2: remaining weight splits ----
    {
        SplitSegs s = {};
        int n = 0;
        auto add = [&](const float* src, int off, int R, int C, int Cp) {
            s.src[n] = src; s.dstoff[n] = off; s.rows[n] = R; s.C[n] = C; s.Cp[n] = Cp; n++;
        };
        add(attn_in_w, OW_WQK, 1024, 512, 512);
        add(attn_in_w + (size_t)1024 * 512, OW_WV0, 256, 512, 512);
        add(attn_in_w + (size_t)1280 * 512, OW_WV1, 256, 512, 512);
        add(attn_out_w, OW_WOUT, 512, 512, 512);
        add(gw1, OW_GW1, 256, 512, 512);
        add(gw2, OW_GW2, 256, 256, 256);
        add(gw3, OW_GW3, 256, 256, 256);
        add(p2w1, OW_P2W1, 256, 512, 512);
        add(p2w2, OW_P2W2, 256, 256, 256);
        s.n = n;
        split_multi<<<512, TB>>>(s, wph, wpl);
    }
    // ---- launch #3: warm (positions the GEMM at #4 for ncu) ----
    warm_kernel<<<1, 32>>>(wph);

    // ---- launch #4: phi1 L1 (fused peA split; profiled) ----
    gemm_phi1a<<<GRID(NTOK, 256), TB, P1A_SMEM>>>(
        peA, wph + OW_P1W1, wpl + OW_P1W1, p1b1, h1h, h1l);

    // phi1 chain (cont.)
    gemm_bf16<2,false,true><<<GRID(NTOK, HIDC), TB, SMEM_TOT>>>(
        h1h, h1l, wph + OW_P1W2, wpl + OW_P1W2, p1b2, nullptr, h2h, h2l, HIDC, HIDC);
    gemm_bf16<1,false,true><<<GRID(NTOK, HIDC), TB, SMEM_TOT>>>(
        h2h, h2l, wph + OW_P1W3, wpl + OW_P1W3, p1b3, nullptr, h1h, h1l, HIDC, HIDC);
    gemm_bf16<0,false,true><<<GRID(NTOK, EFULL), TB, SMEM_TOT>>>(
        h1h, h1l, wph + OW_P1W4, wpl + OW_P1W4, p1b4, nullptr, key1h, key1l, HIDC, EFULL);

    // q,k projection (single-pass bf16) + attention
    gemm_qk1p<<<GRID(NTOK, 1024), TB, QSMEM>>>(
        key1h, wph + OW_WQK, attn_in_b, qk, EFULL, 1024);
    attn2_kernel<<<NGR, TB>>>(qk, key1h, key1l, xwh, xwl);
    gemm_bf16<0,false,true><<<GRID(NGR, 256), TB, SMEM_TOT>>>(
        xwh, xwl, wph + OW_WV0, wpl + OW_WV0, attn_in_b + 1024,
        nullptr, omh, oml, EFULL, EFULL);
    gemm_bf16<0,false,true><<<GRID(NGR, 256), TB, SMEM_TOT>>>(
        xwh + (size_t)NGR * EFULL, xwl + (size_t)NGR * EFULL,
        wph + OW_WV1, wpl + OW_WV1, attn_in_b + 1280,
        nullptr, omh + 256, oml + 256, EFULL, EFULL);
    gemm_bf16<0,true,true><<<GRID(NGR, EFULL), TB, SMEM_TOT>>>(
        omh, oml, wph + OW_WOUT, wpl + OW_WOUT, attn_out_b, km, kmh, kml, EFULL, EFULL);

    // g head -> q_jt at out[0 .. 4096)
    gemm_bf16<1,false,true><<<GRID(NGR, HIDC), TB, SMEM_TOT>>>(
        kmh, kml, wph + OW_GW1, wpl + OW_GW1, gb1, nullptr, hgah, hgal, EFULL, HIDC);
    gemm_bf16<1,false,true><<<GRID(NGR, HIDC), TB, SMEM_TOT>>>(
        hgah, hgal, wph + OW_GW2, wpl + OW_GW2, gb2, nullptr, hgbh, hgbl, HIDC, HIDC);
    gemm_bf16<1,false,true><<<GRID(NGR, HIDC), TB, SMEM_TOT>>>(
        hgbh, hgbl, wph + OW_GW3, wpl + OW_GW3, gb3, nullptr, hgah, hgal, HIDC, HIDC);
    ghead4_kernel<<<NGR / 8, TB>>>(hgah, hgal, gw4, gb4, out);

    // alt path (altval fused into phi2-L1) -> alt_q at out[4096 ..)
    gemm_fused_alt<<<GRID(NTOK, 256), TB, FA_SMEM>>>(
        pe, key1h, key1l, km, wph + OW_P2W1, wpl + OW_P2W1, p2b1, h1h, h1l);
    gemm_bf16<1,false,true><<<GRID(NTOK, HIDC), TB, SMEM_TOT>>>(
        h1h, h1l, wph + OW_P2W2, wpl + OW_P2W2, p2b2, nullptr, h2h, h2l, HIDC, HIDC);
    altq_kernel<<<NTOK / 8, TB>>>(h2h, h2l, p2w3, p2b3, out + NGR);
}

// round 8
// speedup vs baseline: 1.4602x; 1.0889x over previous
#include <cuda_runtime.h>
#include <cuda_bf16.h>
#include <cstdint>
#include <math.h>

// Problem constants
#define NTOK  65536
#define EFULL 512
#define HIDC  256
#define NGR   4096
#define GSZ   16
#define KPAD1 544          // 514 padded to %32

// ---------------- scratch (__device__ globals) ----------------
__device__ __nv_bfloat16 g_h1h[(size_t)NTOK * HIDC];
__device__ __nv_bfloat16 g_h1l[(size_t)NTOK * HIDC];
__device__ __nv_bfloat16 g_h2h[(size_t)NTOK * HIDC];
__device__ __nv_bfloat16 g_h2l[(size_t)NTOK * HIDC];
__device__ __nv_bfloat16 g_key1h[(size_t)NTOK * EFULL];
__device__ __nv_bfloat16 g_key1l[(size_t)NTOK * EFULL];
__device__ __nv_bfloat16 g_qk[(size_t)NTOK * 1024];
__device__ __nv_bfloat16 g_xwh[(size_t)2 * NGR * EFULL];
__device__ __nv_bfloat16 g_xwl[(size_t)2 * NGR * EFULL];
__device__ __nv_bfloat16 g_omh[(size_t)NGR * EFULL];
__device__ __nv_bfloat16 g_oml[(size_t)NGR * EFULL];
__device__ float         g_km[(size_t)NGR * EFULL];
__device__ __nv_bfloat16 g_kmh[(size_t)NGR * EFULL];
__device__ __nv_bfloat16 g_kml[(size_t)NGR * EFULL];
__device__ __nv_bfloat16 g_hgah[(size_t)NGR * HIDC];
__device__ __nv_bfloat16 g_hgal[(size_t)NGR * HIDC];
__device__ __nv_bfloat16 g_hgbh[(size_t)NGR * HIDC];
__device__ __nv_bfloat16 g_hgbl[(size_t)NGR * HIDC];

// weight pool (split bf16). offsets in elements:
#define OW_P1W1 0
#define OW_P1W2 139264
#define OW_P1W3 204800
#define OW_P1W4 270336
#define OW_WQK  401408
#define OW_WV0  925696
#define OW_WV1  1056768
#define OW_WOUT 1187840
#define OW_GW1  1449984
#define OW_GW2  1581056
#define OW_GW3  1646592
#define OW_P2W1 1712128
#define OW_P2W2 1843200
#define OW_TOT  1908736
__device__ __nv_bfloat16 g_wph[OW_TOT];
__device__ __nv_bfloat16 g_wpl[OW_TOT];

__device__ __forceinline__ float elu1(float x) {
    return x > 0.f ? x : (expf(x) - 1.f);
}
__device__ __forceinline__ uint32_t smem_u32(const void* p) {
    uint32_t a;
    asm("{ .reg .u64 t; cvta.to.shared.u64 t, %1; cvt.u32.u64 %0, t; }" : "=r"(a) : "l"(p));
    return a;
}
__device__ __forceinline__ void ldsm4(uint32_t& r0, uint32_t& r1, uint32_t& r2, uint32_t& r3,
                                      uint32_t addr) {
    asm volatile("ldmatrix.sync.aligned.m8n8.x4.shared.b16 {%0,%1,%2,%3}, [%4];"
                 : "=r"(r0), "=r"(r1), "=r"(r2), "=r"(r3) : "r"(addr));
}
__device__ __forceinline__ void mma16816(float* c, const uint32_t* a, const uint32_t* b) {
    asm volatile("mma.sync.aligned.m16n8k16.row.col.f32.bf16.bf16.f32 "
                 "{%0,%1,%2,%3}, {%4,%5,%6,%7}, {%8,%9}, {%0,%1,%2,%3};"
                 : "+f"(c[0]), "+f"(c[1]), "+f"(c[2]), "+f"(c[3])
                 : "r"(a[0]), "r"(a[1]), "r"(a[2]), "r"(a[3]), "r"(b[0]), "r"(b[1]));
}
__device__ __forceinline__ void cvt_split2(float a, float b, uint32_t& hi, uint32_t& lo) {
    __nv_bfloat162 h = __floats2bfloat162_rn(a, b);
    float2 hf = __bfloat1622float2(h);
    __nv_bfloat162 l = __floats2bfloat162_rn(a - hf.x, b - hf.y);
    hi = *reinterpret_cast<uint32_t*>(&h);
    lo = *reinterpret_cast<uint32_t*>(&l);
}
__device__ __forceinline__ float2 bf2f2(uint32_t u) {
    return __bfloat1622float2(*reinterpret_cast<__nv_bfloat162*>(&u));
}
__device__ __forceinline__ uint32_t swz(uint32_t x) { return x ^ ((x >> 3) & 0x70); }

#define CP16(dst, src) \
    asm volatile("cp.async.cg.shared.global [%0], [%1], 16;" :: "r"(dst), "l"(src))
#define CP_COMMIT() asm volatile("cp.async.commit_group;" ::: "memory")
#define CP_WAIT1()  asm volatile("cp.async.wait_group 1;" ::: "memory")
#define CP_WAIT0()  asm volatile("cp.async.wait_group 0;" ::: "memory")

// ======== HMMA NT GEMM with pre-split bf16 operands (3-pass) =================
#define STAGE 32768
#define SMEM_TOT (3 * STAGE)

template <int EPI, bool WF32, bool WSPLIT>
__global__ __launch_bounds__(256, 2) void gemm_bf16(
    const __nv_bfloat16* __restrict__ Ah, const __nv_bfloat16* __restrict__ Al,
    const __nv_bfloat16* __restrict__ Bh, const __nv_bfloat16* __restrict__ Bl,
    const float* __restrict__ bias, float* __restrict__ C,
    __nv_bfloat16* __restrict__ Ch, __nv_bfloat16* __restrict__ Cl,
    int K, int ldC)
{
    extern __shared__ __align__(1024) char smem[];
    const uint32_t sb = smem_u32(smem);
    const int tid = threadIdx.x;
    const int lane = tid & 31;
    const int wid = tid >> 5;
    const int wm = wid & 3;
    const int wn = wid >> 2;
    const int m0 = blockIdx.y * 128;
    const int n0 = blockIdx.x * 128;

    const int nch = K >> 5;
    float acc[2][8][4] = {};

    const int lr = (tid >> 2);
    const int lc = tid & 3;

    auto issue = [&](int ci, int stg) {
        const int k0 = ci << 5;
        const uint32_t so = sb + stg * STAGE;
#pragma unroll
        for (int j = 0; j < 2; j++) {
            int r = lr + j * 64;
            uint32_t d = swz((uint32_t)(r * 64 + lc * 16));
            size_t ao = (size_t)(m0 + r) * K + k0 + lc * 8;
            size_t bo = (size_t)(n0 + r) * K + k0 + lc * 8;
            CP16(so + d,         Ah + ao);
            CP16(so + 8192 + d,  Al + ao);
            CP16(so + 16384 + d, Bh + bo);
            CP16(so + 24576 + d, Bl + bo);
        }
        CP_COMMIT();
    };

    issue(0, 0);
    if (nch > 1) issue(1, 1);

    int stg = 0;
    for (int ci = 0; ci < nch; ci++) {
        if (ci + 1 < nch) { CP_WAIT1(); } else { CP_WAIT0(); }
        __syncthreads();
        if (ci + 2 < nch) {
            int ns = stg + 2; if (ns >= 3) ns -= 3;
            issue(ci + 2, ns);
        }
        const uint32_t so = sb + stg * STAGE;

#pragma unroll
        for (int kk = 0; kk < 2; kk++) {
            uint32_t ah[2][4], al_[2][4];
            {
                int ar = lane & 15;
                int akb = kk * 32 + ((lane >> 4) * 16);
#pragma unroll
                for (int i = 0; i < 2; i++) {
                    uint32_t off = swz((uint32_t)((wm * 32 + i * 16 + ar) * 64 + akb));
                    ldsm4(ah[i][0], ah[i][1], ah[i][2], ah[i][3], so + off);
                    ldsm4(al_[i][0], al_[i][1], al_[i][2], al_[i][3], so + 8192 + off);
                }
            }
            uint32_t bh[8][2], bl_[8][2];
            {
                int br = (lane & 7) + ((lane >> 4) & 1) * 8;
                int bkb = ((lane >> 3) & 1) * 16 + kk * 32;
#pragma unroll
                for (int jf = 0; jf < 4; jf++) {
                    uint32_t off = swz((uint32_t)((wn * 64 + jf * 16 + br) * 64 + bkb));
                    uint32_t r0, r1, r2, r3;
                    ldsm4(r0, r1, r2, r3, so + 16384 + off);
                    bh[2 * jf][0] = r0; bh[2 * jf][1] = r1;
                    bh[2 * jf + 1][0] = r2; bh[2 * jf + 1][1] = r3;
                    ldsm4(r0, r1, r2, r3, so + 24576 + off);
                    bl_[2 * jf][0] = r0; bl_[2 * jf][1] = r1;
                    bl_[2 * jf + 1][0] = r2; bl_[2 * jf + 1][1] = r3;
                }
            }
#pragma unroll
            for (int i = 0; i < 2; i++)
#pragma unroll
                for (int j = 0; j < 8; j++)
                    mma16816(acc[i][j], ah[i], bh[j]);
#pragma unroll
            for (int i = 0; i < 2; i++)
#pragma unroll
                for (int j = 0; j < 8; j++)
                    mma16816(acc[i][j], ah[i], bl_[j]);
#pragma unroll
            for (int i = 0; i < 2; i++)
#pragma unroll
                for (int j = 0; j < 8; j++)
                    mma16816(acc[i][j], al_[i], bh[j]);
        }
        stg++; if (stg == 3) stg = 0;
    }

    // ---- epilogue ----
#pragma unroll
    for (int i = 0; i < 2; i++) {
        int row = m0 + wm * 32 + i * 16 + (lane >> 2);
#pragma unroll
        for (int j = 0; j < 8; j++) {
            int col = n0 + wn * 64 + j * 8 + (lane & 3) * 2;
            float b0 = bias[col], b1 = bias[col + 1];
            float v0 = acc[i][j][0] + b0, v1 = acc[i][j][1] + b1;
            float v2 = acc[i][j][2] + b0, v3 = acc[i][j][3] + b1;
            if (EPI >= 1) { v0 = elu1(v0); v1 = elu1(v1); v2 = elu1(v2); v3 = elu1(v3); }
            if (EPI == 2) { v0 = elu1(v0); v1 = elu1(v1); v2 = elu1(v2); v3 = elu1(v3); }
            size_t o0 = (size_t)row * ldC + col;
            size_t o1 = (size_t)(row + 8) * ldC + col;
            if (WF32) {
                *reinterpret_cast<float2*>(C + o0) = make_float2(v0, v1);
                *reinterpret_cast<float2*>(C + o1) = make_float2(v2, v3);
            }
            if (WSPLIT) {
                uint32_t hi, lo;
                cvt_split2(v0, v1, hi, lo);
                *reinterpret_cast<uint32_t*>(Ch + o0) = hi;
                *reinterpret_cast<uint32_t*>(Cl + o0) = lo;
                cvt_split2(v2, v3, hi, lo);
                *reinterpret_cast<uint32_t*>(Ch + o1) = hi;
                *reinterpret_cast<uint32_t*>(Cl + o1) = lo;
            }
        }
    }
}

// ======== single-pass bf16 GEMM for qk (A hi, B hi only, bf16 out) ==========
#define QSTAGE 16384
#define QSMEM (3 * QSTAGE)
__global__ __launch_bounds__(256, 2) void gemm_qk1p(
    const __nv_bfloat16* __restrict__ Ah, const __nv_bfloat16* __restrict__ Bh,
    const float* __restrict__ bias, __nv_bfloat16* __restrict__ Cb,
    int K, int ldC)
{
    extern __shared__ __align__(1024) char smem[];
    const uint32_t sb = smem_u32(smem);
    const int tid = threadIdx.x;
    const int lane = tid & 31;
    const int wid = tid >> 5;
    const int wm = wid & 3;
    const int wn = wid >> 2;
    const int m0 = blockIdx.y * 128;
    const int n0 = blockIdx.x * 128;

    const int nch = K >> 5;
    float acc[2][8][4] = {};
    const int lr = (tid >> 2);
    const int lc = tid & 3;

    auto issue = [&](int ci, int stg) {
        const int k0 = ci << 5;
        const uint32_t so = sb + stg * QSTAGE;
#pragma unroll
        for (int j = 0; j < 2; j++) {
            int r = lr + j * 64;
            uint32_t d = swz((uint32_t)(r * 64 + lc * 16));
            CP16(so + d,        Ah + (size_t)(m0 + r) * K + k0 + lc * 8);
            CP16(so + 8192 + d, Bh + (size_t)(n0 + r) * K + k0 + lc * 8);
        }
        CP_COMMIT();
    };

    issue(0, 0);
    if (nch > 1) issue(1, 1);

    int stg = 0;
    for (int ci = 0; ci < nch; ci++) {
        if (ci + 1 < nch) { CP_WAIT1(); } else { CP_WAIT0(); }
        __syncthreads();
        if (ci + 2 < nch) {
            int ns = stg + 2; if (ns >= 3) ns -= 3;
            issue(ci + 2, ns);
        }
        const uint32_t so = sb + stg * QSTAGE;
#pragma unroll
        for (int kk = 0; kk < 2; kk++) {
            uint32_t ah[2][4];
            {
                int ar = lane & 15;
                int akb = kk * 32 + ((lane >> 4) * 16);
#pragma unroll
                for (int i = 0; i < 2; i++) {
                    uint32_t off = swz((uint32_t)((wm * 32 + i * 16 + ar) * 64 + akb));
                    ldsm4(ah[i][0], ah[i][1], ah[i][2], ah[i][3], so + off);
                }
            }
            uint32_t bh[8][2];
            {
                int br = (lane & 7) + ((lane >> 4) & 1) * 8;
                int bkb = ((lane >> 3) & 1) * 16 + kk * 32;
#pragma unroll
                for (int jf = 0; jf < 4; jf++) {
                    uint32_t off = swz((uint32_t)((wn * 64 + jf * 16 + br) * 64 + bkb));
                    uint32_t r0, r1, r2, r3;
                    ldsm4(r0, r1, r2, r3, so + 8192 + off);
                    bh[2 * jf][0] = r0; bh[2 * jf][1] = r1;
                    bh[2 * jf + 1][0] = r2; bh[2 * jf + 1][1] = r3;
                }
            }
#pragma unroll
            for (int i = 0; i < 2; i++)
#pragma unroll
                for (int j = 0; j < 8; j++)
                    mma16816(acc[i][j], ah[i], bh[j]);
        }
        stg++; if (stg == 3) stg = 0;
    }

#pragma unroll
    for (int i = 0; i < 2; i++) {
        int row = m0 + wm * 32 + i * 16 + (lane >> 2);
#pragma unroll
        for (int j = 0; j < 8; j++) {
            int col = n0 + wn * 64 + j * 8 + (lane & 3) * 2;
            float b0 = bias[col], b1 = bias[col + 1];
            __nv_bfloat162 p0 = __floats2bfloat162_rn(acc[i][j][0] + b0, acc[i][j][1] + b1);
            __nv_bfloat162 p1 = __floats2bfloat162_rn(acc[i][j][2] + b0, acc[i][j][3] + b1);
            *reinterpret_cast<__nv_bfloat162*>(Cb + (size_t)row * ldC + col) = p0;
            *reinterpret_cast<__nv_bfloat162*>(Cb + (size_t)(row + 8) * ldC + col) = p1;
        }
    }
}

// ============ fused A-build GEMMs: A double-buffered, B triple-buffered ======
#define SA 40
#define F2_AH 0
#define F2_AL 10240
#define F2_ASTAGE 20480
#define F2_BH 0
#define F2_BL 8192
#define F2_BSTAGE 16384
#define F2_BOFF (2 * F2_ASTAGE)          // 40960
#define F2_TOT (F2_BOFF + 3 * F2_BSTAGE) // 90112

__device__ __forceinline__ void fused_compute_chunk(
    uint32_t aBase, uint32_t bBase, int lane, int wm, int wn, float acc[2][8][4])
{
#pragma unroll
    for (int kk = 0; kk < 2; kk++) {
        uint32_t ah[2][4], al_[2][4];
        {
            int ar = lane & 15;
            int akc = ((lane >> 4) << 3) + (kk << 4);
#pragma unroll
            for (int i = 0; i < 2; i++) {
                uint32_t off = (uint32_t)((wm * 32 + i * 16 + ar) * SA + akc) * 2;
                ldsm4(ah[i][0], ah[i][1], ah[i][2], ah[i][3], aBase + F2_AH + off);
                ldsm4(al_[i][0], al_[i][1], al_[i][2], al_[i][3], aBase + F2_AL + off);
            }
        }
        uint32_t bh[8][2], bl_[8][2];
        {
            int br = (lane & 7) + ((lane >> 4) & 1) * 8;
            int bkb = ((lane >> 3) & 1) * 16 + kk * 32;
#pragma unroll
            for (int jf = 0; jf < 4; jf++) {
                uint32_t off = swz((uint32_t)((wn * 64 + jf * 16 + br) * 64 + bkb));
                uint32_t r0, r1, r2, r3;
                ldsm4(r0, r1, r2, r3, bBase + F2_BH + off);
                bh[2 * jf][0] = r0; bh[2 * jf][1] = r1;
                bh[2 * jf + 1][0] = r2; bh[2 * jf + 1][1] = r3;
                ldsm4(r0, r1, r2, r3, bBase + F2_BL + off);
                bl_[2 * jf][0] = r0; bl_[2 * jf][1] = r1;
                bl_[2 * jf + 1][0] = r2; bl_[2 * jf + 1][1] = r3;
            }
        }
#pragma unroll
        for (int i = 0; i < 2; i++)
#pragma unroll
            for (int j = 0; j < 8; j++)
                mma16816(acc[i][j], ah[i], bh[j]);
#pragma unroll
        for (int i = 0; i < 2; i++)
#pragma unroll
            for (int j = 0; j < 8; j++)
                mma16816(acc[i][j], ah[i], bl_[j]);
#pragma unroll
        for (int i = 0; i < 2; i++)
#pragma unroll
            for (int j = 0; j < 8; j++)
                mma16816(acc[i][j], al_[i], bh[j]);
    }
}

__device__ __forceinline__ void fused_epilogue_split(
    const float* bias, __nv_bfloat16* Ch, __nv_bfloat16* Cl,
    int m0, int n0, int lane, int wm, int wn, float acc[2][8][4])
{
#pragma unroll
    for (int i = 0; i < 2; i++) {
        int row = m0 + wm * 32 + i * 16 + (lane >> 2);
#pragma unroll
        for (int j = 0; j < 8; j++) {
            int col = n0 + wn * 64 + j * 8 + (lane & 3) * 2;
            float b0 = bias[col], b1 = bias[col + 1];
            float v0 = elu1(acc[i][j][0] + b0), v1 = elu1(acc[i][j][1] + b1);
            float v2 = elu1(acc[i][j][2] + b0), v3 = elu1(acc[i][j][3] + b1);
            size_t o0 = (size_t)row * HIDC + col;
            size_t o1 = (size_t)(row + 8) * HIDC + col;
            uint32_t hi, lo;
            cvt_split2(v0, v1, hi, lo);
            *reinterpret_cast<uint32_t*>(Ch + o0) = hi;
            *reinterpret_cast<uint32_t*>(Cl + o0) = lo;
            cvt_split2(v2, v3, hi, lo);
            *reinterpret_cast<uint32_t*>(Ch + o1) = hi;
            *reinterpret_cast<uint32_t*>(Cl + o1) = lo;
        }
    }
}

// ======== phi1-L1 GEMM with in-kernel split of fp32 peA ======================
#define P1A_SMEM F2_TOT
__global__ __launch_bounds__(256, 2) void gemm_phi1a(
    const float* __restrict__ peA,
    const __nv_bfloat16* __restrict__ Bh, const __nv_bfloat16* __restrict__ Bl,
    const float* __restrict__ bias,
    __nv_bfloat16* __restrict__ Ch, __nv_bfloat16* __restrict__ Cl)
{
    extern __shared__ __align__(1024) char smem[];
    const uint32_t sb = smem_u32(smem);
    const int tid = threadIdx.x;
    const int lane = tid & 31;
    const int wid = tid >> 5;
    const int wm = wid & 3;
    const int wn = wid >> 2;
    const int m0 = blockIdx.y * 128;
    const int n0 = blockIdx.x * 128;
    const int nch = KPAD1 >> 5;   // 17

    float acc[2][8][4] = {};
    float4 a_r[4];

    const int blr = tid >> 2;
    const int blc = tid & 3;

    auto issueB = [&](int ci, int s3) {
        const int k0 = ci << 5;
        const uint32_t so = sb + F2_BOFF + s3 * F2_BSTAGE;
#pragma unroll
        for (int j = 0; j < 2; j++) {
            int r = blr + j * 64;
            uint32_t d = swz((uint32_t)(r * 64 + blc * 16));
            size_t bo = (size_t)(n0 + r) * KPAD1 + k0 + blc * 8;
            CP16(so + F2_BH + d, Bh + bo);
            CP16(so + F2_BL + d, Bl + bo);
        }
        CP_COMMIT();
    };
    auto prefA = [&](int ci) {
        const int k0 = ci << 5;
#pragma unroll
        for (int j = 0; j < 4; j++) {
            int idx = tid + j * 256;
            int r = idx >> 3, c4 = idx & 7;
            int col = k0 + c4 * 4;
            const float* p = peA + (size_t)(m0 + r) * 514 + col;
            float4 v = make_float4(0.f, 0.f, 0.f, 0.f);
            if (col + 3 < 514) {
                float2 x = *reinterpret_cast<const float2*>(p);
                float2 y = *reinterpret_cast<const float2*>(p + 2);
                v = make_float4(x.x, x.y, y.x, y.y);
            } else {
                if (col + 0 < 514) v.x = p[0];
                if (col + 1 < 514) v.y = p[1];
                if (col + 2 < 514) v.z = p[2];
                if (col + 3 < 514) v.w = p[3];
            }
            a_r[j] = v;
        }
    };

    issueB(0, 0);
    issueB(1, 1);
    prefA(0);

    int s3 = 0;
    for (int ci = 0; ci < nch; ci++) {
        const int s2 = ci & 1;
        if (ci + 1 < nch) { CP_WAIT1(); } else { CP_WAIT0(); }
        __syncthreads();
        if (ci + 2 < nch) {
            int ns = s3 + 2; if (ns >= 3) ns -= 3;
            issueB(ci + 2, ns);
        }
#pragma unroll
        for (int j = 0; j < 4; j++) {
            int idx = tid + j * 256;
            int r = idx >> 3, c4 = idx & 7;
            uint32_t hh01, ll01, hh23, ll23;
            cvt_split2(a_r[j].x, a_r[j].y, hh01, ll01);
            cvt_split2(a_r[j].z, a_r[j].w, hh23, ll23);
            uint32_t o = (uint32_t)(r * SA + c4 * 4) * 2;
            *reinterpret_cast<uint2*>(smem + s2 * F2_ASTAGE + F2_AH + o) = make_uint2(hh01, hh23);
            *reinterpret_cast<uint2*>(smem + s2 * F2_ASTAGE + F2_AL + o) = make_uint2(ll01, ll23);
        }
        if (ci + 1 < nch) prefA(ci + 1);
        __syncthreads();
        fused_compute_chunk(sb + s2 * F2_ASTAGE, sb + F2_BOFF + s3 * F2_BSTAGE,
                            lane, wm, wn, acc);
        s3++; if (s3 == 3) s3 = 0;
    }

    fused_epilogue_split(bias, Ch, Cl, m0, n0, lane, wm, wn, acc);
}

// ======== fused alt-value GEMM: A[r,k] = pe + km[g] - (k1h+k1l)/16 ===========
#define FA_SMEM (16384 + F2_TOT)
__global__ __launch_bounds__(256, 2) void gemm_fused_alt(
    const float* __restrict__ pe,
    const __nv_bfloat16* __restrict__ k1h, const __nv_bfloat16* __restrict__ k1l,
    const float* __restrict__ km,
    const __nv_bfloat16* __restrict__ Bh, const __nv_bfloat16* __restrict__ Bl,
    const float* __restrict__ bias,
    __nv_bfloat16* __restrict__ Ch, __nv_bfloat16* __restrict__ Cl)
{
    extern __shared__ __align__(1024) char smem[];
    float* kmS = reinterpret_cast<float*>(smem);
    char* sdata = smem + 16384;
    const uint32_t sb = smem_u32(smem) + 16384;
    const int tid = threadIdx.x;
    const int lane = tid & 31;
    const int wid = tid >> 5;
    const int wm = wid & 3;
    const int wn = wid >> 2;
    const int m0 = blockIdx.y * 128;
    const int n0 = blockIdx.x * 128;
    const int nch = 16;

    float acc[2][8][4] = {};
    float4 pe_r[4];
    uint2 kh_r[4], kl_r[4];

    const int blr = tid >> 2;
    const int blc = tid & 3;

    auto issueB = [&](int ci, int s3) {
        const int k0 = ci << 5;
        const uint32_t so = sb + F2_BOFF + s3 * F2_BSTAGE;
#pragma unroll
        for (int j = 0; j < 2; j++) {
            int r = blr + j * 64;
            uint32_t d = swz((uint32_t)(r * 64 + blc * 16));
            size_t bo = (size_t)(n0 + r) * EFULL + k0 + blc * 8;
            CP16(so + F2_BH + d, Bh + bo);
            CP16(so + F2_BL + d, Bl + bo);
        }
        CP_COMMIT();
    };
    auto prefA = [&](int ci) {
        const int k0 = ci << 5;
#pragma unroll
        for (int j = 0; j < 4; j++) {
            int idx = tid + j * 256;
            int r = idx >> 3, c4 = idx & 7;
            size_t ao = (size_t)(m0 + r) * EFULL + k0 + c4 * 4;
            pe_r[j] = *reinterpret_cast<const float4*>(pe + ao);
            kh_r[j] = *reinterpret_cast<const uint2*>(k1h + ao);
            kl_r[j] = *reinterpret_cast<const uint2*>(k1l + ao);
        }
    };

    const int g0 = m0 >> 4;
    for (int i = tid; i < 4096; i += 256)
        kmS[i] = km[(size_t)(g0 + (i >> 9)) * EFULL + (i & 511)];

    issueB(0, 0);
    issueB(1, 1);
    prefA(0);

    int s3 = 0;
    for (int ci = 0; ci < nch; ci++) {
        const int s2 = ci & 1;
        const int k0 = ci << 5;
        if (ci + 1 < nch) { CP_WAIT1(); } else { CP_WAIT0(); }
        __syncthreads();
        if (ci + 2 < nch) {
            int ns = s3 + 2; if (ns >= 3) ns -= 3;
            issueB(ci + 2, ns);
        }
#pragma unroll
        for (int j = 0; j < 4; j++) {
            int idx = tid + j * 256;
            int r = idx >> 3, c4 = idx & 7;
            const float4 kmv = *reinterpret_cast<const float4*>(
                &kmS[(r >> 4) * EFULL + k0 + c4 * 4]);
            float2 h01 = bf2f2(kh_r[j].x), h23 = bf2f2(kh_r[j].y);
            float2 l01 = bf2f2(kl_r[j].x), l23 = bf2f2(kl_r[j].y);
            float v0 = pe_r[j].x + kmv.x - (h01.x + l01.x) * 0.0625f;
            float v1 = pe_r[j].y + kmv.y - (h01.y + l01.y) * 0.0625f;
            float v2 = pe_r[j].z + kmv.z - (h23.x + l23.x) * 0.0625f;
            float v3 = pe_r[j].w + kmv.w - (h23.y + l23.y) * 0.0625f;
            uint32_t hh01, ll01, hh23, ll23;
            cvt_split2(v0, v1, hh01, ll01);
            cvt_split2(v2, v3, hh23, ll23);
            uint32_t o = (uint32_t)(r * SA + c4 * 4) * 2;
            *reinterpret_cast<uint2*>(sdata + s2 * F2_ASTAGE + F2_AH + o) = make_uint2(hh01, hh23);
            *reinterpret_cast<uint2*>(sdata + s2 * F2_ASTAGE + F2_AL + o) = make_uint2(ll01, ll23);
        }
        if (ci + 1 < nch) prefA(ci + 1);
        __syncthreads();
        fused_compute_chunk(sb + s2 * F2_ASTAGE, sb + F2_BOFF + s3 * F2_BSTAGE,
                            lane, wm, wn, acc);
        s3++; if (s3 == 3) s3 = 0;
    }

    fused_epilogue_split(bias, Ch, Cl, m0, n0, lane, wm, wn, acc);
}

// ---------------- multi-segment weight split (one launch) ----------------
#define MAXSEG 9
struct SplitSegs {
    const float* src[MAXSEG];
    int dstoff[MAXSEG];
    int C[MAXSEG];
    int Cp[MAXSEG];
    int rows[MAXSEG];
    int n;
};
__global__ __launch_bounds__(256) void split_multi(
    SplitSegs p, __nv_bfloat16* __restrict__ dh, __nv_bfloat16* __restrict__ dl)
{
    const uint32_t stride = gridDim.x * 256u;
    const uint32_t base = blockIdx.x * 256u + threadIdx.x;
    for (int s = 0; s < p.n; s++) {
        const float* src = p.src[s];
        const int C = p.C[s], Cp = p.Cp[s], off = p.dstoff[s];
        const uint32_t tot = (uint32_t)p.rows[s] * Cp;
        for (uint32_t i = base; i < tot; i += stride) {
            uint32_t r = i / (uint32_t)Cp;
            int c = (int)(i - r * (uint32_t)Cp);
            float v = (c < C) ? src[(size_t)r * C + c] : 0.f;
            __nv_bfloat16 h = __float2bfloat16(v);
            dh[off + i] = h;
            dl[off + i] = __float2bfloat16(v - __bfloat162float(h));
        }
    }
}

__global__ void warm_kernel(__nv_bfloat16* p) {
    if (blockIdx.x == 0 && threadIdx.x == 0) {
        volatile __nv_bfloat16* q = p;
        q[0] = q[0];
    }
}

// ---------------- attention v3: mma scores ----------------
// 1 group per block. qk tile in smem (padded rows), scores via m16n8k16.
#define AROW 1032   // bf16 elems per padded row
__global__ __launch_bounds__(256) void attn3_kernel(
    const __nv_bfloat16* __restrict__ qk,
    const __nv_bfloat16* __restrict__ xh, const __nv_bfloat16* __restrict__ xl,
    __nv_bfloat16* __restrict__ xwh, __nv_bfloat16* __restrict__ xwl)
{
    const int g = blockIdx.x;
    const int tid = threadIdx.x;
    const int lane = tid & 31;
    const int wid = tid >> 5;
    __shared__ __align__(16) __nv_bfloat16 qks[16 * AROW];
    __shared__ float sc[2][16][17];
    __shared__ float cw[2][16];
    const uint32_t sbq = smem_u32(qks);

    // load 16x1024 bf16 via uint4 (8 per thread)
    {
        const uint4* src = reinterpret_cast<const uint4*>(qk + (size_t)g * GSZ * 1024);
#pragma unroll
        for (int t = 0; t < 8; t++) {
            int idx = tid + t * 256;          // 0..2047
            int row = idx >> 7;               // 128 uint4 per row
            int c8 = idx & 127;
            *reinterpret_cast<uint4*>(qks + row * AROW + c8 * 8) = src[idx];
        }
    }
    __syncthreads();

    // scores: warp h computes head h (h = 0,1)
    if (wid < 2) {
        const int h = wid;
        float accS[2][4] = {};
        const uint32_t qb = (uint32_t)(h * 256) * 2;          // Q col base bytes
        const uint32_t kb = (uint32_t)(512 + h * 256) * 2;    // K col base bytes
#pragma unroll
        for (int ks = 0; ks < 16; ks++) {
            uint32_t a[4];
            {
                int ar = lane & 15;
                uint32_t addr = sbq + (uint32_t)(ar * AROW) * 2 + qb + ks * 32 + (lane >> 4) * 16;
                ldsm4(a[0], a[1], a[2], a[3], addr);
            }
            uint32_t b0[2], b1[2];
            {
                int br = (lane & 7) + ((lane >> 4) & 1) * 8;
                uint32_t addr = sbq + (uint32_t)(br * AROW) * 2 + kb + ks * 32 + ((lane >> 3) & 1) * 16;
                uint32_t r0, r1, r2, r3;
                ldsm4(r0, r1, r2, r3, addr);
                b0[0] = r0; b0[1] = r1;
                b1[0] = r2; b1[1] = r3;
            }
            mma16816(accS[0], a, b0);
            mma16816(accS[1], a, b1);
        }
        // store score frags: row = lane>>2, cols 2*(lane&3) (+8 for frag 1)
        {
            int row = lane >> 2;
            int col = (lane & 3) * 2;
#pragma unroll
            for (int j = 0; j < 2; j++) {
                sc[h][row][j * 8 + col]     = accS[j][0] * 0.0625f;
                sc[h][row][j * 8 + col + 1] = accS[j][1] * 0.0625f;
                sc[h][row + 8][j * 8 + col]     = accS[j][2] * 0.0625f;
                sc[h][row + 8][j * 8 + col + 1] = accS[j][3] * 0.0625f;
            }
        }
    }
    __syncthreads();

    // softmax rows (32 threads: h = t>>4, tq = t&15)
    if (tid < 32) {
        int h = tid >> 4, tq = tid & 15;
        float mx = -1e30f;
#pragma unroll
        for (int tk = 0; tk < 16; tk++) mx = fmaxf(mx, sc[h][tq][tk]);
        float s = 0.f;
#pragma unroll
        for (int tk = 0; tk < 16; tk++) {
            float e = expf(sc[h][tq][tk] - mx);
            sc[h][tq][tk] = e;
            s += e;
        }
        float inv = 1.f / s;
#pragma unroll
        for (int tk = 0; tk < 16; tk++) sc[h][tq][tk] *= inv;
    }
    __syncthreads();
    // column means
    if (tid < 32) {
        int h = tid >> 4, tk = tid & 15;
        float s = 0.f;
#pragma unroll
        for (int tq = 0; tq < 16; tq++) s += sc[h][tq][tk];
        cw[h][tk] = s * 0.0625f;
    }
    __syncthreads();

    // xw: 128 threads, 4 cols each, both heads per pass over x
    if (tid < 128) {
        int d4 = tid * 4;
        const __nv_bfloat16* xbh = xh + (size_t)g * GSZ * 512 + d4;
        const __nv_bfloat16* xbl = xl + (size_t)g * GSZ * 512 + d4;
        float a0[4] = {}, a1[4] = {};
#pragma unroll
        for (int tk = 0; tk < 16; tk++) {
            uint2 vh = *reinterpret_cast<const uint2*>(xbh + tk * 512);
            uint2 vl = *reinterpret_cast<const uint2*>(xbl + tk * 512);
            float2 h01 = bf2f2(vh.x), h23 = bf2f2(vh.y);
            float2 l01 = bf2f2(vl.x), l23 = bf2f2(vl.y);
            float x0 = h01.x + l01.x, x1 = h01.y + l01.y;
            float x2 = h23.x + l23.x, x3 = h23.y + l23.y;
            float w0 = cw[0][tk], w1 = cw[1][tk];
            a0[0] += w0 * x0; a0[1] += w0 * x1; a0[2] += w0 * x2; a0[3] += w0 * x3;
            a1[0] += w1 * x0; a1[1] += w1 * x1; a1[2] += w1 * x2; a1[3] += w1 * x3;
        }
        uint32_t hi, lo, hi2, lo2;
        size_t o0 = (size_t)g * EFULL + d4;
        cvt_split2(a0[0], a0[1], hi, lo);
        cvt_split2(a0[2], a0[3], hi2, lo2);
        *reinterpret_cast<uint2*>(xwh + o0) = make_uint2(hi, hi2);
        *reinterpret_cast<uint2*>(xwl + o0) = make_uint2(lo, lo2);
        size_t o1 = (size_t)NGR * EFULL + o0;
        cvt_split2(a1[0], a1[1], hi, lo);
        cvt_split2(a1[2], a1[3], hi2, lo2);
        *reinterpret_cast<uint2*>(xwh + o1) = make_uint2(hi, hi2);
        *reinterpret_cast<uint2*>(xwl + o1) = make_uint2(lo, lo2);
    }
}

// ---------------- g head final (vectorized) ----------------
__global__ __launch_bounds__(256) void ghead4_kernel(
    const __nv_bfloat16* __restrict__ hh, const __nv_bfloat16* __restrict__ hl,
    const float* __restrict__ w, const float* __restrict__ b,
    float* __restrict__ out)
{
    int row = blockIdx.x * 8 + (threadIdx.x >> 5);
    int lane = threadIdx.x & 31;
    const __nv_bfloat16* ph = hh + (size_t)row * 256;
    const __nv_bfloat16* pl = hl + (size_t)row * 256;
    float acc = 0.f;
#pragma unroll
    for (int it = 0; it < 2; it++) {
        int k = lane * 4 + it * 128;
        uint2 vh = *reinterpret_cast<const uint2*>(ph + k);
        uint2 vl = *reinterpret_cast<const uint2*>(pl + k);
        float2 h01 = bf2f2(vh.x), h23 = bf2f2(vh.y);
        float2 l01 = bf2f2(vl.x), l23 = bf2f2(vl.y);
        const float4 wv = *reinterpret_cast<const float4*>(w + k);
        acc += (h01.x + l01.x) * wv.x + (h01.y + l01.y) * wv.y
             + (h23.x + l23.x) * wv.z + (h23.y + l23.y) * wv.w;
    }
#pragma unroll
    for (int o = 16; o > 0; o >>= 1)
        acc += __shfl_xor_sync(0xffffffffu, acc, o);
    if (lane == 0) out[row] = acc + b[0];
}

// ---------------- alt_q = hp @ w3^T + b3 (256 -> 2, vectorized) -------------
__global__ __launch_bounds__(256) void altq_kernel(
    const __nv_bfloat16* __restrict__ hh, const __nv_bfloat16* __restrict__ hl,
    const float* __restrict__ w, const float* __restrict__ b,
    float* __restrict__ out)
{
    int row = blockIdx.x * 8 + (threadIdx.x >> 5);
    int lane = threadIdx.x & 31;
    const __nv_bfloat16* ph = hh + (size_t)row * 256;
    const __nv_bfloat16* pl = hl + (size_t)row * 256;
    float a0 = 0.f, a1 = 0.f;
#pragma unroll
    for (int it = 0; it < 2; it++) {
        int k = lane * 4 + it * 128;
        uint2 vh = *reinterpret_cast<const uint2*>(ph + k);
        uint2 vl = *reinterpret_cast<const uint2*>(pl + k);
        float2 h01 = bf2f2(vh.x), h23 = bf2f2(vh.y);
        float2 l01 = bf2f2(vl.x), l23 = bf2f2(vl.y);
        float x0 = h01.x + l01.x, x1 = h01.y + l01.y;
        float x2 = h23.x + l23.x, x3 = h23.y + l23.y;
        const float4 w0 = *reinterpret_cast<const float4*>(w + k);
        const float4 w1 = *reinterpret_cast<const float4*>(w + 256 + k);
        a0 += x0 * w0.x + x1 * w0.y + x2 * w0.z + x3 * w0.w;
        a1 += x0 * w1.x + x1 * w1.y + x2 * w1.z + x3 * w1.w;
    }
#pragma unroll
    for (int o = 16; o > 0; o >>= 1) {
        a0 += __shfl_xor_sync(0xffffffffu, a0, o);
        a1 += __shfl_xor_sync(0xffffffffu, a1, o);
    }
    if (lane == 0) {
        out[(size_t)row * 2 + 0] = a0 + b[0];
        out[(size_t)row * 2 + 1] = a1 + b[1];
    }
}

// ================================================================ host launch
extern "C" void kernel_launch(void* const* d_in, const int* in_sizes, int n_in,
                              void* d_out, int out_size)
{
    const float* pe       = (const float*)d_in[0];
    const float* peA      = (const float*)d_in[1];
    const float* attn_in_w  = (const float*)d_in[2];
    const float* attn_in_b  = (const float*)d_in[3];
    const float* attn_out_w = (const float*)d_in[4];
    const float* attn_out_b = (const float*)d_in[5];
    const float* p1w1 = (const float*)d_in[6];  const float* p1b1 = (const float*)d_in[7];
    const float* p1w2 = (const float*)d_in[8];  const float* p1b2 = (const float*)d_in[9];
    const float* p1w3 = (const float*)d_in[10]; const float* p1b3 = (const float*)d_in[11];
    const float* p1w4 = (const float*)d_in[12]; const float* p1b4 = (const float*)d_in[13];
    const float* gw1 = (const float*)d_in[14];  const float* gb1 = (const float*)d_in[15];
    const float* gw2 = (const float*)d_in[16];  const float* gb2 = (const float*)d_in[17];
    const float* gw3 = (const float*)d_in[18];  const float* gb3 = (const float*)d_in[19];
    const float* gw4 = (const float*)d_in[20];  const float* gb4 = (const float*)d_in[21];
    const float* p2w1 = (const float*)d_in[22]; const float* p2b1 = (const float*)d_in[23];
    const float* p2w2 = (const float*)d_in[24]; const float* p2b2 = (const float*)d_in[25];
    const float* p2w3 = (const float*)d_in[26]; const float* p2b3 = (const float*)d_in[27];
    float* out = (float*)d_out;

    #define SYM(T, v, s) T* v; cudaGetSymbolAddress((void**)&v, s)
    SYM(__nv_bfloat16, h1h, g_h1h);   SYM(__nv_bfloat16, h1l, g_h1l);
    SYM(__nv_bfloat16, h2h, g_h2h);   SYM(__nv_bfloat16, h2l, g_h2l);
    SYM(__nv_bfloat16, key1h, g_key1h); SYM(__nv_bfloat16, key1l, g_key1l);
    SYM(__nv_bfloat16, qk, g_qk);
    SYM(__nv_bfloat16, xwh, g_xwh);   SYM(__nv_bfloat16, xwl, g_xwl);
    SYM(__nv_bfloat16, omh, g_omh);   SYM(__nv_bfloat16, oml, g_oml);
    SYM(float, km, g_km);
    SYM(__nv_bfloat16, kmh, g_kmh);   SYM(__nv_bfloat16, kml, g_kml);
    SYM(__nv_bfloat16, hgah, g_hgah); SYM(__nv_bfloat16, hgal, g_hgal);
    SYM(__nv_bfloat16, hgbh, g_hgbh); SYM(__nv_bfloat16, hgbl, g_hgbl);
    SYM(__nv_bfloat16, wph, g_wph);   SYM(__nv_bfloat16, wpl, g_wpl);

    cudaFuncSetAttribute(gemm_bf16<1,false,true>, cudaFuncAttributeMaxDynamicSharedMemorySize, SMEM_TOT);
    cudaFuncSetAttribute(gemm_bf16<2,false,true>, cudaFuncAttributeMaxDynamicSharedMemorySize, SMEM_TOT);
    cudaFuncSetAttribute(gemm_bf16<0,false,true>, cudaFuncAttributeMaxDynamicSharedMemorySize, SMEM_TOT);
    cudaFuncSetAttribute(gemm_bf16<0,true,true>,  cudaFuncAttributeMaxDynamicSharedMemorySize, SMEM_TOT);
    cudaFuncSetAttribute(gemm_qk1p, cudaFuncAttributeMaxDynamicSharedMemorySize, QSMEM);
    cudaFuncSetAttribute(gemm_phi1a, cudaFuncAttributeMaxDynamicSharedMemorySize, P1A_SMEM);
    cudaFuncSetAttribute(gemm_fused_alt, cudaFuncAttributeMaxDynamicSharedMemorySize, FA_SMEM);

    const int TB = 256;
    #define GRID(Mv, Nv) dim3((Nv) / 128, (Mv) / 128)

    // ---- launch #1: phi1 weight splits ----
    {
        SplitSegs s = {};
        int n = 0;
        auto add = [&](const float* src, int off, int R, int C, int Cp) {
            s.src[n] = src; s.dstoff[n] = off; s.rows[n] = R; s.C[n] = C; s.Cp[n] = Cp; n++;
        };
        add(p1w1, OW_P1W1, 256, 514, KPAD1);
        add(p1w2, OW_P1W2, 256, 256, 256);
        add(p1w3, OW_P1W3, 256, 256, 256);
        add(p1w4, OW_P1W4, 512, 256, 256);
        s.n = n;
        split_multi<<<512, TB>>>(s, wph, wpl);
    }
    // ---- launch #2: remaining weight splits ----
    {
        SplitSegs s = {};
        int n = 0;
        auto add = [&](const float* src, int off, int R, int C, int Cp) {
            s.src[n] = src; s.dstoff[n] = off; s.rows[n] = R; s.C[n] = C; s.Cp[n] = Cp; n++;
        };
        add(attn_in_w, OW_WQK, 1024, 512, 512);
        add(attn_in_w + (size_t)1024 * 512, OW_WV0, 256, 512, 512);
        add(attn_in_w + (size_t)1280 * 512, OW_WV1, 256, 512, 512);
        add(attn_out_w, OW_WOUT, 512, 512, 512);
        add(gw1, OW_GW1, 256, 512, 512);
        add(gw2, OW_GW2, 256, 256, 256);
        add(gw3, OW_GW3, 256, 256, 256);
        add(p2w1, OW_P2W1, 256, 512, 512);
        add(p2w2, OW_P2W2, 256, 256, 256);
        s.n = n;
        split_multi<<<512, TB>>>(s, wph, wpl);
    }
    // ---- launch #3: warm ----
    warm_kernel<<<1, 32>>>(wph);

    // ---- launch #4: phi1 L1 (profiled) ----
    gemm_phi1a<<<GRID(NTOK, 256), TB, P1A_SMEM>>>(
        peA, wph + OW_P1W1, wpl + OW_P1W1, p1b1, h1h, h1l);

    // phi1 chain (cont.)
    gemm_bf16<2,false,true><<<GRID(NTOK, HIDC), TB, SMEM_TOT>>>(
        h1h, h1l, wph + OW_P1W2, wpl + OW_P1W2, p1b2, nullptr, h2h, h2l, HIDC, HIDC);
    gemm_bf16<1,false,true><<<GRID(NTOK, HIDC), TB, SMEM_TOT>>>(
        h2h, h2l, wph + OW_P1W3, wpl + OW_P1W3, p1b3, nullptr, h1h, h1l, HIDC, HIDC);
    gemm_bf16<0,false,true><<<GRID(NTOK, EFULL), TB, SMEM_TOT>>>(
        h1h, h1l, wph + OW_P1W4, wpl + OW_P1W4, p1b4, nullptr, key1h, key1l, HIDC, EFULL);

    // q,k projection (single-pass bf16) + attention (mma scores)
    gemm_qk1p<<<GRID(NTOK, 1024), TB, QSMEM>>>(
        key1h, wph + OW_WQK, attn_in_b, qk, EFULL, 1024);
    attn3_kernel<<<NGR, TB>>>(qk, key1h, key1l, xwh, xwl);
    gemm_bf16<0,false,true><<<GRID(NGR, 256), TB, SMEM_TOT>>>(
        xwh, xwl, wph + OW_WV0, wpl + OW_WV0, attn_in_b + 1024,
        nullptr, omh, oml, EFULL, EFULL);
    gemm_bf16<0,false,true><<<GRID(NGR, 256), TB, SMEM_TOT>>>(
        xwh + (size_t)NGR * EFULL, xwl + (size_t)NGR * EFULL,
        wph + OW_WV1, wpl + OW_WV1, attn_in_b + 1280,
        nullptr, omh + 256, oml + 256, EFULL, EFULL);
    gemm_bf16<0,true,true><<<GRID(NGR, EFULL), TB, SMEM_TOT>>>(
        omh, oml, wph + OW_WOUT, wpl + OW_WOUT, attn_out_b, km, kmh, kml, EFULL, EFULL);

    // g head -> q_jt at out[0 .. 4096)
    gemm_bf16<1,false,true><<<GRID(NGR, HIDC), TB, SMEM_TOT>>>(
        kmh, kml, wph + OW_GW1, wpl + OW_GW1, gb1, nullptr, hgah, hgal, EFULL, HIDC);
    gemm_bf16<1,false,true><<<GRID(NGR, HIDC), TB, SMEM_TOT>>>(
        hgah, hgal, wph + OW_GW2, wpl + OW_GW2, gb2, nullptr, hgbh, hgbl, HIDC, HIDC);
    gemm_bf16<1,false,true><<<GRID(NGR, HIDC), TB, SMEM_TOT>>>(
        hgbh, hgbl, wph + OW_GW3, wpl + OW_GW3, gb3, nullptr, hgah, hgal, HIDC, HIDC);
    ghead4_kernel<<<NGR / 8, TB>>>(hgah, hgal, gw4, gb4, out);

    // alt path (altval fused into phi2-L1) -> alt_q at out[4096 ..)
    gemm_fused_alt<<<GRID(NTOK, 256), TB, FA_SMEM>>>(
        pe, key1h, key1l, km, wph + OW_P2W1, wpl + OW_P2W1, p2b1, h1h, h1l);
    gemm_bf16<1,false,true><<<GRID(NTOK, HIDC), TB, SMEM_TOT>>>(
        h1h, h1l, wph + OW_P2W2, wpl + OW_P2W2, p2b2, nullptr, h2h, h2l, HIDC, HIDC);
    altq_kernel<<<NTOK / 8, TB>>>(h2h, h2l, p2w3, p2b3, out + NGR);
}

// round 9
// speedup vs baseline: 1.5364x; 1.0522x over previous
#include <cuda_runtime.h>
#include <cuda_bf16.h>
#include <cstdint>
#include <math.h>

// Problem constants
#define NTOK  65536
#define EFULL 512
#define HIDC  256
#define NGR   4096
#define GSZ   16
#define KPAD1 544          // 514 padded to %32

// ---------------- scratch (__device__ globals) ----------------
__device__ __nv_bfloat16 g_h1h[(size_t)NTOK * HIDC];
__device__ __nv_bfloat16 g_h1l[(size_t)NTOK * HIDC];
__device__ __nv_bfloat16 g_h2h[(size_t)NTOK * HIDC];
__device__ __nv_bfloat16 g_h2l[(size_t)NTOK * HIDC];
__device__ __nv_bfloat16 g_key1h[(size_t)NTOK * EFULL];
__device__ __nv_bfloat16 g_key1l[(size_t)NTOK * EFULL];
__device__ __nv_bfloat16 g_qk[(size_t)NTOK * 1024];
__device__ __nv_bfloat16 g_xwh[(size_t)2 * NGR * EFULL];
__device__ __nv_bfloat16 g_xwl[(size_t)2 * NGR * EFULL];
__device__ __nv_bfloat16 g_omh[(size_t)NGR * EFULL];
__device__ __nv_bfloat16 g_oml[(size_t)NGR * EFULL];
__device__ float         g_km[(size_t)NGR * EFULL];
__device__ __nv_bfloat16 g_kmh[(size_t)NGR * EFULL];
__device__ __nv_bfloat16 g_kml[(size_t)NGR * EFULL];
__device__ __nv_bfloat16 g_hgah[(size_t)NGR * HIDC];
__device__ __nv_bfloat16 g_hgal[(size_t)NGR * HIDC];
__device__ __nv_bfloat16 g_hgbh[(size_t)NGR * HIDC];
__device__ __nv_bfloat16 g_hgbl[(size_t)NGR * HIDC];
__device__ float         g_bc[1024];

// weight pool (split bf16). offsets in elements:
#define OW_P1W1 0
#define OW_P1W2 139264
#define OW_P1W3 204800
#define OW_P1W4 270336
#define OW_WQK  401408
#define OW_WV0  925696
#define OW_WV1  1056768
#define OW_WOUT 1187840
#define OW_GW1  1449984
#define OW_GW2  1581056
#define OW_GW3  1646592
#define OW_P2W1 1712128
#define OW_P2W2 1843200
#define OW_WC   1908736           // composed Wqk@W4: 1024x256
#define OW_TOT  2170880
__device__ __nv_bfloat16 g_wph[OW_TOT];
__device__ __nv_bfloat16 g_wpl[OW_TOT];

__device__ __forceinline__ float elu1(float x) {
    return x > 0.f ? x : (expf(x) - 1.f);
}
__device__ __forceinline__ uint32_t smem_u32(const void* p) {
    uint32_t a;
    asm("{ .reg .u64 t; cvta.to.shared.u64 t, %1; cvt.u32.u64 %0, t; }" : "=r"(a) : "l"(p));
    return a;
}
__device__ __forceinline__ void ldsm4(uint32_t& r0, uint32_t& r1, uint32_t& r2, uint32_t& r3,
                                      uint32_t addr) {
    asm volatile("ldmatrix.sync.aligned.m8n8.x4.shared.b16 {%0,%1,%2,%3}, [%4];"
                 : "=r"(r0), "=r"(r1), "=r"(r2), "=r"(r3) : "r"(addr));
}
__device__ __forceinline__ void mma16816(float* c, const uint32_t* a, const uint32_t* b) {
    asm volatile("mma.sync.aligned.m16n8k16.row.col.f32.bf16.bf16.f32 "
                 "{%0,%1,%2,%3}, {%4,%5,%6,%7}, {%8,%9}, {%0,%1,%2,%3};"
                 : "+f"(c[0]), "+f"(c[1]), "+f"(c[2]), "+f"(c[3])
                 : "r"(a[0]), "r"(a[1]), "r"(a[2]), "r"(a[3]), "r"(b[0]), "r"(b[1]));
}
__device__ __forceinline__ void cvt_split2(float a, float b, uint32_t& hi, uint32_t& lo) {
    __nv_bfloat162 h = __floats2bfloat162_rn(a, b);
    float2 hf = __bfloat1622float2(h);
    __nv_bfloat162 l = __floats2bfloat162_rn(a - hf.x, b - hf.y);
    hi = *reinterpret_cast<uint32_t*>(&h);
    lo = *reinterpret_cast<uint32_t*>(&l);
}
__device__ __forceinline__ float2 bf2f2(uint32_t u) {
    return __bfloat1622float2(*reinterpret_cast<__nv_bfloat162*>(&u));
}
__device__ __forceinline__ uint32_t swz(uint32_t x) { return x ^ ((x >> 3) & 0x70); }

#define CP16(dst, src) \
    asm volatile("cp.async.cg.shared.global [%0], [%1], 16;" :: "r"(dst), "l"(src))
#define CP_COMMIT() asm volatile("cp.async.commit_group;" ::: "memory")
#define CP_WAIT1()  asm volatile("cp.async.wait_group 1;" ::: "memory")
#define CP_WAIT0()  asm volatile("cp.async.wait_group 0;" ::: "memory")

// ======== HMMA NT GEMM with pre-split bf16 operands (3-pass) =================
#define STAGE 32768
#define SMEM_TOT (3 * STAGE)

// shared mainloop body macro-ish via device function on stage pointers
template <int EPI, bool WF32, bool WSPLIT>
__global__ __launch_bounds__(256, 2) void gemm_bf16(
    const __nv_bfloat16* __restrict__ Ah, const __nv_bfloat16* __restrict__ Al,
    const __nv_bfloat16* __restrict__ Bh, const __nv_bfloat16* __restrict__ Bl,
    const float* __restrict__ bias, float* __restrict__ C,
    __nv_bfloat16* __restrict__ Ch, __nv_bfloat16* __restrict__ Cl,
    int K, int ldC)
{
    extern __shared__ __align__(1024) char smem[];
    const uint32_t sb = smem_u32(smem);
    const int tid = threadIdx.x;
    const int lane = tid & 31;
    const int wid = tid >> 5;
    const int wm = wid & 3;
    const int wn = wid >> 2;
    const int m0 = blockIdx.y * 128;
    const int n0 = blockIdx.x * 128;

    const int nch = K >> 5;
    float acc[2][8][4] = {};
    const int lr = (tid >> 2);
    const int lc = tid & 3;

    auto issue = [&](int ci, int stg) {
        const int k0 = ci << 5;
        const uint32_t so = sb + stg * STAGE;
#pragma unroll
        for (int j = 0; j < 2; j++) {
            int r = lr + j * 64;
            uint32_t d = swz((uint32_t)(r * 64 + lc * 16));
            size_t ao = (size_t)(m0 + r) * K + k0 + lc * 8;
            size_t bo = (size_t)(n0 + r) * K + k0 + lc * 8;
            CP16(so + d,         Ah + ao);
            CP16(so + 8192 + d,  Al + ao);
            CP16(so + 16384 + d, Bh + bo);
            CP16(so + 24576 + d, Bl + bo);
        }
        CP_COMMIT();
    };

    issue(0, 0);
    if (nch > 1) issue(1, 1);

    int stg = 0;
    for (int ci = 0; ci < nch; ci++) {
        if (ci + 1 < nch) { CP_WAIT1(); } else { CP_WAIT0(); }
        __syncthreads();
        if (ci + 2 < nch) {
            int ns = stg + 2; if (ns >= 3) ns -= 3;
            issue(ci + 2, ns);
        }
        const uint32_t so = sb + stg * STAGE;
#pragma unroll
        for (int kk = 0; kk < 2; kk++) {
            uint32_t ah[2][4], al_[2][4];
            {
                int ar = lane & 15;
                int akb = kk * 32 + ((lane >> 4) * 16);
#pragma unroll
                for (int i = 0; i < 2; i++) {
                    uint32_t off = swz((uint32_t)((wm * 32 + i * 16 + ar) * 64 + akb));
                    ldsm4(ah[i][0], ah[i][1], ah[i][2], ah[i][3], so + off);
                    ldsm4(al_[i][0], al_[i][1], al_[i][2], al_[i][3], so + 8192 + off);
                }
            }
            uint32_t bh[8][2], bl_[8][2];
            {
                int br = (lane & 7) + ((lane >> 4) & 1) * 8;
                int bkb = ((lane >> 3) & 1) * 16 + kk * 32;
#pragma unroll
                for (int jf = 0; jf < 4; jf++) {
                    uint32_t off = swz((uint32_t)((wn * 64 + jf * 16 + br) * 64 + bkb));
                    uint32_t r0, r1, r2, r3;
                    ldsm4(r0, r1, r2, r3, so + 16384 + off);
                    bh[2 * jf][0] = r0; bh[2 * jf][1] = r1;
                    bh[2 * jf + 1][0] = r2; bh[2 * jf + 1][1] = r3;
                    ldsm4(r0, r1, r2, r3, so + 24576 + off);
                    bl_[2 * jf][0] = r0; bl_[2 * jf][1] = r1;
                    bl_[2 * jf + 1][0] = r2; bl_[2 * jf + 1][1] = r3;
                }
            }
#pragma unroll
            for (int i = 0; i < 2; i++)
#pragma unroll
                for (int j = 0; j < 8; j++)
                    mma16816(acc[i][j], ah[i], bh[j]);
#pragma unroll
            for (int i = 0; i < 2; i++)
#pragma unroll
                for (int j = 0; j < 8; j++)
                    mma16816(acc[i][j], ah[i], bl_[j]);
#pragma unroll
            for (int i = 0; i < 2; i++)
#pragma unroll
                for (int j = 0; j < 8; j++)
                    mma16816(acc[i][j], al_[i], bh[j]);
        }
        stg++; if (stg == 3) stg = 0;
    }

#pragma unroll
    for (int i = 0; i < 2; i++) {
        int row = m0 + wm * 32 + i * 16 + (lane >> 2);
#pragma unroll
        for (int j = 0; j < 8; j++) {
            int col = n0 + wn * 64 + j * 8 + (lane & 3) * 2;
            float b0 = bias[col], b1 = bias[col + 1];
            float v0 = acc[i][j][0] + b0, v1 = acc[i][j][1] + b1;
            float v2 = acc[i][j][2] + b0, v3 = acc[i][j][3] + b1;
            if (EPI >= 1) { v0 = elu1(v0); v1 = elu1(v1); v2 = elu1(v2); v3 = elu1(v3); }
            if (EPI == 2) { v0 = elu1(v0); v1 = elu1(v1); v2 = elu1(v2); v3 = elu1(v3); }
            size_t o0 = (size_t)row * ldC + col;
            size_t o1 = (size_t)(row + 8) * ldC + col;
            if (WF32) {
                *reinterpret_cast<float2*>(C + o0) = make_float2(v0, v1);
                *reinterpret_cast<float2*>(C + o1) = make_float2(v2, v3);
            }
            if (WSPLIT) {
                uint32_t hi, lo;
                cvt_split2(v0, v1, hi, lo);
                *reinterpret_cast<uint32_t*>(Ch + o0) = hi;
                *reinterpret_cast<uint32_t*>(Cl + o0) = lo;
                cvt_split2(v2, v3, hi, lo);
                *reinterpret_cast<uint32_t*>(Ch + o1) = hi;
                *reinterpret_cast<uint32_t*>(Cl + o1) = lo;
            }
        }
    }
}

// ======== GEMM + fused final-dot epilogue (elu, then dot with dw, atomicAdd) =
// N must be 256. dout[row*NOUT + o] += sum_col elu(gemm+bias)[row,col]*dw[o*256+col]
template <int NOUT>
__global__ __launch_bounds__(256, 2) void gemm_dot(
    const __nv_bfloat16* __restrict__ Ah, const __nv_bfloat16* __restrict__ Al,
    const __nv_bfloat16* __restrict__ Bh, const __nv_bfloat16* __restrict__ Bl,
    const float* __restrict__ bias, const float* __restrict__ dw,
    const float* __restrict__ dbias, float* __restrict__ dout, int K)
{
    extern __shared__ __align__(1024) char smem[];
    const uint32_t sb = smem_u32(smem);
    const int tid = threadIdx.x;
    const int lane = tid & 31;
    const int wid = tid >> 5;
    const int wm = wid & 3;
    const int wn = wid >> 2;
    const int m0 = blockIdx.y * 128;
    const int n0 = blockIdx.x * 128;

    const int nch = K >> 5;
    float acc[2][8][4] = {};
    const int lr = (tid >> 2);
    const int lc = tid & 3;

    auto issue = [&](int ci, int stg) {
        const int k0 = ci << 5;
        const uint32_t so = sb + stg * STAGE;
#pragma unroll
        for (int j = 0; j < 2; j++) {
            int r = lr + j * 64;
            uint32_t d = swz((uint32_t)(r * 64 + lc * 16));
            size_t ao = (size_t)(m0 + r) * K + k0 + lc * 8;
            size_t bo = (size_t)(n0 + r) * K + k0 + lc * 8;
            CP16(so + d,         Ah + ao);
            CP16(so + 8192 + d,  Al + ao);
            CP16(so + 16384 + d, Bh + bo);
            CP16(so + 24576 + d, Bl + bo);
        }
        CP_COMMIT();
    };

    issue(0, 0);
    if (nch > 1) issue(1, 1);

    int stg = 0;
    for (int ci = 0; ci < nch; ci++) {
        if (ci + 1 < nch) { CP_WAIT1(); } else { CP_WAIT0(); }
        __syncthreads();
        if (ci + 2 < nch) {
            int ns = stg + 2; if (ns >= 3) ns -= 3;
            issue(ci + 2, ns);
        }
        const uint32_t so = sb + stg * STAGE;
#pragma unroll
        for (int kk = 0; kk < 2; kk++) {
            uint32_t ah[2][4], al_[2][4];
            {
                int ar = lane & 15;
                int akb = kk * 32 + ((lane >> 4) * 16);
#pragma unroll
                for (int i = 0; i < 2; i++) {
                    uint32_t off = swz((uint32_t)((wm * 32 + i * 16 + ar) * 64 + akb));
                    ldsm4(ah[i][0], ah[i][1], ah[i][2], ah[i][3], so + off);
                    ldsm4(al_[i][0], al_[i][1], al_[i][2], al_[i][3], so + 8192 + off);
                }
            }
            uint32_t bh[8][2], bl_[8][2];
            {
                int br = (lane & 7) + ((lane >> 4) & 1) * 8;
                int bkb = ((lane >> 3) & 1) * 16 + kk * 32;
#pragma unroll
                for (int jf = 0; jf < 4; jf++) {
                    uint32_t off = swz((uint32_t)((wn * 64 + jf * 16 + br) * 64 + bkb));
                    uint32_t r0, r1, r2, r3;
                    ldsm4(r0, r1, r2, r3, so + 16384 + off);
                    bh[2 * jf][0] = r0; bh[2 * jf][1] = r1;
                    bh[2 * jf + 1][0] = r2; bh[2 * jf + 1][1] = r3;
                    ldsm4(r0, r1, r2, r3, so + 24576 + off);
                    bl_[2 * jf][0] = r0; bl_[2 * jf][1] = r1;
                    bl_[2 * jf + 1][0] = r2; bl_[2 * jf + 1][1] = r3;
                }
            }
#pragma unroll
            for (int i = 0; i < 2; i++)
#pragma unroll
                for (int j = 0; j < 8; j++)
                    mma16816(acc[i][j], ah[i], bh[j]);
#pragma unroll
            for (int i = 0; i < 2; i++)
#pragma unroll
                for (int j = 0; j < 8; j++)
                    mma16816(acc[i][j], ah[i], bl_[j]);
#pragma unroll
            for (int i = 0; i < 2; i++)
#pragma unroll
                for (int j = 0; j < 8; j++)
                    mma16816(acc[i][j], al_[i], bh[j]);
        }
        stg++; if (stg == 3) stg = 0;
    }

    // ---- fused dot epilogue ----
    float dsum[2][2][NOUT];
#pragma unroll
    for (int i = 0; i < 2; i++)
#pragma unroll
        for (int hf = 0; hf < 2; hf++)
#pragma unroll
            for (int o = 0; o < NOUT; o++) dsum[i][hf][o] = 0.f;

#pragma unroll
    for (int i = 0; i < 2; i++) {
#pragma unroll
        for (int j = 0; j < 8; j++) {
            int col = n0 + wn * 64 + j * 8 + (lane & 3) * 2;
            float b0 = bias[col], b1 = bias[col + 1];
            float v0 = elu1(acc[i][j][0] + b0), v1 = elu1(acc[i][j][1] + b1);
            float v2 = elu1(acc[i][j][2] + b0), v3 = elu1(acc[i][j][3] + b1);
#pragma unroll
            for (int o = 0; o < NOUT; o++) {
                float w0 = dw[o * 256 + col], w1 = dw[o * 256 + col + 1];
                dsum[i][0][o] += v0 * w0 + v1 * w1;
                dsum[i][1][o] += v2 * w0 + v3 * w1;
            }
        }
    }
    // reduce over the 4 lanes sharing a row (lane&3)
#pragma unroll
    for (int i = 0; i < 2; i++)
#pragma unroll
        for (int hf = 0; hf < 2; hf++)
#pragma unroll
            for (int o = 0; o < NOUT; o++) {
                float s = dsum[i][hf][o];
                s += __shfl_xor_sync(0xffffffffu, s, 1);
                s += __shfl_xor_sync(0xffffffffu, s, 2);
                dsum[i][hf][o] = s;
            }
    if ((lane & 3) == 0) {
        const bool addb = (blockIdx.x == 0 && wn == 0);
#pragma unroll
        for (int i = 0; i < 2; i++)
#pragma unroll
            for (int hf = 0; hf < 2; hf++) {
                int row = m0 + wm * 32 + i * 16 + (lane >> 2) + hf * 8;
#pragma unroll
                for (int o = 0; o < NOUT; o++) {
                    float v = dsum[i][hf][o];
                    if (addb) v += dbias[o];
                    atomicAdd(&dout[(size_t)row * NOUT + o], v);
                }
            }
    }
}

// ======== single-pass bf16 GEMM for qk (A hi, B hi only, bf16 out) ==========
#define QSTAGE 16384
#define QSMEM (3 * QSTAGE)
__global__ __launch_bounds__(256, 2) void gemm_qk1p(
    const __nv_bfloat16* __restrict__ Ah, const __nv_bfloat16* __restrict__ Bh,
    const float* __restrict__ bias, __nv_bfloat16* __restrict__ Cb,
    int K, int ldC)
{
    extern __shared__ __align__(1024) char smem[];
    const uint32_t sb = smem_u32(smem);
    const int tid = threadIdx.x;
    const int lane = tid & 31;
    const int wid = tid >> 5;
    const int wm = wid & 3;
    const int wn = wid >> 2;
    const int m0 = blockIdx.y * 128;
    const int n0 = blockIdx.x * 128;

    const int nch = K >> 5;
    float acc[2][8][4] = {};
    const int lr = (tid >> 2);
    const int lc = tid & 3;

    auto issue = [&](int ci, int stg) {
        const int k0 = ci << 5;
        const uint32_t so = sb + stg * QSTAGE;
#pragma unroll
        for (int j = 0; j < 2; j++) {
            int r = lr + j * 64;
            uint32_t d = swz((uint32_t)(r * 64 + lc * 16));
            CP16(so + d,        Ah + (size_t)(m0 + r) * K + k0 + lc * 8);
            CP16(so + 8192 + d, Bh + (size_t)(n0 + r) * K + k0 + lc * 8);
        }
        CP_COMMIT();
    };

    issue(0, 0);
    if (nch > 1) issue(1, 1);

    int stg = 0;
    for (int ci = 0; ci < nch; ci++) {
        if (ci + 1 < nch) { CP_WAIT1(); } else { CP_WAIT0(); }
        __syncthreads();
        if (ci + 2 < nch) {
            int ns = stg + 2; if (ns >= 3) ns -= 3;
            issue(ci + 2, ns);
        }
        const uint32_t so = sb + stg * QSTAGE;
#pragma unroll
        for (int kk = 0; kk < 2; kk++) {
            uint32_t ah[2][4];
            {
                int ar = lane & 15;
                int akb = kk * 32 + ((lane >> 4) * 16);
#pragma unroll
                for (int i = 0; i < 2; i++) {
                    uint32_t off = swz((uint32_t)((wm * 32 + i * 16 + ar) * 64 + akb));
                    ldsm4(ah[i][0], ah[i][1], ah[i][2], ah[i][3], so + off);
                }
            }
            uint32_t bh[8][2];
            {
                int br = (lane & 7) + ((lane >> 4) & 1) * 8;
                int bkb = ((lane >> 3) & 1) * 16 + kk * 32;
#pragma unroll
                for (int jf = 0; jf < 4; jf++) {
                    uint32_t off = swz((uint32_t)((wn * 64 + jf * 16 + br) * 64 + bkb));
                    uint32_t r0, r1, r2, r3;
                    ldsm4(r0, r1, r2, r3, so + 8192 + off);
                    bh[2 * jf][0] = r0; bh[2 * jf][1] = r1;
                    bh[2 * jf + 1][0] = r2; bh[2 * jf + 1][1] = r3;
                }
            }
#pragma unroll
            for (int i = 0; i < 2; i++)
#pragma unroll
                for (int j = 0; j < 8; j++)
                    mma16816(acc[i][j], ah[i], bh[j]);
        }
        stg++; if (stg == 3) stg = 0;
    }

#pragma unroll
    for (int i = 0; i < 2; i++) {
        int row = m0 + wm * 32 + i * 16 + (lane >> 2);
#pragma unroll
        for (int j = 0; j < 8; j++) {
            int col = n0 + wn * 64 + j * 8 + (lane & 3) * 2;
            float b0 = bias[col], b1 = bias[col + 1];
            __nv_bfloat162 p0 = __floats2bfloat162_rn(acc[i][j][0] + b0, acc[i][j][1] + b1);
            __nv_bfloat162 p1 = __floats2bfloat162_rn(acc[i][j][2] + b0, acc[i][j][3] + b1);
            *reinterpret_cast<__nv_bfloat162*>(Cb + (size_t)row * ldC + col) = p0;
            *reinterpret_cast<__nv_bfloat162*>(Cb + (size_t)(row + 8) * ldC + col) = p1;
        }
    }
}

// ============ fused A-build GEMMs: A double-buffered, B triple-buffered ======
#define SA 40
#define F2_AH 0
#define F2_AL 10240
#define F2_ASTAGE 20480
#define F2_BH 0
#define F2_BL 8192
#define F2_BSTAGE 16384
#define F2_BOFF (2 * F2_ASTAGE)
#define F2_TOT (F2_BOFF + 3 * F2_BSTAGE)

__device__ __forceinline__ void fused_compute_chunk(
    uint32_t aBase, uint32_t bBase, int lane, int wm, int wn, float acc[2][8][4])
{
#pragma unroll
    for (int kk = 0; kk < 2; kk++) {
        uint32_t ah[2][4], al_[2][4];
        {
            int ar = lane & 15;
            int akc = ((lane >> 4) << 3) + (kk << 4);
#pragma unroll
            for (int i = 0; i < 2; i++) {
                uint32_t off = (uint32_t)((wm * 32 + i * 16 + ar) * SA + akc) * 2;
                ldsm4(ah[i][0], ah[i][1], ah[i][2], ah[i][3], aBase + F2_AH + off);
                ldsm4(al_[i][0], al_[i][1], al_[i][2], al_[i][3], aBase + F2_AL + off);
            }
        }
        uint32_t bh[8][2], bl_[8][2];
        {
            int br = (lane & 7) + ((lane >> 4) & 1) * 8;
            int bkb = ((lane >> 3) & 1) * 16 + kk * 32;
#pragma unroll
            for (int jf = 0; jf < 4; jf++) {
                uint32_t off = swz((uint32_t)((wn * 64 + jf * 16 + br) * 64 + bkb));
                uint32_t r0, r1, r2, r3;
                ldsm4(r0, r1, r2, r3, bBase + F2_BH + off);
                bh[2 * jf][0] = r0; bh[2 * jf][1] = r1;
                bh[2 * jf + 1][0] = r2; bh[2 * jf + 1][1] = r3;
                ldsm4(r0, r1, r2, r3, bBase + F2_BL + off);
                bl_[2 * jf][0] = r0; bl_[2 * jf][1] = r1;
                bl_[2 * jf + 1][0] = r2; bl_[2 * jf + 1][1] = r3;
            }
        }
#pragma unroll
        for (int i = 0; i < 2; i++)
#pragma unroll
            for (int j = 0; j < 8; j++)
                mma16816(acc[i][j], ah[i], bh[j]);
#pragma unroll
        for (int i = 0; i < 2; i++)
#pragma unroll
            for (int j = 0; j < 8; j++)
                mma16816(acc[i][j], ah[i], bl_[j]);
#pragma unroll
        for (int i = 0; i < 2; i++)
#pragma unroll
            for (int j = 0; j < 8; j++)
                mma16816(acc[i][j], al_[i], bh[j]);
    }
}

__device__ __forceinline__ void fused_epilogue_split(
    const float* bias, __nv_bfloat16* Ch, __nv_bfloat16* Cl,
    int m0, int n0, int lane, int wm, int wn, float acc[2][8][4])
{
#pragma unroll
    for (int i = 0; i < 2; i++) {
        int row = m0 + wm * 32 + i * 16 + (lane >> 2);
#pragma unroll
        for (int j = 0; j < 8; j++) {
            int col = n0 + wn * 64 + j * 8 + (lane & 3) * 2;
            float b0 = bias[col], b1 = bias[col + 1];
            float v0 = elu1(acc[i][j][0] + b0), v1 = elu1(acc[i][j][1] + b1);
            float v2 = elu1(acc[i][j][2] + b0), v3 = elu1(acc[i][j][3] + b1);
            size_t o0 = (size_t)row * HIDC + col;
            size_t o1 = (size_t)(row + 8) * HIDC + col;
            uint32_t hi, lo;
            cvt_split2(v0, v1, hi, lo);
            *reinterpret_cast<uint32_t*>(Ch + o0) = hi;
            *reinterpret_cast<uint32_t*>(Cl + o0) = lo;
            cvt_split2(v2, v3, hi, lo);
            *reinterpret_cast<uint32_t*>(Ch + o1) = hi;
            *reinterpret_cast<uint32_t*>(Cl + o1) = lo;
        }
    }
}

// ======== phi1-L1 GEMM with in-kernel split of fp32 peA ======================
#define P1A_SMEM F2_TOT
__global__ __launch_bounds__(256, 2) void gemm_phi1a(
    const float* __restrict__ peA,
    const __nv_bfloat16* __restrict__ Bh, const __nv_bfloat16* __restrict__ Bl,
    const float* __restrict__ bias,
    __nv_bfloat16* __restrict__ Ch, __nv_bfloat16* __restrict__ Cl)
{
    extern __shared__ __align__(1024) char smem[];
    const uint32_t sb = smem_u32(smem);
    const int tid = threadIdx.x;
    const int lane = tid & 31;
    const int wid = tid >> 5;
    const int wm = wid & 3;
    const int wn = wid >> 2;
    const int m0 = blockIdx.y * 128;
    const int n0 = blockIdx.x * 128;
    const int nch = KPAD1 >> 5;

    float acc[2][8][4] = {};
    float4 a_r[4];
    const int blr = tid >> 2;
    const int blc = tid & 3;

    auto issueB = [&](int ci, int s3) {
        const int k0 = ci << 5;
        const uint32_t so = sb + F2_BOFF + s3 * F2_BSTAGE;
#pragma unroll
        for (int j = 0; j < 2; j++) {
            int r = blr + j * 64;
            uint32_t d = swz((uint32_t)(r * 64 + blc * 16));
            size_t bo = (size_t)(n0 + r) * KPAD1 + k0 + blc * 8;
            CP16(so + F2_BH + d, Bh + bo);
            CP16(so + F2_BL + d, Bl + bo);
        }
        CP_COMMIT();
    };
    auto prefA = [&](int ci) {
        const int k0 = ci << 5;
#pragma unroll
        for (int j = 0; j < 4; j++) {
            int idx = tid + j * 256;
            int r = idx >> 3, c4 = idx & 7;
            int col = k0 + c4 * 4;
            const float* p = peA + (size_t)(m0 + r) * 514 + col;
            float4 v = make_float4(0.f, 0.f, 0.f, 0.f);
            if (col + 3 < 514) {
                float2 x = *reinterpret_cast<const float2*>(p);
                float2 y = *reinterpret_cast<const float2*>(p + 2);
                v = make_float4(x.x, x.y, y.x, y.y);
            } else {
                if (col + 0 < 514) v.x = p[0];
                if (col + 1 < 514) v.y = p[1];
                if (col + 2 < 514) v.z = p[2];
                if (col + 3 < 514) v.w = p[3];
            }
            a_r[j] = v;
        }
    };

    issueB(0, 0);
    issueB(1, 1);
    prefA(0);

    int s3 = 0;
    for (int ci = 0; ci < nch; ci++) {
        const int s2 = ci & 1;
        if (ci + 1 < nch) { CP_WAIT1(); } else { CP_WAIT0(); }
        __syncthreads();
        if (ci + 2 < nch) {
            int ns = s3 + 2; if (ns >= 3) ns -= 3;
            issueB(ci + 2, ns);
        }
#pragma unroll
        for (int j = 0; j < 4; j++) {
            int idx = tid + j * 256;
            int r = idx >> 3, c4 = idx & 7;
            uint32_t hh01, ll01, hh23, ll23;
            cvt_split2(a_r[j].x, a_r[j].y, hh01, ll01);
            cvt_split2(a_r[j].z, a_r[j].w, hh23, ll23);
            uint32_t o = (uint32_t)(r * SA + c4 * 4) * 2;
            *reinterpret_cast<uint2*>(smem + s2 * F2_ASTAGE + F2_AH + o) = make_uint2(hh01, hh23);
            *reinterpret_cast<uint2*>(smem + s2 * F2_ASTAGE + F2_AL + o) = make_uint2(ll01, ll23);
        }
        if (ci + 1 < nch) prefA(ci + 1);
        __syncthreads();
        fused_compute_chunk(sb + s2 * F2_ASTAGE, sb + F2_BOFF + s3 * F2_BSTAGE,
                            lane, wm, wn, acc);
        s3++; if (s3 == 3) s3 = 0;
    }

    fused_epilogue_split(bias, Ch, Cl, m0, n0, lane, wm, wn, acc);
}

// ======== fused alt-value GEMM ===============================================
#define FA_SMEM (16384 + F2_TOT)
__global__ __launch_bounds__(256, 2) void gemm_fused_alt(
    const float* __restrict__ pe,
    const __nv_bfloat16* __restrict__ k1h, const __nv_bfloat16* __restrict__ k1l,
    const float* __restrict__ km,
    const __nv_bfloat16* __restrict__ Bh, const __nv_bfloat16* __restrict__ Bl,
    const float* __restrict__ bias,
    __nv_bfloat16* __restrict__ Ch, __nv_bfloat16* __restrict__ Cl)
{
    extern __shared__ __align__(1024) char smem[];
    float* kmS = reinterpret_cast<float*>(smem);
    char* sdata = smem + 16384;
    const uint32_t sb = smem_u32(smem) + 16384;
    const int tid = threadIdx.x;
    const int lane = tid & 31;
    const int wid = tid >> 5;
    const int wm = wid & 3;
    const int wn = wid >> 2;
    const int m0 = blockIdx.y * 128;
    const int n0 = blockIdx.x * 128;
    const int nch = 16;

    float acc[2][8][4] = {};
    float4 pe_r[4];
    uint2 kh_r[4], kl_r[4];
    const int blr = tid >> 2;
    const int blc = tid & 3;

    auto issueB = [&](int ci, int s3) {
        const int k0 = ci << 5;
        const uint32_t so = sb + F2_BOFF + s3 * F2_BSTAGE;
#pragma unroll
        for (int j = 0; j < 2; j++) {
            int r = blr + j * 64;
            uint32_t d = swz((uint32_t)(r * 64 + blc * 16));
            size_t bo = (size_t)(n0 + r) * EFULL + k0 + blc * 8;
            CP16(so + F2_BH + d, Bh + bo);
            CP16(so + F2_BL + d, Bl + bo);
        }
        CP_COMMIT();
    };
    auto prefA = [&](int ci) {
        const int k0 = ci << 5;
#pragma unroll
        for (int j = 0; j < 4; j++) {
            int idx = tid + j * 256;
            int r = idx >> 3, c4 = idx & 7;
            size_t ao = (size_t)(m0 + r) * EFULL + k0 + c4 * 4;
            pe_r[j] = *reinterpret_cast<const float4*>(pe + ao);
            kh_r[j] = *reinterpret_cast<const uint2*>(k1h + ao);
            kl_r[j] = *reinterpret_cast<const uint2*>(k1l + ao);
        }
    };

    const int g0 = m0 >> 4;
    for (int i = tid; i < 4096; i += 256)
        kmS[i] = km[(size_t)(g0 + (i >> 9)) * EFULL + (i & 511)];

    issueB(0, 0);
    issueB(1, 1);
    prefA(0);

    int s3 = 0;
    for (int ci = 0; ci < nch; ci++) {
        const int s2 = ci & 1;
        const int k0 = ci << 5;
        if (ci + 1 < nch) { CP_WAIT1(); } else { CP_WAIT0(); }
        __syncthreads();
        if (ci + 2 < nch) {
            int ns = s3 + 2; if (ns >= 3) ns -= 3;
            issueB(ci + 2, ns);
        }
#pragma unroll
        for (int j = 0; j < 4; j++) {
            int idx = tid + j * 256;
            int r = idx >> 3, c4 = idx & 7;
            const float4 kmv = *reinterpret_cast<const float4*>(
                &kmS[(r >> 4) * EFULL + k0 + c4 * 4]);
            float2 h01 = bf2f2(kh_r[j].x), h23 = bf2f2(kh_r[j].y);
            float2 l01 = bf2f2(kl_r[j].x), l23 = bf2f2(kl_r[j].y);
            float v0 = pe_r[j].x + kmv.x - (h01.x + l01.x) * 0.0625f;
            float v1 = pe_r[j].y + kmv.y - (h01.y + l01.y) * 0.0625f;
            float v2 = pe_r[j].z + kmv.z - (h23.x + l23.x) * 0.0625f;
            float v3 = pe_r[j].w + kmv.w - (h23.y + l23.y) * 0.0625f;
            uint32_t hh01, ll01, hh23, ll23;
            cvt_split2(v0, v1, hh01, ll01);
            cvt_split2(v2, v3, hh23, ll23);
            uint32_t o = (uint32_t)(r * SA + c4 * 4) * 2;
            *reinterpret_cast<uint2*>(sdata + s2 * F2_ASTAGE + F2_AH + o) = make_uint2(hh01, hh23);
            *reinterpret_cast<uint2*>(sdata + s2 * F2_ASTAGE + F2_AL + o) = make_uint2(ll01, ll23);
        }
        if (ci + 1 < nch) prefA(ci + 1);
        __syncthreads();
        fused_compute_chunk(sb + s2 * F2_ASTAGE, sb + F2_BOFF + s3 * F2_BSTAGE,
                            lane, wm, wn, acc);
        s3++; if (s3 == 3) s3 = 0;
    }

    fused_epilogue_split(bias, Ch, Cl, m0, n0, lane, wm, wn, acc);
}

// ---------------- multi-segment weight split ----------------
#define MAXSEG 9
struct SplitSegs {
    const float* src[MAXSEG];
    int dstoff[MAXSEG];
    int C[MAXSEG];
    int Cp[MAXSEG];
    int rows[MAXSEG];
    int n;
};
__global__ __launch_bounds__(256) void split_multi(
    SplitSegs p, __nv_bfloat16* __restrict__ dh, __nv_bfloat16* __restrict__ dl)
{
    const uint32_t stride = gridDim.x * 256u;
    const uint32_t base = blockIdx.x * 256u + threadIdx.x;
    for (int s = 0; s < p.n; s++) {
        const float* src = p.src[s];
        const int C = p.C[s], Cp = p.Cp[s], off = p.dstoff[s];
        const uint32_t tot = (uint32_t)p.rows[s] * Cp;
        for (uint32_t i = base; i < tot; i += stride) {
            uint32_t r = i / (uint32_t)Cp;
            int c = (int)(i - r * (uint32_t)Cp);
            float v = (c < C) ? src[(size_t)r * C + c] : 0.f;
            __nv_bfloat16 h = __float2bfloat16(v);
            dh[off + i] = h;
            dl[off + i] = __float2bfloat16(v - __bfloat162float(h));
        }
    }
}

// ---------------- compose Wc = Wqk @ W4, bc = Wqk@b4 + bqk ------------------
__global__ __launch_bounds__(256) void compose_wc(
    const float* __restrict__ wqk, const float* __restrict__ w4,
    const float* __restrict__ b4, const float* __restrict__ bqk,
    __nv_bfloat16* __restrict__ ch, __nv_bfloat16* __restrict__ cl,
    float* __restrict__ bc)
{
    __shared__ float wrow[512];
    const int n = blockIdx.x;
    const int tid = threadIdx.x;
    wrow[tid] = wqk[(size_t)n * 512 + tid];
    wrow[tid + 256] = wqk[(size_t)n * 512 + tid + 256];
    __syncthreads();
    float acc = 0.f;
#pragma unroll 8
    for (int j = 0; j < 512; j++)
        acc += wrow[j] * w4[(size_t)j * 256 + tid];
    __nv_bfloat16 h = __float2bfloat16(acc);
    ch[(size_t)n * 256 + tid] = h;
    cl[(size_t)n * 256 + tid] = __float2bfloat16(acc - __bfloat162float(h));
    if (tid < 32) {
        float s = 0.f;
        for (int j = tid; j < 512; j += 32) s += wrow[j] * b4[j];
#pragma unroll
        for (int o = 16; o > 0; o >>= 1) s += __shfl_xor_sync(0xffffffffu, s, o);
        if (tid == 0) bc[n] = s + bqk[n];
    }
}

// ---------------- zero output ----------------
__global__ __launch_bounds__(256) void zero_out(float* __restrict__ p, int n) {
    int i = blockIdx.x * 256 + threadIdx.x;
    if (i < n) p[i] = 0.f;
}

// ---------------- attention v3: mma scores ----------------
#define AROW 1032
__global__ __launch_bounds__(256) void attn3_kernel(
    const __nv_bfloat16* __restrict__ qk,
    const __nv_bfloat16* __restrict__ xh, const __nv_bfloat16* __restrict__ xl,
    __nv_bfloat16* __restrict__ xwh, __nv_bfloat16* __restrict__ xwl)
{
    const int g = blockIdx.x;
    const int tid = threadIdx.x;
    const int lane = tid & 31;
    const int wid = tid >> 5;
    __shared__ __align__(16) __nv_bfloat16 qks[16 * AROW];
    __shared__ float sc[2][16][17];
    __shared__ float cw[2][16];
    const uint32_t sbq = smem_u32(qks);

    {
        const uint4* src = reinterpret_cast<const uint4*>(qk + (size_t)g * GSZ * 1024);
#pragma unroll
        for (int t = 0; t < 8; t++) {
            int idx = tid + t * 256;
            int row = idx >> 7;
            int c8 = idx & 127;
            *reinterpret_cast<uint4*>(qks + row * AROW + c8 * 8) = src[idx];
        }
    }
    __syncthreads();

    if (wid < 2) {
        const int h = wid;
        float accS[2][4] = {};
        const uint32_t qb = (uint32_t)(h * 256) * 2;
        const uint32_t kb = (uint32_t)(512 + h * 256) * 2;
#pragma unroll
        for (int ks = 0; ks < 16; ks++) {
            uint32_t a[4];
            {
                int ar = lane & 15;
                uint32_t addr = sbq + (uint32_t)(ar * AROW) * 2 + qb + ks * 32 + (lane >> 4) * 16;
                ldsm4(a[0], a[1], a[2], a[3], addr);
            }
            uint32_t b0[2], b1[2];
            {
                int br = (lane & 7) + ((lane >> 4) & 1) * 8;
                uint32_t addr = sbq + (uint32_t)(br * AROW) * 2 + kb + ks * 32 + ((lane >> 3) & 1) * 16;
                uint32_t r0, r1, r2, r3;
                ldsm4(r0, r1, r2, r3, addr);
                b0[0] = r0; b0[1] = r1;
                b1[0] = r2; b1[1] = r3;
            }
            mma16816(accS[0], a, b0);
            mma16816(accS[1], a, b1);
        }
        {
            int row = lane >> 2;
            int col = (lane & 3) * 2;
#pragma unroll
            for (int j = 0; j < 2; j++) {
                sc[h][row][j * 8 + col]     = accS[j][0] * 0.0625f;
                sc[h][row][j * 8 + col + 1] = accS[j][1] * 0.0625f;
                sc[h][row + 8][j * 8 + col]     = accS[j][2] * 0.0625f;
                sc[h][row + 8][j * 8 + col + 1] = accS[j][3] * 0.0625f;
            }
        }
    }
    __syncthreads();

    if (tid < 32) {
        int h = tid >> 4, tq = tid & 15;
        float mx = -1e30f;
#pragma unroll
        for (int tk = 0; tk < 16; tk++) mx = fmaxf(mx, sc[h][tq][tk]);
        float s = 0.f;
#pragma unroll
        for (int tk = 0; tk < 16; tk++) {
            float e = expf(sc[h][tq][tk] - mx);
            sc[h][tq][tk] = e;
            s += e;
        }
        float inv = 1.f / s;
#pragma unroll
        for (int tk = 0; tk < 16; tk++) sc[h][tq][tk] *= inv;
    }
    __syncthreads();
    if (tid < 32) {
        int h = tid >> 4, tk = tid & 15;
        float s = 0.f;
#pragma unroll
        for (int tq = 0; tq < 16; tq++) s += sc[h][tq][tk];
        cw[h][tk] = s * 0.0625f;
    }
    __syncthreads();

    if (tid < 128) {
        int d4 = tid * 4;
        const __nv_bfloat16* xbh = xh + (size_t)g * GSZ * 512 + d4;
        const __nv_bfloat16* xbl = xl + (size_t)g * GSZ * 512 + d4;
        float a0[4] = {}, a1[4] = {};
#pragma unroll
        for (int tk = 0; tk < 16; tk++) {
            uint2 vh = *reinterpret_cast<const uint2*>(xbh + tk * 512);
            uint2 vl = *reinterpret_cast<const uint2*>(xbl + tk * 512);
            float2 h01 = bf2f2(vh.x), h23 = bf2f2(vh.y);
            float2 l01 = bf2f2(vl.x), l23 = bf2f2(vl.y);
            float x0 = h01.x + l01.x, x1 = h01.y + l01.y;
            float x2 = h23.x + l23.x, x3 = h23.y + l23.y;
            float w0 = cw[0][tk], w1 = cw[1][tk];
            a0[0] += w0 * x0; a0[1] += w0 * x1; a0[2] += w0 * x2; a0[3] += w0 * x3;
            a1[0] += w1 * x0; a1[1] += w1 * x1; a1[2] += w1 * x2; a1[3] += w1 * x3;
        }
        uint32_t hi, lo, hi2, lo2;
        size_t o0 = (size_t)g * EFULL + d4;
        cvt_split2(a0[0], a0[1], hi, lo);
        cvt_split2(a0[2], a0[3], hi2, lo2);
        *reinterpret_cast<uint2*>(xwh + o0) = make_uint2(hi, hi2);
        *reinterpret_cast<uint2*>(xwl + o0) = make_uint2(lo, lo2);
        size_t o1 = (size_t)NGR * EFULL + o0;
        cvt_split2(a1[0], a1[1], hi, lo);
        cvt_split2(a1[2], a1[3], hi2, lo2);
        *reinterpret_cast<uint2*>(xwh + o1) = make_uint2(hi, hi2);
        *reinterpret_cast<uint2*>(xwl + o1) = make_uint2(lo, lo2);
    }
}

// ================================================================ host launch
extern "C" void kernel_launch(void* const* d_in, const int* in_sizes, int n_in,
                              void* d_out, int out_size)
{
    const float* pe       = (const float*)d_in[0];
    const float* peA      = (const float*)d_in[1];
    const float* attn_in_w  = (const float*)d_in[2];
    const float* attn_in_b  = (const float*)d_in[3];
    const float* attn_out_w = (const float*)d_in[4];
    const float* attn_out_b = (const float*)d_in[5];
    const float* p1w1 = (const float*)d_in[6];  const float* p1b1 = (const float*)d_in[7];
    const float* p1w2 = (const float*)d_in[8];  const float* p1b2 = (const float*)d_in[9];
    const float* p1w3 = (const float*)d_in[10]; const float* p1b3 = (const float*)d_in[11];
    const float* p1w4 = (const float*)d_in[12]; const float* p1b4 = (const float*)d_in[13];
    const float* gw1 = (const float*)d_in[14];  const float* gb1 = (const float*)d_in[15];
    const float* gw2 = (const float*)d_in[16];  const float* gb2 = (const float*)d_in[17];
    const float* gw3 = (const float*)d_in[18];  const float* gb3 = (const float*)d_in[19];
    const float* gw4 = (const float*)d_in[20];  const float* gb4 = (const float*)d_in[21];
    const float* p2w1 = (const float*)d_in[22]; const float* p2b1 = (const float*)d_in[23];
    const float* p2w2 = (const float*)d_in[24]; const float* p2b2 = (const float*)d_in[25];
    const float* p2w3 = (const float*)d_in[26]; const float* p2b3 = (const float*)d_in[27];
    float* out = (float*)d_out;

    #define SYM(T, v, s) T* v; cudaGetSymbolAddress((void**)&v, s)
    SYM(__nv_bfloat16, h1h, g_h1h);   SYM(__nv_bfloat16, h1l, g_h1l);
    SYM(__nv_bfloat16, h2h, g_h2h);   SYM(__nv_bfloat16, h2l, g_h2l);
    SYM(__nv_bfloat16, key1h, g_key1h); SYM(__nv_bfloat16, key1l, g_key1l);
    SYM(__nv_bfloat16, qk, g_qk);
    SYM(__nv_bfloat16, xwh, g_xwh);   SYM(__nv_bfloat16, xwl, g_xwl);
    SYM(__nv_bfloat16, omh, g_omh);   SYM(__nv_bfloat16, oml, g_oml);
    SYM(float, km, g_km);
    SYM(__nv_bfloat16, kmh, g_kmh);   SYM(__nv_bfloat16, kml, g_kml);
    SYM(__nv_bfloat16, hgah, g_hgah); SYM(__nv_bfloat16, hgal, g_hgal);
    SYM(__nv_bfloat16, hgbh, g_hgbh); SYM(__nv_bfloat16, hgbl, g_hgbl);
    SYM(__nv_bfloat16, wph, g_wph);   SYM(__nv_bfloat16, wpl, g_wpl);
    SYM(float, bc, g_bc);

    cudaFuncSetAttribute(gemm_bf16<1,false,true>, cudaFuncAttributeMaxDynamicSharedMemorySize, SMEM_TOT);
    cudaFuncSetAttribute(gemm_bf16<2,false,true>, cudaFuncAttributeMaxDynamicSharedMemorySize, SMEM_TOT);
    cudaFuncSetAttribute(gemm_bf16<0,false,true>, cudaFuncAttributeMaxDynamicSharedMemorySize, SMEM_TOT);
    cudaFuncSetAttribute(gemm_bf16<0,true,true>,  cudaFuncAttributeMaxDynamicSharedMemorySize, SMEM_TOT);
    cudaFuncSetAttribute(gemm_dot<1>, cudaFuncAttributeMaxDynamicSharedMemorySize, SMEM_TOT);
    cudaFuncSetAttribute(gemm_dot<2>, cudaFuncAttributeMaxDynamicSharedMemorySize, SMEM_TOT);
    cudaFuncSetAttribute(gemm_qk1p, cudaFuncAttributeMaxDynamicSharedMemorySize, QSMEM);
    cudaFuncSetAttribute(gemm_phi1a, cudaFuncAttributeMaxDynamicSharedMemorySize, P1A_SMEM);
    cudaFuncSetAttribute(gemm_fused_alt, cudaFuncAttributeMaxDynamicSharedMemorySize, FA_SMEM);

    const int TB = 256;
    #define GRID(Mv, Nv) dim3((Nv) / 128, (Mv) / 128)

    // #1: zero the output (fused dot epilogues accumulate into it)
    zero_out<<<(out_size + 255) / 256, TB>>>(out, out_size);

    // #2: phi1 weight splits
    {
        SplitSegs s = {};
        int n = 0;
        auto add = [&](const float* src, int off, int R, int C, int Cp) {
            s.src[n] = src; s.dstoff[n] = off; s.rows[n] = R; s.C[n] = C; s.Cp[n] = Cp; n++;
        };
        add(p1w1, OW_P1W1, 256, 514, KPAD1);
        add(p1w2, OW_P1W2, 256, 256, 256);
        add(p1w3, OW_P1W3, 256, 256, 256);
        add(p1w4, OW_P1W4, 512, 256, 256);
        s.n = n;
        split_multi<<<512, TB>>>(s, wph, wpl);
    }
    // #3: remaining weight splits
    {
        SplitSegs s = {};
        int n = 0;
        auto add = [&](const float* src, int off, int R, int C, int Cp) {
            s.src[n] = src; s.dstoff[n] = off; s.rows[n] = R; s.C[n] = C; s.Cp[n] = Cp; n++;
        };
        add(attn_in_w + (size_t)1024 * 512, OW_WV0, 256, 512, 512);
        add(attn_in_w + (size_t)1280 * 512, OW_WV1, 256, 512, 512);
        add(attn_out_w, OW_WOUT, 512, 512, 512);
        add(gw1, OW_GW1, 256, 512, 512);
        add(gw2, OW_GW2, 256, 256, 256);
        add(gw3, OW_GW3, 256, 256, 256);
        add(p2w1, OW_P2W1, 256, 512, 512);
        add(p2w2, OW_P2W2, 256, 256, 256);
        s.n = n;
        split_multi<<<512, TB>>>(s, wph, wpl);
    }

    // #4: phi1 L1 (profiled)
    gemm_phi1a<<<GRID(NTOK, 256), TB, P1A_SMEM>>>(
        peA, wph + OW_P1W1, wpl + OW_P1W1, p1b1, h1h, h1l);

    // #5: compose Wc = Wqk@W4, bc
    compose_wc<<<1024, TB>>>(attn_in_w, p1w4, p1b4, attn_in_b,
                             wph + OW_WC, wpl + OW_WC, bc);

    // phi1 chain (cont.)
    gemm_bf16<2,false,true><<<GRID(NTOK, HIDC), TB, SMEM_TOT>>>(
        h1h, h1l, wph + OW_P1W2, wpl + OW_P1W2, p1b2, nullptr, h2h, h2l, HIDC, HIDC);
    gemm_bf16<1,false,true><<<GRID(NTOK, HIDC), TB, SMEM_TOT>>>(
        h2h, h2l, wph + OW_P1W3, wpl + OW_P1W3, p1b3, nullptr, h1h, h1l, HIDC, HIDC);
    gemm_bf16<0,false,true><<<GRID(NTOK, EFULL), TB, SMEM_TOT>>>(
        h1h, h1l, wph + OW_P1W4, wpl + OW_P1W4, p1b4, nullptr, key1h, key1l, HIDC, EFULL);

    // qk = h1 @ Wc^T + bc  (K=256, exact composition; single-pass bf16)
    gemm_qk1p<<<GRID(NTOK, 1024), TB, QSMEM>>>(
        h1h, wph + OW_WC, bc, qk, HIDC, 1024);
    attn3_kernel<<<NGR, TB>>>(qk, key1h, key1l, xwh, xwl);
    gemm_bf16<0,false,true><<<GRID(NGR, 256), TB, SMEM_TOT>>>(
        xwh, xwl, wph + OW_WV0, wpl + OW_WV0, attn_in_b + 1024,
        nullptr, omh, oml, EFULL, EFULL);
    gemm_bf16<0,false,true><<<GRID(NGR, 256), TB, SMEM_TOT>>>(
        xwh + (size_t)NGR * EFULL, xwl + (size_t)NGR * EFULL,
        wph + OW_WV1, wpl + OW_WV1, attn_in_b + 1280,
        nullptr, omh + 256, oml + 256, EFULL, EFULL);
    gemm_bf16<0,true,true><<<GRID(NGR, EFULL), TB, SMEM_TOT>>>(
        omh, oml, wph + OW_WOUT, wpl + OW_WOUT, attn_out_b, km, kmh, kml, EFULL, EFULL);

    // g head -> q_jt at out[0 .. 4096)  (gw3 + final dot fused)
    gemm_bf16<1,false,true><<<GRID(NGR, HIDC), TB, SMEM_TOT>>>(
        kmh, kml, wph + OW_GW1, wpl + OW_GW1, gb1, nullptr, hgah, hgal, EFULL, HIDC);
    gemm_bf16<1,false,true><<<GRID(NGR, HIDC), TB, SMEM_TOT>>>(
        hgah, hgal, wph + OW_GW2, wpl + OW_GW2, gb2, nullptr, hgbh, hgbl, HIDC, HIDC);
    gemm_dot<1><<<GRID(NGR, HIDC), TB, SMEM_TOT>>>(
        hgbh, hgbl, wph + OW_GW3, wpl + OW_GW3, gb3, gw4, gb4, out, HIDC);

    // alt path -> alt_q at out[4096 ..)  (p2w2 + final dot fused)
    gemm_fused_alt<<<GRID(NTOK, 256), TB, FA_SMEM>>>(
        pe, key1h, key1l, km, wph + OW_P2W1, wpl + OW_P2W1, p2b1, h1h, h1l);
    gemm_dot<2><<<GRID(NTOK, HIDC), TB, SMEM_TOT>>>(
        h1h, h1l, wph + OW_P2W2, wpl + OW_P2W2, p2b2, p2w3, p2b3, out + NGR, HIDC);
}

// round 10
// speedup vs baseline: 1.8290x; 1.1905x over previous
#include <cuda_runtime.h>
#include <cuda_bf16.h>
#include <cstdint>
#include <math.h>

// Problem constants
#define NTOK  65536
#define EFULL 512
#define HIDC  256
#define NGR   4096
#define GSZ   16
#define KPAD1 544          // 514 padded to %32

// ---------------- scratch (__device__ globals) ----------------
__device__ __nv_bfloat16 g_h1h[(size_t)NTOK * HIDC];
__device__ __nv_bfloat16 g_h1l[(size_t)NTOK * HIDC];
__device__ __nv_bfloat16 g_h2h[(size_t)NTOK * HIDC];
__device__ __nv_bfloat16 g_h2l[(size_t)NTOK * HIDC];
__device__ __nv_bfloat16 g_qk[(size_t)NTOK * 1024];
__device__ __nv_bfloat16 g_xwh[(size_t)2 * NGR * HIDC];
__device__ __nv_bfloat16 g_xwl[(size_t)2 * NGR * HIDC];
__device__ __nv_bfloat16 g_omh[(size_t)NGR * EFULL];
__device__ __nv_bfloat16 g_oml[(size_t)NGR * EFULL];
__device__ float         g_km[(size_t)NGR * EFULL];
__device__ __nv_bfloat16 g_kmh[(size_t)NGR * EFULL];
__device__ __nv_bfloat16 g_kml[(size_t)NGR * EFULL];
__device__ float         g_kmp[(size_t)NGR * HIDC];
__device__ __nv_bfloat16 g_hgah[(size_t)NGR * HIDC];
__device__ __nv_bfloat16 g_hgal[(size_t)NGR * HIDC];
__device__ __nv_bfloat16 g_hgbh[(size_t)NGR * HIDC];
__device__ __nv_bfloat16 g_hgbl[(size_t)NGR * HIDC];
__device__ float         g_bc[1024];
__device__ float         g_bv2[512];
__device__ float         g_bb[256];

// weight pool (split bf16). offsets in elements:
#define OW_P1W1 0                 // 256x544
#define OW_P1W2 139264            // 256x256
#define OW_P1W3 204800            // 256x256
#define OW_WOUT 270336            // 512x512
#define OW_GW1  532480            // 256x512
#define OW_GW2  663552            // 256x256
#define OW_GW3  729088            // 256x256
#define OW_P2W1 794624            // 256x512
#define OW_P2W2 925696            // 256x256
#define OW_WC   991232            // Wqk@W4: 1024x256
#define OW_WVC  1253376           // (Wv01@W4): 512x256 (both heads)
#define OW_WC3  1384448           // -(P2W1@W4)/16: 256x256
#define OW_TOT  1449984
__device__ __nv_bfloat16 g_wph[OW_TOT];
__device__ __nv_bfloat16 g_wpl[OW_TOT];

__device__ __forceinline__ float elu1(float x) {
    return x > 0.f ? x : (expf(x) - 1.f);
}
__device__ __forceinline__ uint32_t smem_u32(const void* p) {
    uint32_t a;
    asm("{ .reg .u64 t; cvta.to.shared.u64 t, %1; cvt.u32.u64 %0, t; }" : "=r"(a) : "l"(p));
    return a;
}
__device__ __forceinline__ void ldsm4(uint32_t& r0, uint32_t& r1, uint32_t& r2, uint32_t& r3,
                                      uint32_t addr) {
    asm volatile("ldmatrix.sync.aligned.m8n8.x4.shared.b16 {%0,%1,%2,%3}, [%4];"
                 : "=r"(r0), "=r"(r1), "=r"(r2), "=r"(r3) : "r"(addr));
}
__device__ __forceinline__ void mma16816(float* c, const uint32_t* a, const uint32_t* b) {
    asm volatile("mma.sync.aligned.m16n8k16.row.col.f32.bf16.bf16.f32 "
                 "{%0,%1,%2,%3}, {%4,%5,%6,%7}, {%8,%9}, {%0,%1,%2,%3};"
                 : "+f"(c[0]), "+f"(c[1]), "+f"(c[2]), "+f"(c[3])
                 : "r"(a[0]), "r"(a[1]), "r"(a[2]), "r"(a[3]), "r"(b[0]), "r"(b[1]));
}
__device__ __forceinline__ void cvt_split2(float a, float b, uint32_t& hi, uint32_t& lo) {
    __nv_bfloat162 h = __floats2bfloat162_rn(a, b);
    float2 hf = __bfloat1622float2(h);
    __nv_bfloat162 l = __floats2bfloat162_rn(a - hf.x, b - hf.y);
    hi = *reinterpret_cast<uint32_t*>(&h);
    lo = *reinterpret_cast<uint32_t*>(&l);
}
__device__ __forceinline__ float2 bf2f2(uint32_t u) {
    return __bfloat1622float2(*reinterpret_cast<__nv_bfloat162*>(&u));
}
__device__ __forceinline__ uint32_t swz(uint32_t x) { return x ^ ((x >> 3) & 0x70); }

#define CP16(dst, src) \
    asm volatile("cp.async.cg.shared.global [%0], [%1], 16;" :: "r"(dst), "l"(src))
#define CP_COMMIT() asm volatile("cp.async.commit_group;" ::: "memory")
#define CP_WAIT1()  asm volatile("cp.async.wait_group 1;" ::: "memory")
#define CP_WAIT0()  asm volatile("cp.async.wait_group 0;" ::: "memory")

// ======== HMMA NT GEMM with pre-split bf16 operands (3-pass) =================
#define STAGE 32768
#define SMEM_TOT (3 * STAGE)

template <int EPI, bool WF32, bool WSPLIT>
__global__ __launch_bounds__(256, 2) void gemm_bf16(
    const __nv_bfloat16* __restrict__ Ah, const __nv_bfloat16* __restrict__ Al,
    const __nv_bfloat16* __restrict__ Bh, const __nv_bfloat16* __restrict__ Bl,
    const float* __restrict__ bias, float* __restrict__ C,
    __nv_bfloat16* __restrict__ Ch, __nv_bfloat16* __restrict__ Cl,
    int K, int ldC)
{
    extern __shared__ __align__(1024) char smem[];
    const uint32_t sb = smem_u32(smem);
    const int tid = threadIdx.x;
    const int lane = tid & 31;
    const int wid = tid >> 5;
    const int wm = wid & 3;
    const int wn = wid >> 2;
    const int m0 = blockIdx.y * 128;
    const int n0 = blockIdx.x * 128;

    const int nch = K >> 5;
    float acc[2][8][4] = {};
    const int lr = (tid >> 2);
    const int lc = tid & 3;

    auto issue = [&](int ci, int stg) {
        const int k0 = ci << 5;
        const uint32_t so = sb + stg * STAGE;
#pragma unroll
        for (int j = 0; j < 2; j++) {
            int r = lr + j * 64;
            uint32_t d = swz((uint32_t)(r * 64 + lc * 16));
            size_t ao = (size_t)(m0 + r) * K + k0 + lc * 8;
            size_t bo = (size_t)(n0 + r) * K + k0 + lc * 8;
            CP16(so + d,         Ah + ao);
            CP16(so + 8192 + d,  Al + ao);
            CP16(so + 16384 + d, Bh + bo);
            CP16(so + 24576 + d, Bl + bo);
        }
        CP_COMMIT();
    };

    issue(0, 0);
    if (nch > 1) issue(1, 1);

    int stg = 0;
    for (int ci = 0; ci < nch; ci++) {
        if (ci + 1 < nch) { CP_WAIT1(); } else { CP_WAIT0(); }
        __syncthreads();
        if (ci + 2 < nch) {
            int ns = stg + 2; if (ns >= 3) ns -= 3;
            issue(ci + 2, ns);
        }
        const uint32_t so = sb + stg * STAGE;
#pragma unroll
        for (int kk = 0; kk < 2; kk++) {
            uint32_t ah[2][4], al_[2][4];
            {
                int ar = lane & 15;
                int akb = kk * 32 + ((lane >> 4) * 16);
#pragma unroll
                for (int i = 0; i < 2; i++) {
                    uint32_t off = swz((uint32_t)((wm * 32 + i * 16 + ar) * 64 + akb));
                    ldsm4(ah[i][0], ah[i][1], ah[i][2], ah[i][3], so + off);
                    ldsm4(al_[i][0], al_[i][1], al_[i][2], al_[i][3], so + 8192 + off);
                }
            }
            uint32_t bh[8][2], bl_[8][2];
            {
                int br = (lane & 7) + ((lane >> 4) & 1) * 8;
                int bkb = ((lane >> 3) & 1) * 16 + kk * 32;
#pragma unroll
                for (int jf = 0; jf < 4; jf++) {
                    uint32_t off = swz((uint32_t)((wn * 64 + jf * 16 + br) * 64 + bkb));
                    uint32_t r0, r1, r2, r3;
                    ldsm4(r0, r1, r2, r3, so + 16384 + off);
                    bh[2 * jf][0] = r0; bh[2 * jf][1] = r1;
                    bh[2 * jf + 1][0] = r2; bh[2 * jf + 1][1] = r3;
                    ldsm4(r0, r1, r2, r3, so + 24576 + off);
                    bl_[2 * jf][0] = r0; bl_[2 * jf][1] = r1;
                    bl_[2 * jf + 1][0] = r2; bl_[2 * jf + 1][1] = r3;
                }
            }
#pragma unroll
            for (int i = 0; i < 2; i++)
#pragma unroll
                for (int j = 0; j < 8; j++)
                    mma16816(acc[i][j], ah[i], bh[j]);
#pragma unroll
            for (int i = 0; i < 2; i++)
#pragma unroll
                for (int j = 0; j < 8; j++)
                    mma16816(acc[i][j], ah[i], bl_[j]);
#pragma unroll
            for (int i = 0; i < 2; i++)
#pragma unroll
                for (int j = 0; j < 8; j++)
                    mma16816(acc[i][j], al_[i], bh[j]);
        }
        stg++; if (stg == 3) stg = 0;
    }

#pragma unroll
    for (int i = 0; i < 2; i++) {
        int row = m0 + wm * 32 + i * 16 + (lane >> 2);
#pragma unroll
        for (int j = 0; j < 8; j++) {
            int col = n0 + wn * 64 + j * 8 + (lane & 3) * 2;
            float b0 = bias[col], b1 = bias[col + 1];
            float v0 = acc[i][j][0] + b0, v1 = acc[i][j][1] + b1;
            float v2 = acc[i][j][2] + b0, v3 = acc[i][j][3] + b1;
            if (EPI >= 1) { v0 = elu1(v0); v1 = elu1(v1); v2 = elu1(v2); v3 = elu1(v3); }
            if (EPI == 2) { v0 = elu1(v0); v1 = elu1(v1); v2 = elu1(v2); v3 = elu1(v3); }
            size_t o0 = (size_t)row * ldC + col;
            size_t o1 = (size_t)(row + 8) * ldC + col;
            if (WF32) {
                *reinterpret_cast<float2*>(C + o0) = make_float2(v0, v1);
                *reinterpret_cast<float2*>(C + o1) = make_float2(v2, v3);
            }
            if (WSPLIT) {
                uint32_t hi, lo;
                cvt_split2(v0, v1, hi, lo);
                *reinterpret_cast<uint32_t*>(Ch + o0) = hi;
                *reinterpret_cast<uint32_t*>(Cl + o0) = lo;
                cvt_split2(v2, v3, hi, lo);
                *reinterpret_cast<uint32_t*>(Ch + o1) = hi;
                *reinterpret_cast<uint32_t*>(Cl + o1) = lo;
            }
        }
    }
}

// ======== GEMM + fused final-dot epilogue ====================================
template <int NOUT>
__global__ __launch_bounds__(256, 2) void gemm_dot(
    const __nv_bfloat16* __restrict__ Ah, const __nv_bfloat16* __restrict__ Al,
    const __nv_bfloat16* __restrict__ Bh, const __nv_bfloat16* __restrict__ Bl,
    const float* __restrict__ bias, const float* __restrict__ dw,
    const float* __restrict__ dbias, float* __restrict__ dout, int K)
{
    extern __shared__ __align__(1024) char smem[];
    const uint32_t sb = smem_u32(smem);
    const int tid = threadIdx.x;
    const int lane = tid & 31;
    const int wid = tid >> 5;
    const int wm = wid & 3;
    const int wn = wid >> 2;
    const int m0 = blockIdx.y * 128;
    const int n0 = blockIdx.x * 128;

    const int nch = K >> 5;
    float acc[2][8][4] = {};
    const int lr = (tid >> 2);
    const int lc = tid & 3;

    auto issue = [&](int ci, int stg) {
        const int k0 = ci << 5;
        const uint32_t so = sb + stg * STAGE;
#pragma unroll
        for (int j = 0; j < 2; j++) {
            int r = lr + j * 64;
            uint32_t d = swz((uint32_t)(r * 64 + lc * 16));
            size_t ao = (size_t)(m0 + r) * K + k0 + lc * 8;
            size_t bo = (size_t)(n0 + r) * K + k0 + lc * 8;
            CP16(so + d,         Ah + ao);
            CP16(so + 8192 + d,  Al + ao);
            CP16(so + 16384 + d, Bh + bo);
            CP16(so + 24576 + d, Bl + bo);
        }
        CP_COMMIT();
    };

    issue(0, 0);
    if (nch > 1) issue(1, 1);

    int stg = 0;
    for (int ci = 0; ci < nch; ci++) {
        if (ci + 1 < nch) { CP_WAIT1(); } else { CP_WAIT0(); }
        __syncthreads();
        if (ci + 2 < nch) {
            int ns = stg + 2; if (ns >= 3) ns -= 3;
            issue(ci + 2, ns);
        }
        const uint32_t so = sb + stg * STAGE;
#pragma unroll
        for (int kk = 0; kk < 2; kk++) {
            uint32_t ah[2][4], al_[2][4];
            {
                int ar = lane & 15;
                int akb = kk * 32 + ((lane >> 4) * 16);
#pragma unroll
                for (int i = 0; i < 2; i++) {
                    uint32_t off = swz((uint32_t)((wm * 32 + i * 16 + ar) * 64 + akb));
                    ldsm4(ah[i][0], ah[i][1], ah[i][2], ah[i][3], so + off);
                    ldsm4(al_[i][0], al_[i][1], al_[i][2], al_[i][3], so + 8192 + off);
                }
            }
            uint32_t bh[8][2], bl_[8][2];
            {
                int br = (lane & 7) + ((lane >> 4) & 1) * 8;
                int bkb = ((lane >> 3) & 1) * 16 + kk * 32;
#pragma unroll
                for (int jf = 0; jf < 4; jf++) {
                    uint32_t off = swz((uint32_t)((wn * 64 + jf * 16 + br) * 64 + bkb));
                    uint32_t r0, r1, r2, r3;
                    ldsm4(r0, r1, r2, r3, so + 16384 + off);
                    bh[2 * jf][0] = r0; bh[2 * jf][1] = r1;
                    bh[2 * jf + 1][0] = r2; bh[2 * jf + 1][1] = r3;
                    ldsm4(r0, r1, r2, r3, so + 24576 + off);
                    bl_[2 * jf][0] = r0; bl_[2 * jf][1] = r1;
                    bl_[2 * jf + 1][0] = r2; bl_[2 * jf + 1][1] = r3;
                }
            }
#pragma unroll
            for (int i = 0; i < 2; i++)
#pragma unroll
                for (int j = 0; j < 8; j++)
                    mma16816(acc[i][j], ah[i], bh[j]);
#pragma unroll
            for (int i = 0; i < 2; i++)
#pragma unroll
                for (int j = 0; j < 8; j++)
                    mma16816(acc[i][j], ah[i], bl_[j]);
#pragma unroll
            for (int i = 0; i < 2; i++)
#pragma unroll
                for (int j = 0; j < 8; j++)
                    mma16816(acc[i][j], al_[i], bh[j]);
        }
        stg++; if (stg == 3) stg = 0;
    }

    float dsum[2][2][NOUT];
#pragma unroll
    for (int i = 0; i < 2; i++)
#pragma unroll
        for (int hf = 0; hf < 2; hf++)
#pragma unroll
            for (int o = 0; o < NOUT; o++) dsum[i][hf][o] = 0.f;

#pragma unroll
    for (int i = 0; i < 2; i++) {
#pragma unroll
        for (int j = 0; j < 8; j++) {
            int col = n0 + wn * 64 + j * 8 + (lane & 3) * 2;
            float b0 = bias[col], b1 = bias[col + 1];
            float v0 = elu1(acc[i][j][0] + b0), v1 = elu1(acc[i][j][1] + b1);
            float v2 = elu1(acc[i][j][2] + b0), v3 = elu1(acc[i][j][3] + b1);
#pragma unroll
            for (int o = 0; o < NOUT; o++) {
                float w0 = dw[o * 256 + col], w1 = dw[o * 256 + col + 1];
                dsum[i][0][o] += v0 * w0 + v1 * w1;
                dsum[i][1][o] += v2 * w0 + v3 * w1;
            }
        }
    }
#pragma unroll
    for (int i = 0; i < 2; i++)
#pragma unroll
        for (int hf = 0; hf < 2; hf++)
#pragma unroll
            for (int o = 0; o < NOUT; o++) {
                float s = dsum[i][hf][o];
                s += __shfl_xor_sync(0xffffffffu, s, 1);
                s += __shfl_xor_sync(0xffffffffu, s, 2);
                dsum[i][hf][o] = s;
            }
    if ((lane & 3) == 0) {
        const bool addb = (blockIdx.x == 0 && wn == 0);
#pragma unroll
        for (int i = 0; i < 2; i++)
#pragma unroll
            for (int hf = 0; hf < 2; hf++) {
                int row = m0 + wm * 32 + i * 16 + (lane >> 2) + hf * 8;
#pragma unroll
                for (int o = 0; o < NOUT; o++) {
                    float v = dsum[i][hf][o];
                    if (addb) v += dbias[o];
                    atomicAdd(&dout[(size_t)row * NOUT + o], v);
                }
            }
    }
}

// ======== single-pass bf16 GEMM for qk ======================================
#define QSTAGE 16384
#define QSMEM (3 * QSTAGE)
__global__ __launch_bounds__(256, 2) void gemm_qk1p(
    const __nv_bfloat16* __restrict__ Ah, const __nv_bfloat16* __restrict__ Bh,
    const float* __restrict__ bias, __nv_bfloat16* __restrict__ Cb,
    int K, int ldC)
{
    extern __shared__ __align__(1024) char smem[];
    const uint32_t sb = smem_u32(smem);
    const int tid = threadIdx.x;
    const int lane = tid & 31;
    const int wid = tid >> 5;
    const int wm = wid & 3;
    const int wn = wid >> 2;
    const int m0 = blockIdx.y * 128;
    const int n0 = blockIdx.x * 128;

    const int nch = K >> 5;
    float acc[2][8][4] = {};
    const int lr = (tid >> 2);
    const int lc = tid & 3;

    auto issue = [&](int ci, int stg) {
        const int k0 = ci << 5;
        const uint32_t so = sb + stg * QSTAGE;
#pragma unroll
        for (int j = 0; j < 2; j++) {
            int r = lr + j * 64;
            uint32_t d = swz((uint32_t)(r * 64 + lc * 16));
            CP16(so + d,        Ah + (size_t)(m0 + r) * K + k0 + lc * 8);
            CP16(so + 8192 + d, Bh + (size_t)(n0 + r) * K + k0 + lc * 8);
        }
        CP_COMMIT();
    };

    issue(0, 0);
    if (nch > 1) issue(1, 1);

    int stg = 0;
    for (int ci = 0; ci < nch; ci++) {
        if (ci + 1 < nch) { CP_WAIT1(); } else { CP_WAIT0(); }
        __syncthreads();
        if (ci + 2 < nch) {
            int ns = stg + 2; if (ns >= 3) ns -= 3;
            issue(ci + 2, ns);
        }
        const uint32_t so = sb + stg * QSTAGE;
#pragma unroll
        for (int kk = 0; kk < 2; kk++) {
            uint32_t ah[2][4];
            {
                int ar = lane & 15;
                int akb = kk * 32 + ((lane >> 4) * 16);
#pragma unroll
                for (int i = 0; i < 2; i++) {
                    uint32_t off = swz((uint32_t)((wm * 32 + i * 16 + ar) * 64 + akb));
                    ldsm4(ah[i][0], ah[i][1], ah[i][2], ah[i][3], so + off);
                }
            }
            uint32_t bh[8][2];
            {
                int br = (lane & 7) + ((lane >> 4) & 1) * 8;
                int bkb = ((lane >> 3) & 1) * 16 + kk * 32;
#pragma unroll
                for (int jf = 0; jf < 4; jf++) {
                    uint32_t off = swz((uint32_t)((wn * 64 + jf * 16 + br) * 64 + bkb));
                    uint32_t r0, r1, r2, r3;
                    ldsm4(r0, r1, r2, r3, so + 8192 + off);
                    bh[2 * jf][0] = r0; bh[2 * jf][1] = r1;
                    bh[2 * jf + 1][0] = r2; bh[2 * jf + 1][1] = r3;
                }
            }
#pragma unroll
            for (int i = 0; i < 2; i++)
#pragma unroll
                for (int j = 0; j < 8; j++)
                    mma16816(acc[i][j], ah[i], bh[j]);
        }
        stg++; if (stg == 3) stg = 0;
    }

#pragma unroll
    for (int i = 0; i < 2; i++) {
        int row = m0 + wm * 32 + i * 16 + (lane >> 2);
#pragma unroll
        for (int j = 0; j < 8; j++) {
            int col = n0 + wn * 64 + j * 8 + (lane & 3) * 2;
            float b0 = bias[col], b1 = bias[col + 1];
            __nv_bfloat162 p0 = __floats2bfloat162_rn(acc[i][j][0] + b0, acc[i][j][1] + b1);
            __nv_bfloat162 p1 = __floats2bfloat162_rn(acc[i][j][2] + b0, acc[i][j][3] + b1);
            *reinterpret_cast<__nv_bfloat162*>(Cb + (size_t)row * ldC + col) = p0;
            *reinterpret_cast<__nv_bfloat162*>(Cb + (size_t)(row + 8) * ldC + col) = p1;
        }
    }
}

// ============ fused A-build GEMM machinery (SA=40 A layout) ==================
#define SA 40
#define F2_AH 0
#define F2_AL 10240
#define F2_ASTAGE 20480
#define F2_BH 0
#define F2_BL 8192
#define F2_BSTAGE 16384
#define F2_BOFF (2 * F2_ASTAGE)
#define F2_TOT (F2_BOFF + 3 * F2_BSTAGE)

__device__ __forceinline__ void fused_compute_chunk(
    uint32_t aBase, uint32_t bBase, int lane, int wm, int wn, float acc[2][8][4])
{
#pragma unroll
    for (int kk = 0; kk < 2; kk++) {
        uint32_t ah[2][4], al_[2][4];
        {
            int ar = lane & 15;
            int akc = ((lane >> 4) << 3) + (kk << 4);
#pragma unroll
            for (int i = 0; i < 2; i++) {
                uint32_t off = (uint32_t)((wm * 32 + i * 16 + ar) * SA + akc) * 2;
                ldsm4(ah[i][0], ah[i][1], ah[i][2], ah[i][3], aBase + F2_AH + off);
                ldsm4(al_[i][0], al_[i][1], al_[i][2], al_[i][3], aBase + F2_AL + off);
            }
        }
        uint32_t bh[8][2], bl_[8][2];
        {
            int br = (lane & 7) + ((lane >> 4) & 1) * 8;
            int bkb = ((lane >> 3) & 1) * 16 + kk * 32;
#pragma unroll
            for (int jf = 0; jf < 4; jf++) {
                uint32_t off = swz((uint32_t)((wn * 64 + jf * 16 + br) * 64 + bkb));
                uint32_t r0, r1, r2, r3;
                ldsm4(r0, r1, r2, r3, bBase + F2_BH + off);
                bh[2 * jf][0] = r0; bh[2 * jf][1] = r1;
                bh[2 * jf + 1][0] = r2; bh[2 * jf + 1][1] = r3;
                ldsm4(r0, r1, r2, r3, bBase + F2_BL + off);
                bl_[2 * jf][0] = r0; bl_[2 * jf][1] = r1;
                bl_[2 * jf + 1][0] = r2; bl_[2 * jf + 1][1] = r3;
            }
        }
#pragma unroll
        for (int i = 0; i < 2; i++)
#pragma unroll
            for (int j = 0; j < 8; j++)
                mma16816(acc[i][j], ah[i], bh[j]);
#pragma unroll
        for (int i = 0; i < 2; i++)
#pragma unroll
            for (int j = 0; j < 8; j++)
                mma16816(acc[i][j], ah[i], bl_[j]);
#pragma unroll
        for (int i = 0; i < 2; i++)
#pragma unroll
            for (int j = 0; j < 8; j++)
                mma16816(acc[i][j], al_[i], bh[j]);
    }
}

__device__ __forceinline__ void fused_epilogue_split(
    const float* bias, __nv_bfloat16* Ch, __nv_bfloat16* Cl,
    int m0, int n0, int lane, int wm, int wn, float acc[2][8][4])
{
#pragma unroll
    for (int i = 0; i < 2; i++) {
        int row = m0 + wm * 32 + i * 16 + (lane >> 2);
#pragma unroll
        for (int j = 0; j < 8; j++) {
            int col = n0 + wn * 64 + j * 8 + (lane & 3) * 2;
            float b0 = bias[col], b1 = bias[col + 1];
            float v0 = elu1(acc[i][j][0] + b0), v1 = elu1(acc[i][j][1] + b1);
            float v2 = elu1(acc[i][j][2] + b0), v3 = elu1(acc[i][j][3] + b1);
            size_t o0 = (size_t)row * HIDC + col;
            size_t o1 = (size_t)(row + 8) * HIDC + col;
            uint32_t hi, lo;
            cvt_split2(v0, v1, hi, lo);
            *reinterpret_cast<uint32_t*>(Ch + o0) = hi;
            *reinterpret_cast<uint32_t*>(Cl + o0) = lo;
            cvt_split2(v2, v3, hi, lo);
            *reinterpret_cast<uint32_t*>(Ch + o1) = hi;
            *reinterpret_cast<uint32_t*>(Cl + o1) = lo;
        }
    }
}

// ======== phi1-L1 GEMM with in-kernel split of fp32 peA ======================
#define P1A_SMEM F2_TOT
__global__ __launch_bounds__(256, 2) void gemm_phi1a(
    const float* __restrict__ peA,
    const __nv_bfloat16* __restrict__ Bh, const __nv_bfloat16* __restrict__ Bl,
    const float* __restrict__ bias,
    __nv_bfloat16* __restrict__ Ch, __nv_bfloat16* __restrict__ Cl)
{
    extern __shared__ __align__(1024) char smem[];
    const uint32_t sb = smem_u32(smem);
    const int tid = threadIdx.x;
    const int lane = tid & 31;
    const int wid = tid >> 5;
    const int wm = wid & 3;
    const int wn = wid >> 2;
    const int m0 = blockIdx.y * 128;
    const int n0 = blockIdx.x * 128;
    const int nch = KPAD1 >> 5;

    float acc[2][8][4] = {};
    float4 a_r[4];
    const int blr = tid >> 2;
    const int blc = tid & 3;

    auto issueB = [&](int ci, int s3) {
        const int k0 = ci << 5;
        const uint32_t so = sb + F2_BOFF + s3 * F2_BSTAGE;
#pragma unroll
        for (int j = 0; j < 2; j++) {
            int r = blr + j * 64;
            uint32_t d = swz((uint32_t)(r * 64 + blc * 16));
            size_t bo = (size_t)(n0 + r) * KPAD1 + k0 + blc * 8;
            CP16(so + F2_BH + d, Bh + bo);
            CP16(so + F2_BL + d, Bl + bo);
        }
        CP_COMMIT();
    };
    auto prefA = [&](int ci) {
        const int k0 = ci << 5;
#pragma unroll
        for (int j = 0; j < 4; j++) {
            int idx = tid + j * 256;
            int r = idx >> 3, c4 = idx & 7;
            int col = k0 + c4 * 4;
            const float* p = peA + (size_t)(m0 + r) * 514 + col;
            float4 v = make_float4(0.f, 0.f, 0.f, 0.f);
            if (col + 3 < 514) {
                float2 x = *reinterpret_cast<const float2*>(p);
                float2 y = *reinterpret_cast<const float2*>(p + 2);
                v = make_float4(x.x, x.y, y.x, y.y);
            } else {
                if (col + 0 < 514) v.x = p[0];
                if (col + 1 < 514) v.y = p[1];
                if (col + 2 < 514) v.z = p[2];
                if (col + 3 < 514) v.w = p[3];
            }
            a_r[j] = v;
        }
    };

    issueB(0, 0);
    issueB(1, 1);
    prefA(0);

    int s3 = 0;
    for (int ci = 0; ci < nch; ci++) {
        const int s2 = ci & 1;
        if (ci + 1 < nch) { CP_WAIT1(); } else { CP_WAIT0(); }
        __syncthreads();
        if (ci + 2 < nch) {
            int ns = s3 + 2; if (ns >= 3) ns -= 3;
            issueB(ci + 2, ns);
        }
#pragma unroll
        for (int j = 0; j < 4; j++) {
            int idx = tid + j * 256;
            int r = idx >> 3, c4 = idx & 7;
            uint32_t hh01, ll01, hh23, ll23;
            cvt_split2(a_r[j].x, a_r[j].y, hh01, ll01);
            cvt_split2(a_r[j].z, a_r[j].w, hh23, ll23);
            uint32_t o = (uint32_t)(r * SA + c4 * 4) * 2;
            *reinterpret_cast<uint2*>(smem + s2 * F2_ASTAGE + F2_AH + o) = make_uint2(hh01, hh23);
            *reinterpret_cast<uint2*>(smem + s2 * F2_ASTAGE + F2_AL + o) = make_uint2(ll01, ll23);
        }
        if (ci + 1 < nch) prefA(ci + 1);
        __syncthreads();
        fused_compute_chunk(sb + s2 * F2_ASTAGE, sb + F2_BOFF + s3 * F2_BSTAGE,
                            lane, wm, wn, acc);
        s3++; if (s3 == 3) s3 = 0;
    }

    fused_epilogue_split(bias, Ch, Cl, m0, n0, lane, wm, wn, acc);
}

// ======== alt2: dual-source GEMM =============================================
// C = elu( pe@P2W1^T  +  h1@Wc3m^T  +  kmP[group] ), split output.
// Phase 1: 16 chunks over pe (K=512, fp32 split on the fly, B=P2W1 stride 512)
// Phase 2: 8 chunks over h1 (K=256, pre-split, B=Wc3m stride 256)
#define ALT2_KMP 8192
#define ALT2_SMEM (ALT2_KMP + F2_TOT)
__global__ __launch_bounds__(256, 2) void gemm_alt2(
    const float* __restrict__ pe,
    const __nv_bfloat16* __restrict__ h1h, const __nv_bfloat16* __restrict__ h1l,
    const float* __restrict__ kmP,
    const __nv_bfloat16* __restrict__ B1h, const __nv_bfloat16* __restrict__ B1l,
    const __nv_bfloat16* __restrict__ B2h, const __nv_bfloat16* __restrict__ B2l,
    __nv_bfloat16* __restrict__ Ch, __nv_bfloat16* __restrict__ Cl)
{
    extern __shared__ __align__(1024) char smem[];
    float* kmS = reinterpret_cast<float*>(smem);
    char* sdata = smem + ALT2_KMP;
    const uint32_t sb = smem_u32(smem) + ALT2_KMP;
    const int tid = threadIdx.x;
    const int lane = tid & 31;
    const int wid = tid >> 5;
    const int wm = wid & 3;
    const int wn = wid >> 2;
    const int m0 = blockIdx.y * 128;
    const int n0 = blockIdx.x * 128;
    const int nch = 24;   // 16 pe + 8 h1

    float acc[2][8][4] = {};
    float4 a_r[4];
    const int blr = tid >> 2;
    const int blc = tid & 3;

    auto issueB = [&](int ci, int s3) {
        const uint32_t so = sb + F2_BOFF + s3 * F2_BSTAGE;
#pragma unroll
        for (int j = 0; j < 2; j++) {
            int r = blr + j * 64;
            uint32_t d = swz((uint32_t)(r * 64 + blc * 16));
            if (ci < 16) {
                size_t bo = (size_t)(n0 + r) * 512 + (ci << 5) + blc * 8;
                CP16(so + F2_BH + d, B1h + bo);
                CP16(so + F2_BL + d, B1l + bo);
            } else {
                size_t bo = (size_t)(n0 + r) * 256 + ((ci - 16) << 5) + blc * 8;
                CP16(so + F2_BH + d, B2h + bo);
                CP16(so + F2_BL + d, B2l + bo);
            }
        }
        CP_COMMIT();
    };
    auto prefA = [&](int ci) {
#pragma unroll
        for (int j = 0; j < 4; j++) {
            int idx = tid + j * 256;
            int r = idx >> 3, c4 = idx & 7;
            if (ci < 16) {
                size_t ao = (size_t)(m0 + r) * 512 + (ci << 5) + c4 * 4;
                a_r[j] = *reinterpret_cast<const float4*>(pe + ao);
            } else {
                size_t ao = (size_t)(m0 + r) * 256 + ((ci - 16) << 5) + c4 * 4;
                uint2 vh = *reinterpret_cast<const uint2*>(h1h + ao);
                uint2 vl = *reinterpret_cast<const uint2*>(h1l + ao);
                a_r[j] = make_float4(__uint_as_float(vh.x), __uint_as_float(vh.y),
                                     __uint_as_float(vl.x), __uint_as_float(vl.y));
            }
        }
    };

    // kmP tile for the 8 groups in this M-tile (8 x 256 fp32)
    const int g0 = m0 >> 4;
    for (int i = tid; i < 2048; i += 256)
        kmS[i] = kmP[(size_t)(g0 + (i >> 8)) * 256 + (i & 255)];

    issueB(0, 0);
    issueB(1, 1);
    prefA(0);

    int s3 = 0;
    for (int ci = 0; ci < nch; ci++) {
        const int s2 = ci & 1;
        if (ci + 1 < nch) { CP_WAIT1(); } else { CP_WAIT0(); }
        __syncthreads();
        if (ci + 2 < nch) {
            int ns = s3 + 2; if (ns >= 3) ns -= 3;
            issueB(ci + 2, ns);
        }
        const bool cvt = (ci < 16);
#pragma unroll
        for (int j = 0; j < 4; j++) {
            int idx = tid + j * 256;
            int r = idx >> 3, c4 = idx & 7;
            uint32_t hh01, ll01, hh23, ll23;
            if (cvt) {
                cvt_split2(a_r[j].x, a_r[j].y, hh01, ll01);
                cvt_split2(a_r[j].z, a_r[j].w, hh23, ll23);
            } else {
                hh01 = __float_as_uint(a_r[j].x);
                hh23 = __float_as_uint(a_r[j].y);
                ll01 = __float_as_uint(a_r[j].z);
                ll23 = __float_as_uint(a_r[j].w);
            }
            uint32_t o = (uint32_t)(r * SA + c4 * 4) * 2;
            *reinterpret_cast<uint2*>(sdata + s2 * F2_ASTAGE + F2_AH + o) = make_uint2(hh01, hh23);
            *reinterpret_cast<uint2*>(sdata + s2 * F2_ASTAGE + F2_AL + o) = make_uint2(ll01, ll23);
        }
        if (ci + 1 < nch) prefA(ci + 1);
        __syncthreads();
        fused_compute_chunk(sb + s2 * F2_ASTAGE, sb + F2_BOFF + s3 * F2_BSTAGE,
                            lane, wm, wn, acc);
        s3++; if (s3 == 3) s3 = 0;
    }

    // epilogue: per-group kmP bias + elu + split store
#pragma unroll
    for (int i = 0; i < 2; i++) {
        int rl = wm * 32 + i * 16 + (lane >> 2);   // local row 0..127
        int row = m0 + rl;
#pragma unroll
        for (int j = 0; j < 8; j++) {
            int col = n0 + wn * 64 + j * 8 + (lane & 3) * 2;
            float b0a = kmS[(rl >> 4) * 256 + col];
            float b1a = kmS[(rl >> 4) * 256 + col + 1];
            float b0b = kmS[((rl + 8) >> 4) * 256 + col];
            float b1b = kmS[((rl + 8) >> 4) * 256 + col + 1];
            float v0 = elu1(acc[i][j][0] + b0a), v1 = elu1(acc[i][j][1] + b1a);
            float v2 = elu1(acc[i][j][2] + b0b), v3 = elu1(acc[i][j][3] + b1b);
            size_t o0 = (size_t)row * HIDC + col;
            size_t o1 = (size_t)(row + 8) * HIDC + col;
            uint32_t hi, lo;
            cvt_split2(v0, v1, hi, lo);
            *reinterpret_cast<uint32_t*>(Ch + o0) = hi;
            *reinterpret_cast<uint32_t*>(Cl + o0) = lo;
            cvt_split2(v2, v3, hi, lo);
            *reinterpret_cast<uint32_t*>(Ch + o1) = hi;
            *reinterpret_cast<uint32_t*>(Cl + o1) = lo;
        }
    }
}

// ---------------- multi-segment weight split ----------------
#define MAXSEG 9
struct SplitSegs {
    const float* src[MAXSEG];
    int dstoff[MAXSEG];
    int C[MAXSEG];
    int Cp[MAXSEG];
    int rows[MAXSEG];
    int n;
};
__global__ __launch_bounds__(256) void split_multi(
    SplitSegs p, __nv_bfloat16* __restrict__ dh, __nv_bfloat16* __restrict__ dl)
{
    const uint32_t stride = gridDim.x * 256u;
    const uint32_t base = blockIdx.x * 256u + threadIdx.x;
    for (int s = 0; s < p.n; s++) {
        const float* src = p.src[s];
        const int C = p.C[s], Cp = p.Cp[s], off = p.dstoff[s];
        const uint32_t tot = (uint32_t)p.rows[s] * Cp;
        for (uint32_t i = base; i < tot; i += stride) {
            uint32_t r = i / (uint32_t)Cp;
            int c = (int)(i - r * (uint32_t)Cp);
            float v = (c < C) ? src[(size_t)r * C + c] : 0.f;
            __nv_bfloat16 h = __float2bfloat16(v);
            dh[off + i] = h;
            dl[off + i] = __float2bfloat16(v - __bfloat162float(h));
        }
    }
}

// ---------------- compose all: {Wqk, Wv01, P2W1} x W4 -----------------------
// blk<1024: Wqk row -> OW_WC, bias bc = Wqk@b4 + bqk
// 1024<=blk<1536: Wv01 row -> OW_WVC, bias bv2 = Wv01@b4 + bv
// 1536<=blk<1792: P2W1 row (scale -1/16) -> OW_WC3, bias bb = p2b1 - P2W1@b4/16
__global__ __launch_bounds__(256) void compose_all(
    const float* __restrict__ wqk, const float* __restrict__ wv01,
    const float* __restrict__ p2w1, const float* __restrict__ w4,
    const float* __restrict__ b4, const float* __restrict__ battn,
    const float* __restrict__ p2b1,
    __nv_bfloat16* __restrict__ chp, __nv_bfloat16* __restrict__ clp,
    float* __restrict__ bc, float* __restrict__ bv2, float* __restrict__ bb)
{
    __shared__ float wrow[512];
    const int blk = blockIdx.x;
    const int tid = threadIdx.x;
    const float* src;
    const float* bin;
    float* bout;
    float scale;
    int outoff, n;
    if (blk < 1024)      { src = wqk;  n = blk;        scale = 1.f;       outoff = OW_WC;  bin = battn;        bout = bc;  }
    else if (blk < 1536) { src = wv01; n = blk - 1024; scale = 1.f;       outoff = OW_WVC; bin = battn + 1024; bout = bv2; }
    else                 { src = p2w1; n = blk - 1536; scale = -0.0625f;  outoff = OW_WC3; bin = p2b1;         bout = bb;  }
    wrow[tid] = src[(size_t)n * 512 + tid];
    wrow[tid + 256] = src[(size_t)n * 512 + tid + 256];
    __syncthreads();
    float acc = 0.f;
#pragma unroll 8
    for (int j = 0; j < 512; j++)
        acc += wrow[j] * w4[(size_t)j * 256 + tid];
    acc *= scale;
    __nv_bfloat16 h = __float2bfloat16(acc);
    chp[outoff + (size_t)n * 256 + tid] = h;
    clp[outoff + (size_t)n * 256 + tid] = __float2bfloat16(acc - __bfloat162float(h));
    if (tid < 32) {
        float s = 0.f;
        for (int j = tid; j < 512; j += 32) s += wrow[j] * b4[j];
#pragma unroll
        for (int o = 16; o > 0; o >>= 1) s += __shfl_xor_sync(0xffffffffu, s, o);
        if (tid == 0) bout[n] = s * scale + bin[n];
    }
}

// ---------------- zero output ----------------
__global__ __launch_bounds__(256) void zero_out(float* __restrict__ p, int n) {
    int i = blockIdx.x * 256 + threadIdx.x;
    if (i < n) p[i] = 0.f;
}

// ---------------- attention v4: mma scores, h1-based hw ---------------------
#define AROW 1032
__global__ __launch_bounds__(256) void attn4_kernel(
    const __nv_bfloat16* __restrict__ qk,
    const __nv_bfloat16* __restrict__ h1h, const __nv_bfloat16* __restrict__ h1l,
    __nv_bfloat16* __restrict__ hwh, __nv_bfloat16* __restrict__ hwl)
{
    const int g = blockIdx.x;
    const int tid = threadIdx.x;
    const int lane = tid & 31;
    const int wid = tid >> 5;
    __shared__ __align__(16) __nv_bfloat16 qks[16 * AROW];
    __shared__ float sc[2][16][17];
    __shared__ float cw[2][16];
    const uint32_t sbq = smem_u32(qks);

    {
        const uint4* src = reinterpret_cast<const uint4*>(qk + (size_t)g * GSZ * 1024);
#pragma unroll
        for (int t = 0; t < 8; t++) {
            int idx = tid + t * 256;
            int row = idx >> 7;
            int c8 = idx & 127;
            *reinterpret_cast<uint4*>(qks + row * AROW + c8 * 8) = src[idx];
        }
    }
    __syncthreads();

    if (wid < 2) {
        const int h = wid;
        float accS[2][4] = {};
        const uint32_t qb = (uint32_t)(h * 256) * 2;
        const uint32_t kb = (uint32_t)(512 + h * 256) * 2;
#pragma unroll
        for (int ks = 0; ks < 16; ks++) {
            uint32_t a[4];
            {
                int ar = lane & 15;
                uint32_t addr = sbq + (uint32_t)(ar * AROW) * 2 + qb + ks * 32 + (lane >> 4) * 16;
                ldsm4(a[0], a[1], a[2], a[3], addr);
            }
            uint32_t b0[2], b1[2];
            {
                int br = (lane & 7) + ((lane >> 4) & 1) * 8;
                uint32_t addr = sbq + (uint32_t)(br * AROW) * 2 + kb + ks * 32 + ((lane >> 3) & 1) * 16;
                uint32_t r0, r1, r2, r3;
                ldsm4(r0, r1, r2, r3, addr);
                b0[0] = r0; b0[1] = r1;
                b1[0] = r2; b1[1] = r3;
            }
            mma16816(accS[0], a, b0);
            mma16816(accS[1], a, b1);
        }
        {
            int row = lane >> 2;
            int col = (lane & 3) * 2;
#pragma unroll
            for (int j = 0; j < 2; j++) {
                sc[h][row][j * 8 + col]     = accS[j][0] * 0.0625f;
                sc[h][row][j * 8 + col + 1] = accS[j][1] * 0.0625f;
                sc[h][row + 8][j * 8 + col]     = accS[j][2] * 0.0625f;
                sc[h][row + 8][j * 8 + col + 1] = accS[j][3] * 0.0625f;
            }
        }
    }
    __syncthreads();

    if (tid < 32) {
        int h = tid >> 4, tq = tid & 15;
        float mx = -1e30f;
#pragma unroll
        for (int tk = 0; tk < 16; tk++) mx = fmaxf(mx, sc[h][tq][tk]);
        float s = 0.f;
#pragma unroll
        for (int tk = 0; tk < 16; tk++) {
            float e = expf(sc[h][tq][tk] - mx);
            sc[h][tq][tk] = e;
            s += e;
        }
        float inv = 1.f / s;
#pragma unroll
        for (int tk = 0; tk < 16; tk++) sc[h][tq][tk] *= inv;
    }
    __syncthreads();
    if (tid < 32) {
        int h = tid >> 4, tk = tid & 15;
        float s = 0.f;
#pragma unroll
        for (int tq = 0; tq < 16; tq++) s += sc[h][tq][tk];
        cw[h][tk] = s * 0.0625f;
    }
    __syncthreads();

    // hw: 128 threads x 2 cols; reads h1 (256 cols) split
    if (tid < 128) {
        int d2 = tid * 2;
        const __nv_bfloat16* xbh = h1h + (size_t)g * GSZ * 256 + d2;
        const __nv_bfloat16* xbl = h1l + (size_t)g * GSZ * 256 + d2;
        float a0[2] = {}, a1[2] = {};
#pragma unroll
        for (int tk = 0; tk < 16; tk++) {
            uint32_t vh = *reinterpret_cast<const uint32_t*>(xbh + tk * 256);
            uint32_t vl = *reinterpret_cast<const uint32_t*>(xbl + tk * 256);
            float2 hh = bf2f2(vh), ll = bf2f2(vl);
            float x0 = hh.x + ll.x, x1 = hh.y + ll.y;
            float w0 = cw[0][tk], w1 = cw[1][tk];
            a0[0] += w0 * x0; a0[1] += w0 * x1;
            a1[0] += w1 * x0; a1[1] += w1 * x1;
        }
        uint32_t hi, lo;
        size_t o0 = (size_t)g * HIDC + d2;
        cvt_split2(a0[0], a0[1], hi, lo);
        *reinterpret_cast<uint32_t*>(hwh + o0) = hi;
        *reinterpret_cast<uint32_t*>(hwl + o0) = lo;
        size_t o1 = (size_t)NGR * HIDC + o0;
        cvt_split2(a1[0], a1[1], hi, lo);
        *reinterpret_cast<uint32_t*>(hwh + o1) = hi;
        *reinterpret_cast<uint32_t*>(hwl + o1) = lo;
    }
}

// ================================================================ host launch
extern "C" void kernel_launch(void* const* d_in, const int* in_sizes, int n_in,
                              void* d_out, int out_size)
{
    const float* pe       = (const float*)d_in[0];
    const float* peA      = (const float*)d_in[1];
    const float* attn_in_w  = (const float*)d_in[2];
    const float* attn_in_b  = (const float*)d_in[3];
    const float* attn_out_w = (const float*)d_in[4];
    const float* attn_out_b = (const float*)d_in[5];
    const float* p1w1 = (const float*)d_in[6];  const float* p1b1 = (const float*)d_in[7];
    const float* p1w2 = (const float*)d_in[8];  const float* p1b2 = (const float*)d_in[9];
    const float* p1w3 = (const float*)d_in[10]; const float* p1b3 = (const float*)d_in[11];
    const float* p1w4 = (const float*)d_in[12]; const float* p1b4 = (const float*)d_in[13];
    const float* gw1 = (const float*)d_in[14];  const float* gb1 = (const float*)d_in[15];
    const float* gw2 = (const float*)d_in[16];  const float* gb2 = (const float*)d_in[17];
    const float* gw3 = (const float*)d_in[18];  const float* gb3 = (const float*)d_in[19];
    const float* gw4 = (const float*)d_in[20];  const float* gb4 = (const float*)d_in[21];
    const float* p2w1 = (const float*)d_in[22]; const float* p2b1 = (const float*)d_in[23];
    const float* p2w2 = (const float*)d_in[24]; const float* p2b2 = (const float*)d_in[25];
    const float* p2w3 = (const float*)d_in[26]; const float* p2b3 = (const float*)d_in[27];
    float* out = (float*)d_out;

    #define SYM(T, v, s) T* v; cudaGetSymbolAddress((void**)&v, s)
    SYM(__nv_bfloat16, h1h, g_h1h);   SYM(__nv_bfloat16, h1l, g_h1l);
    SYM(__nv_bfloat16, h2h, g_h2h);   SYM(__nv_bfloat16, h2l, g_h2l);
    SYM(__nv_bfloat16, qk, g_qk);
    SYM(__nv_bfloat16, xwh, g_xwh);   SYM(__nv_bfloat16, xwl, g_xwl);
    SYM(__nv_bfloat16, omh, g_omh);   SYM(__nv_bfloat16, oml, g_oml);
    SYM(float, km, g_km);
    SYM(__nv_bfloat16, kmh, g_kmh);   SYM(__nv_bfloat16, kml, g_kml);
    SYM(float, kmpf, g_kmp);
    SYM(__nv_bfloat16, hgah, g_hgah); SYM(__nv_bfloat16, hgal, g_hgal);
    SYM(__nv_bfloat16, hgbh, g_hgbh); SYM(__nv_bfloat16, hgbl, g_hgbl);
    SYM(__nv_bfloat16, wph, g_wph);   SYM(__nv_bfloat16, wpl, g_wpl);
    SYM(float, bc, g_bc);
    SYM(float, bv2, g_bv2);
    SYM(float, bb, g_bb);

    cudaFuncSetAttribute(gemm_bf16<1,false,true>, cudaFuncAttributeMaxDynamicSharedMemorySize, SMEM_TOT);
    cudaFuncSetAttribute(gemm_bf16<2,false,true>, cudaFuncAttributeMaxDynamicSharedMemorySize, SMEM_TOT);
    cudaFuncSetAttribute(gemm_bf16<0,false,true>, cudaFuncAttributeMaxDynamicSharedMemorySize, SMEM_TOT);
    cudaFuncSetAttribute(gemm_bf16<0,true,true>,  cudaFuncAttributeMaxDynamicSharedMemorySize, SMEM_TOT);
    cudaFuncSetAttribute(gemm_bf16<0,true,false>, cudaFuncAttributeMaxDynamicSharedMemorySize, SMEM_TOT);
    cudaFuncSetAttribute(gemm_dot<1>, cudaFuncAttributeMaxDynamicSharedMemorySize, SMEM_TOT);
    cudaFuncSetAttribute(gemm_dot<2>, cudaFuncAttributeMaxDynamicSharedMemorySize, SMEM_TOT);
    cudaFuncSetAttribute(gemm_qk1p, cudaFuncAttributeMaxDynamicSharedMemorySize, QSMEM);
    cudaFuncSetAttribute(gemm_phi1a, cudaFuncAttributeMaxDynamicSharedMemorySize, P1A_SMEM);
    cudaFuncSetAttribute(gemm_alt2, cudaFuncAttributeMaxDynamicSharedMemorySize, ALT2_SMEM);

    const int TB = 256;
    #define GRID(Mv, Nv) dim3((Nv) / 128, (Mv) / 128)

    // #1: zero the output
    zero_out<<<(out_size + 255) / 256, TB>>>(out, out_size);

    // #2: phi1 weight splits
    {
        SplitSegs s = {};
        int n = 0;
        auto add = [&](const float* src, int off, int R, int C, int Cp) {
            s.src[n] = src; s.dstoff[n] = off; s.rows[n] = R; s.C[n] = C; s.Cp[n] = Cp; n++;
        };
        add(p1w1, OW_P1W1, 256, 514, KPAD1);
        add(p1w2, OW_P1W2, 256, 256, 256);
        add(p1w3, OW_P1W3, 256, 256, 256);
        s.n = n;
        split_multi<<<512, TB>>>(s, wph, wpl);
    }
    // #3: remaining weight splits
    {
        SplitSegs s = {};
        int n = 0;
        auto add = [&](const float* src, int off, int R, int C, int Cp) {
            s.src[n] = src; s.dstoff[n] = off; s.rows[n] = R; s.C[n] = C; s.Cp[n] = Cp; n++;
        };
        add(attn_out_w, OW_WOUT, 512, 512, 512);
        add(gw1, OW_GW1, 256, 512, 512);
        add(gw2, OW_GW2, 256, 256, 256);
        add(gw3, OW_GW3, 256, 256, 256);
        add(p2w1, OW_P2W1, 256, 512, 512);
        add(p2w2, OW_P2W2, 256, 256, 256);
        s.n = n;
        split_multi<<<512, TB>>>(s, wph, wpl);
    }

    // #4: phi1 L1 (profiled)
    gemm_phi1a<<<GRID(NTOK, 256), TB, P1A_SMEM>>>(
        peA, wph + OW_P1W1, wpl + OW_P1W1, p1b1, h1h, h1l);

    // #5: compose Wc, WVc, Wc3m + biases
    compose_all<<<1792, TB>>>(attn_in_w, attn_in_w + (size_t)1024 * 512, p2w1,
                              p1w4, p1b4, attn_in_b, p2b1,
                              wph, wpl, bc, bv2, bb);

    // phi1 chain (cont.)
    gemm_bf16<2,false,true><<<GRID(NTOK, HIDC), TB, SMEM_TOT>>>(
        h1h, h1l, wph + OW_P1W2, wpl + OW_P1W2, p1b2, nullptr, h2h, h2l, HIDC, HIDC);
    gemm_bf16<1,false,true><<<GRID(NTOK, HIDC), TB, SMEM_TOT>>>(
        h2h, h2l, wph + OW_P1W3, wpl + OW_P1W3, p1b3, nullptr, h1h, h1l, HIDC, HIDC);

    // qk = h1 @ Wc^T + bc (single-pass bf16, K=256)
    gemm_qk1p<<<GRID(NTOK, 1024), TB, QSMEM>>>(
        h1h, wph + OW_WC, bc, qk, HIDC, 1024);
    // attention -> hw (per head, 256-dim)
    attn4_kernel<<<NGR, TB>>>(qk, h1h, h1l, xwh, xwl);
    // o_mean per head via composed WVc (K=256)
    gemm_bf16<0,false,true><<<GRID(NGR, 256), TB, SMEM_TOT>>>(
        xwh, xwl, wph + OW_WVC, wpl + OW_WVC, bv2,
        nullptr, omh, oml, HIDC, EFULL);
    gemm_bf16<0,false,true><<<GRID(NGR, 256), TB, SMEM_TOT>>>(
        xwh + (size_t)NGR * HIDC, xwl + (size_t)NGR * HIDC,
        wph + OW_WVC + 65536, wpl + OW_WVC + 65536, bv2 + 256,
        nullptr, omh + 256, oml + 256, HIDC, EFULL);
    // km = omean @ Wo^T + bo
    gemm_bf16<0,true,true><<<GRID(NGR, EFULL), TB, SMEM_TOT>>>(
        omh, oml, wph + OW_WOUT, wpl + OW_WOUT, attn_out_b, km, kmh, kml, EFULL, EFULL);
    // kmP = km @ P2W1^T + bb
    gemm_bf16<0,true,false><<<GRID(NGR, 256), TB, SMEM_TOT>>>(
        kmh, kml, wph + OW_P2W1, wpl + OW_P2W1, bb, kmpf, nullptr, nullptr, EFULL, HIDC);

    // g head -> q_jt at out[0 .. 4096)
    gemm_bf16<1,false,true><<<GRID(NGR, HIDC), TB, SMEM_TOT>>>(
        kmh, kml, wph + OW_GW1, wpl + OW_GW1, gb1, nullptr, hgah, hgal, EFULL, HIDC);
    gemm_bf16<1,false,true><<<GRID(NGR, HIDC), TB, SMEM_TOT>>>(
        hgah, hgal, wph + OW_GW2, wpl + OW_GW2, gb2, nullptr, hgbh, hgbl, HIDC, HIDC);
    gemm_dot<1><<<GRID(NGR, HIDC), TB, SMEM_TOT>>>(
        hgbh, hgbl, wph + OW_GW3, wpl + OW_GW3, gb3, gw4, gb4, out, HIDC);

    // alt path: hp = elu(pe@P2W1^T + h1@Wc3m^T + kmP[g]) -> p2w2 + dot
    gemm_alt2<<<GRID(NTOK, 256), TB, ALT2_SMEM>>>(
        pe, h1h, h1l, kmpf,
        wph + OW_P2W1, wpl + OW_P2W1, wph + OW_WC3, wpl + OW_WC3,
        h2h, h2l);
    gemm_dot<2><<<GRID(NTOK, HIDC), TB, SMEM_TOT>>>(
        h2h, h2l, wph + OW_P2W2, wpl + OW_P2W2, p2b2, p2w3, p2b3, out + NGR, HIDC);
}

// round 11
// speedup vs baseline: 2.2389x; 1.2241x over previous
#include <cuda_runtime.h>
#include <cuda_fp16.h>
#include <cstdint>
#include <math.h>

// Problem constants
#define NTOK  65536
#define EFULL 512
#define HIDC  256
#define NGR   4096
#define GSZ   16
#define KPAD1 544          // 514 padded to %32

// ---------------- scratch (__device__ globals) ----------------
__device__ __half g_h1h[(size_t)NTOK * HIDC];
__device__ __half g_h1l[(size_t)NTOK * HIDC];
__device__ __half g_h2h[(size_t)NTOK * HIDC];
__device__ __half g_h2l[(size_t)NTOK * HIDC];
__device__ __half g_qk[(size_t)NTOK * 1024];
__device__ __half g_xwh[(size_t)2 * NGR * HIDC];
__device__ __half g_xwl[(size_t)2 * NGR * HIDC];
__device__ __half g_omh[(size_t)NGR * EFULL];
__device__ __half g_oml[(size_t)NGR * EFULL];
__device__ float  g_km[(size_t)NGR * EFULL];
__device__ __half g_kmh[(size_t)NGR * EFULL];
__device__ __half g_kml[(size_t)NGR * EFULL];
__device__ float  g_kmp[(size_t)NGR * HIDC];
__device__ __half g_hgah[(size_t)NGR * HIDC];
__device__ __half g_hgal[(size_t)NGR * HIDC];
__device__ __half g_hgbh[(size_t)NGR * HIDC];
__device__ __half g_hgbl[(size_t)NGR * HIDC];
__device__ float  g_bc[1024];
__device__ float  g_bv2[512];
__device__ float  g_bb[256];

// weight pool (single fp16 — B operands need no lo plane). offsets in elements:
#define OW_P1W1 0                 // 256x544
#define OW_P1W2 139264            // 256x256
#define OW_P1W3 204800            // 256x256
#define OW_WOUT 270336            // 512x512
#define OW_GW1  532480            // 256x512
#define OW_GW2  663552            // 256x256
#define OW_GW3  729088            // 256x256
#define OW_P2W1 794624            // 256x512
#define OW_P2W2 925696            // 256x256
#define OW_WC   991232            // Wqk@W4: 1024x256
#define OW_WVC  1253376           // Wv01@W4: 512x256
#define OW_WC3  1384448           // -(P2W1@W4)/16: 256x256
#define OW_TOT  1449984
__device__ __half g_wp[OW_TOT];

__device__ __forceinline__ float elu1(float x) {
    return x > 0.f ? x : (expf(x) - 1.f);
}
__device__ __forceinline__ uint32_t smem_u32(const void* p) {
    uint32_t a;
    asm("{ .reg .u64 t; cvta.to.shared.u64 t, %1; cvt.u32.u64 %0, t; }" : "=r"(a) : "l"(p));
    return a;
}
__device__ __forceinline__ void ldsm4(uint32_t& r0, uint32_t& r1, uint32_t& r2, uint32_t& r3,
                                      uint32_t addr) {
    asm volatile("ldmatrix.sync.aligned.m8n8.x4.shared.b16 {%0,%1,%2,%3}, [%4];"
                 : "=r"(r0), "=r"(r1), "=r"(r2), "=r"(r3) : "r"(addr));
}
__device__ __forceinline__ void mma16816(float* c, const uint32_t* a, const uint32_t* b) {
    asm volatile("mma.sync.aligned.m16n8k16.row.col.f32.f16.f16.f32 "
                 "{%0,%1,%2,%3}, {%4,%5,%6,%7}, {%8,%9}, {%0,%1,%2,%3};"
                 : "+f"(c[0]), "+f"(c[1]), "+f"(c[2]), "+f"(c[3])
                 : "r"(a[0]), "r"(a[1]), "r"(a[2]), "r"(a[3]), "r"(b[0]), "r"(b[1]));
}
__device__ __forceinline__ void cvt_split2(float a, float b, uint32_t& hi, uint32_t& lo) {
    __half2 h = __floats2half2_rn(a, b);
    float2 hf = __half22float2(h);
    __half2 l = __floats2half2_rn(a - hf.x, b - hf.y);
    hi = *reinterpret_cast<uint32_t*>(&h);
    lo = *reinterpret_cast<uint32_t*>(&l);
}
__device__ __forceinline__ float2 h2f2(uint32_t u) {
    return __half22float2(*reinterpret_cast<__half2*>(&u));
}
__device__ __forceinline__ uint32_t swz(uint32_t x) { return x ^ ((x >> 3) & 0x70); }

#define CP16(dst, src) \
    asm volatile("cp.async.cg.shared.global [%0], [%1], 16;" :: "r"(dst), "l"(src))
#define CP_COMMIT() asm volatile("cp.async.commit_group;" ::: "memory")
#define CP_WAIT1()  asm volatile("cp.async.wait_group 1;" ::: "memory")
#define CP_WAIT0()  asm volatile("cp.async.wait_group 0;" ::: "memory")

// ======== 2-pass fp16 NT GEMM: A split hi/lo (exact), B single fp16 ==========
#define STAGE 24576
#define SMEM_TOT (3 * STAGE)

template <int EPI, bool WF32, bool WSPLIT>
__global__ __launch_bounds__(256, 2) void gemm_2p(
    const __half* __restrict__ Ah, const __half* __restrict__ Al,
    const __half* __restrict__ B,
    const float* __restrict__ bias, float* __restrict__ C,
    __half* __restrict__ Ch, __half* __restrict__ Cl,
    int K, int ldC)
{
    extern __shared__ __align__(1024) char smem[];
    const uint32_t sb = smem_u32(smem);
    const int tid = threadIdx.x;
    const int lane = tid & 31;
    const int wid = tid >> 5;
    const int wm = wid & 3;
    const int wn = wid >> 2;
    const int m0 = blockIdx.y * 128;
    const int n0 = blockIdx.x * 128;

    const int nch = K >> 5;
    float acc[2][8][4] = {};
    const int lr = (tid >> 2);
    const int lc = tid & 3;

    auto issue = [&](int ci, int stg) {
        const int k0 = ci << 5;
        const uint32_t so = sb + stg * STAGE;
#pragma unroll
        for (int j = 0; j < 2; j++) {
            int r = lr + j * 64;
            uint32_t d = swz((uint32_t)(r * 64 + lc * 16));
            size_t ao = (size_t)(m0 + r) * K + k0 + lc * 8;
            size_t bo = (size_t)(n0 + r) * K + k0 + lc * 8;
            CP16(so + d,         Ah + ao);
            CP16(so + 8192 + d,  Al + ao);
            CP16(so + 16384 + d, B + bo);
        }
        CP_COMMIT();
    };

    issue(0, 0);
    if (nch > 1) issue(1, 1);

    int stg = 0;
    for (int ci = 0; ci < nch; ci++) {
        if (ci + 1 < nch) { CP_WAIT1(); } else { CP_WAIT0(); }
        __syncthreads();
        if (ci + 2 < nch) {
            int ns = stg + 2; if (ns >= 3) ns -= 3;
            issue(ci + 2, ns);
        }
        const uint32_t so = sb + stg * STAGE;
#pragma unroll
        for (int kk = 0; kk < 2; kk++) {
            uint32_t ah[2][4], al_[2][4];
            {
                int ar = lane & 15;
                int akb = kk * 32 + ((lane >> 4) * 16);
#pragma unroll
                for (int i = 0; i < 2; i++) {
                    uint32_t off = swz((uint32_t)((wm * 32 + i * 16 + ar) * 64 + akb));
                    ldsm4(ah[i][0], ah[i][1], ah[i][2], ah[i][3], so + off);
                    ldsm4(al_[i][0], al_[i][1], al_[i][2], al_[i][3], so + 8192 + off);
                }
            }
            uint32_t bh[8][2];
            {
                int br = (lane & 7) + ((lane >> 4) & 1) * 8;
                int bkb = ((lane >> 3) & 1) * 16 + kk * 32;
#pragma unroll
                for (int jf = 0; jf < 4; jf++) {
                    uint32_t off = swz((uint32_t)((wn * 64 + jf * 16 + br) * 64 + bkb));
                    uint32_t r0, r1, r2, r3;
                    ldsm4(r0, r1, r2, r3, so + 16384 + off);
                    bh[2 * jf][0] = r0; bh[2 * jf][1] = r1;
                    bh[2 * jf + 1][0] = r2; bh[2 * jf + 1][1] = r3;
                }
            }
#pragma unroll
            for (int i = 0; i < 2; i++)
#pragma unroll
                for (int j = 0; j < 8; j++)
                    mma16816(acc[i][j], ah[i], bh[j]);
#pragma unroll
            for (int i = 0; i < 2; i++)
#pragma unroll
                for (int j = 0; j < 8; j++)
                    mma16816(acc[i][j], al_[i], bh[j]);
        }
        stg++; if (stg == 3) stg = 0;
    }

#pragma unroll
    for (int i = 0; i < 2; i++) {
        int row = m0 + wm * 32 + i * 16 + (lane >> 2);
#pragma unroll
        for (int j = 0; j < 8; j++) {
            int col = n0 + wn * 64 + j * 8 + (lane & 3) * 2;
            float b0 = bias[col], b1 = bias[col + 1];
            float v0 = acc[i][j][0] + b0, v1 = acc[i][j][1] + b1;
            float v2 = acc[i][j][2] + b0, v3 = acc[i][j][3] + b1;
            if (EPI >= 1) { v0 = elu1(v0); v1 = elu1(v1); v2 = elu1(v2); v3 = elu1(v3); }
            if (EPI == 2) { v0 = elu1(v0); v1 = elu1(v1); v2 = elu1(v2); v3 = elu1(v3); }
            size_t o0 = (size_t)row * ldC + col;
            size_t o1 = (size_t)(row + 8) * ldC + col;
            if (WF32) {
                *reinterpret_cast<float2*>(C + o0) = make_float2(v0, v1);
                *reinterpret_cast<float2*>(C + o1) = make_float2(v2, v3);
            }
            if (WSPLIT) {
                uint32_t hi, lo;
                cvt_split2(v0, v1, hi, lo);
                *reinterpret_cast<uint32_t*>(Ch + o0) = hi;
                *reinterpret_cast<uint32_t*>(Cl + o0) = lo;
                cvt_split2(v2, v3, hi, lo);
                *reinterpret_cast<uint32_t*>(Ch + o1) = hi;
                *reinterpret_cast<uint32_t*>(Cl + o1) = lo;
            }
        }
    }
}

// ======== 2-pass GEMM + fused final-dot epilogue =============================
template <int NOUT>
__global__ __launch_bounds__(256, 2) void gemm_dot(
    const __half* __restrict__ Ah, const __half* __restrict__ Al,
    const __half* __restrict__ B,
    const float* __restrict__ bias, const float* __restrict__ dw,
    const float* __restrict__ dbias, float* __restrict__ dout, int K)
{
    extern __shared__ __align__(1024) char smem[];
    const uint32_t sb = smem_u32(smem);
    const int tid = threadIdx.x;
    const int lane = tid & 31;
    const int wid = tid >> 5;
    const int wm = wid & 3;
    const int wn = wid >> 2;
    const int m0 = blockIdx.y * 128;
    const int n0 = blockIdx.x * 128;

    const int nch = K >> 5;
    float acc[2][8][4] = {};
    const int lr = (tid >> 2);
    const int lc = tid & 3;

    auto issue = [&](int ci, int stg) {
        const int k0 = ci << 5;
        const uint32_t so = sb + stg * STAGE;
#pragma unroll
        for (int j = 0; j < 2; j++) {
            int r = lr + j * 64;
            uint32_t d = swz((uint32_t)(r * 64 + lc * 16));
            size_t ao = (size_t)(m0 + r) * K + k0 + lc * 8;
            size_t bo = (size_t)(n0 + r) * K + k0 + lc * 8;
            CP16(so + d,         Ah + ao);
            CP16(so + 8192 + d,  Al + ao);
            CP16(so + 16384 + d, B + bo);
        }
        CP_COMMIT();
    };

    issue(0, 0);
    if (nch > 1) issue(1, 1);

    int stg = 0;
    for (int ci = 0; ci < nch; ci++) {
        if (ci + 1 < nch) { CP_WAIT1(); } else { CP_WAIT0(); }
        __syncthreads();
        if (ci + 2 < nch) {
            int ns = stg + 2; if (ns >= 3) ns -= 3;
            issue(ci + 2, ns);
        }
        const uint32_t so = sb + stg * STAGE;
#pragma unroll
        for (int kk = 0; kk < 2; kk++) {
            uint32_t ah[2][4], al_[2][4];
            {
                int ar = lane & 15;
                int akb = kk * 32 + ((lane >> 4) * 16);
#pragma unroll
                for (int i = 0; i < 2; i++) {
                    uint32_t off = swz((uint32_t)((wm * 32 + i * 16 + ar) * 64 + akb));
                    ldsm4(ah[i][0], ah[i][1], ah[i][2], ah[i][3], so + off);
                    ldsm4(al_[i][0], al_[i][1], al_[i][2], al_[i][3], so + 8192 + off);
                }
            }
            uint32_t bh[8][2];
            {
                int br = (lane & 7) + ((lane >> 4) & 1) * 8;
                int bkb = ((lane >> 3) & 1) * 16 + kk * 32;
#pragma unroll
                for (int jf = 0; jf < 4; jf++) {
                    uint32_t off = swz((uint32_t)((wn * 64 + jf * 16 + br) * 64 + bkb));
                    uint32_t r0, r1, r2, r3;
                    ldsm4(r0, r1, r2, r3, so + 16384 + off);
                    bh[2 * jf][0] = r0; bh[2 * jf][1] = r1;
                    bh[2 * jf + 1][0] = r2; bh[2 * jf + 1][1] = r3;
                }
            }
#pragma unroll
            for (int i = 0; i < 2; i++)
#pragma unroll
                for (int j = 0; j < 8; j++)
                    mma16816(acc[i][j], ah[i], bh[j]);
#pragma unroll
            for (int i = 0; i < 2; i++)
#pragma unroll
                for (int j = 0; j < 8; j++)
                    mma16816(acc[i][j], al_[i], bh[j]);
        }
        stg++; if (stg == 3) stg = 0;
    }

    float dsum[2][2][NOUT];
#pragma unroll
    for (int i = 0; i < 2; i++)
#pragma unroll
        for (int hf = 0; hf < 2; hf++)
#pragma unroll
            for (int o = 0; o < NOUT; o++) dsum[i][hf][o] = 0.f;

#pragma unroll
    for (int i = 0; i < 2; i++) {
#pragma unroll
        for (int j = 0; j < 8; j++) {
            int col = n0 + wn * 64 + j * 8 + (lane & 3) * 2;
            float b0 = bias[col], b1 = bias[col + 1];
            float v0 = elu1(acc[i][j][0] + b0), v1 = elu1(acc[i][j][1] + b1);
            float v2 = elu1(acc[i][j][2] + b0), v3 = elu1(acc[i][j][3] + b1);
#pragma unroll
            for (int o = 0; o < NOUT; o++) {
                float w0 = dw[o * 256 + col], w1 = dw[o * 256 + col + 1];
                dsum[i][0][o] += v0 * w0 + v1 * w1;
                dsum[i][1][o] += v2 * w0 + v3 * w1;
            }
        }
    }
#pragma unroll
    for (int i = 0; i < 2; i++)
#pragma unroll
        for (int hf = 0; hf < 2; hf++)
#pragma unroll
            for (int o = 0; o < NOUT; o++) {
                float s = dsum[i][hf][o];
                s += __shfl_xor_sync(0xffffffffu, s, 1);
                s += __shfl_xor_sync(0xffffffffu, s, 2);
                dsum[i][hf][o] = s;
            }
    if ((lane & 3) == 0) {
        const bool addb = (blockIdx.x == 0 && wn == 0);
#pragma unroll
        for (int i = 0; i < 2; i++)
#pragma unroll
            for (int hf = 0; hf < 2; hf++) {
                int row = m0 + wm * 32 + i * 16 + (lane >> 2) + hf * 8;
#pragma unroll
                for (int o = 0; o < NOUT; o++) {
                    float v = dsum[i][hf][o];
                    if (addb) v += dbias[o];
                    atomicAdd(&dout[(size_t)row * NOUT + o], v);
                }
            }
    }
}

// ======== single-pass fp16 GEMM for qk ======================================
#define QSTAGE 16384
#define QSMEM (3 * QSTAGE)
__global__ __launch_bounds__(256, 2) void gemm_qk1p(
    const __half* __restrict__ Ah, const __half* __restrict__ B,
    const float* __restrict__ bias, __half* __restrict__ Cb,
    int K, int ldC)
{
    extern __shared__ __align__(1024) char smem[];
    const uint32_t sb = smem_u32(smem);
    const int tid = threadIdx.x;
    const int lane = tid & 31;
    const int wid = tid >> 5;
    const int wm = wid & 3;
    const int wn = wid >> 2;
    const int m0 = blockIdx.y * 128;
    const int n0 = blockIdx.x * 128;

    const int nch = K >> 5;
    float acc[2][8][4] = {};
    const int lr = (tid >> 2);
    const int lc = tid & 3;

    auto issue = [&](int ci, int stg) {
        const int k0 = ci << 5;
        const uint32_t so = sb + stg * QSTAGE;
#pragma unroll
        for (int j = 0; j < 2; j++) {
            int r = lr + j * 64;
            uint32_t d = swz((uint32_t)(r * 64 + lc * 16));
            CP16(so + d,        Ah + (size_t)(m0 + r) * K + k0 + lc * 8);
            CP16(so + 8192 + d, B + (size_t)(n0 + r) * K + k0 + lc * 8);
        }
        CP_COMMIT();
    };

    issue(0, 0);
    if (nch > 1) issue(1, 1);

    int stg = 0;
    for (int ci = 0; ci < nch; ci++) {
        if (ci + 1 < nch) { CP_WAIT1(); } else { CP_WAIT0(); }
        __syncthreads();
        if (ci + 2 < nch) {
            int ns = stg + 2; if (ns >= 3) ns -= 3;
            issue(ci + 2, ns);
        }
        const uint32_t so = sb + stg * QSTAGE;
#pragma unroll
        for (int kk = 0; kk < 2; kk++) {
            uint32_t ah[2][4];
            {
                int ar = lane & 15;
                int akb = kk * 32 + ((lane >> 4) * 16);
#pragma unroll
                for (int i = 0; i < 2; i++) {
                    uint32_t off = swz((uint32_t)((wm * 32 + i * 16 + ar) * 64 + akb));
                    ldsm4(ah[i][0], ah[i][1], ah[i][2], ah[i][3], so + off);
                }
            }
            uint32_t bh[8][2];
            {
                int br = (lane & 7) + ((lane >> 4) & 1) * 8;
                int bkb = ((lane >> 3) & 1) * 16 + kk * 32;
#pragma unroll
                for (int jf = 0; jf < 4; jf++) {
                    uint32_t off = swz((uint32_t)((wn * 64 + jf * 16 + br) * 64 + bkb));
                    uint32_t r0, r1, r2, r3;
                    ldsm4(r0, r1, r2, r3, so + 8192 + off);
                    bh[2 * jf][0] = r0; bh[2 * jf][1] = r1;
                    bh[2 * jf + 1][0] = r2; bh[2 * jf + 1][1] = r3;
                }
            }
#pragma unroll
            for (int i = 0; i < 2; i++)
#pragma unroll
                for (int j = 0; j < 8; j++)
                    mma16816(acc[i][j], ah[i], bh[j]);
        }
        stg++; if (stg == 3) stg = 0;
    }

#pragma unroll
    for (int i = 0; i < 2; i++) {
        int row = m0 + wm * 32 + i * 16 + (lane >> 2);
#pragma unroll
        for (int j = 0; j < 8; j++) {
            int col = n0 + wn * 64 + j * 8 + (lane & 3) * 2;
            float b0 = bias[col], b1 = bias[col + 1];
            __half2 p0 = __floats2half2_rn(acc[i][j][0] + b0, acc[i][j][1] + b1);
            __half2 p1 = __floats2half2_rn(acc[i][j][2] + b0, acc[i][j][3] + b1);
            *reinterpret_cast<__half2*>(Cb + (size_t)row * ldC + col) = p0;
            *reinterpret_cast<__half2*>(Cb + (size_t)(row + 8) * ldC + col) = p1;
        }
    }
}

// ============ fused A-build GEMM machinery (SA=40 A layout, B single) ========
#define SA 40
#define F2_AH 0
#define F2_AL 10240
#define F2_ASTAGE 20480
#define F2_BSTAGE 8192
#define F2_BOFF (2 * F2_ASTAGE)          // 40960
#define F2_TOT (F2_BOFF + 3 * F2_BSTAGE) // 65536

__device__ __forceinline__ void fused_compute_chunk(
    uint32_t aBase, uint32_t bBase, int lane, int wm, int wn, float acc[2][8][4])
{
#pragma unroll
    for (int kk = 0; kk < 2; kk++) {
        uint32_t ah[2][4], al_[2][4];
        {
            int ar = lane & 15;
            int akc = ((lane >> 4) << 3) + (kk << 4);
#pragma unroll
            for (int i = 0; i < 2; i++) {
                uint32_t off = (uint32_t)((wm * 32 + i * 16 + ar) * SA + akc) * 2;
                ldsm4(ah[i][0], ah[i][1], ah[i][2], ah[i][3], aBase + F2_AH + off);
                ldsm4(al_[i][0], al_[i][1], al_[i][2], al_[i][3], aBase + F2_AL + off);
            }
        }
        uint32_t bh[8][2];
        {
            int br = (lane & 7) + ((lane >> 4) & 1) * 8;
            int bkb = ((lane >> 3) & 1) * 16 + kk * 32;
#pragma unroll
            for (int jf = 0; jf < 4; jf++) {
                uint32_t off = swz((uint32_t)((wn * 64 + jf * 16 + br) * 64 + bkb));
                uint32_t r0, r1, r2, r3;
                ldsm4(r0, r1, r2, r3, bBase + off);
                bh[2 * jf][0] = r0; bh[2 * jf][1] = r1;
                bh[2 * jf + 1][0] = r2; bh[2 * jf + 1][1] = r3;
            }
        }
#pragma unroll
        for (int i = 0; i < 2; i++)
#pragma unroll
            for (int j = 0; j < 8; j++)
                mma16816(acc[i][j], ah[i], bh[j]);
#pragma unroll
        for (int i = 0; i < 2; i++)
#pragma unroll
            for (int j = 0; j < 8; j++)
                mma16816(acc[i][j], al_[i], bh[j]);
    }
}

__device__ __forceinline__ void fused_epilogue_split(
    const float* bias, __half* Ch, __half* Cl,
    int m0, int n0, int lane, int wm, int wn, float acc[2][8][4])
{
#pragma unroll
    for (int i = 0; i < 2; i++) {
        int row = m0 + wm * 32 + i * 16 + (lane >> 2);
#pragma unroll
        for (int j = 0; j < 8; j++) {
            int col = n0 + wn * 64 + j * 8 + (lane & 3) * 2;
            float b0 = bias[col], b1 = bias[col + 1];
            float v0 = elu1(acc[i][j][0] + b0), v1 = elu1(acc[i][j][1] + b1);
            float v2 = elu1(acc[i][j][2] + b0), v3 = elu1(acc[i][j][3] + b1);
            size_t o0 = (size_t)row * HIDC + col;
            size_t o1 = (size_t)(row + 8) * HIDC + col;
            uint32_t hi, lo;
            cvt_split2(v0, v1, hi, lo);
            *reinterpret_cast<uint32_t*>(Ch + o0) = hi;
            *reinterpret_cast<uint32_t*>(Cl + o0) = lo;
            cvt_split2(v2, v3, hi, lo);
            *reinterpret_cast<uint32_t*>(Ch + o1) = hi;
            *reinterpret_cast<uint32_t*>(Cl + o1) = lo;
        }
    }
}

// ======== phi1-L1 GEMM with in-kernel split of fp32 peA ======================
#define P1A_SMEM F2_TOT
__global__ __launch_bounds__(256, 2) void gemm_phi1a(
    const float* __restrict__ peA,
    const __half* __restrict__ B,
    const float* __restrict__ bias,
    __half* __restrict__ Ch, __half* __restrict__ Cl)
{
    extern __shared__ __align__(1024) char smem[];
    const uint32_t sb = smem_u32(smem);
    const int tid = threadIdx.x;
    const int lane = tid & 31;
    const int wid = tid >> 5;
    const int wm = wid & 3;
    const int wn = wid >> 2;
    const int m0 = blockIdx.y * 128;
    const int n0 = blockIdx.x * 128;
    const int nch = KPAD1 >> 5;

    float acc[2][8][4] = {};
    float4 a_r[4];
    const int blr = tid >> 2;
    const int blc = tid & 3;

    auto issueB = [&](int ci, int s3) {
        const int k0 = ci << 5;
        const uint32_t so = sb + F2_BOFF + s3 * F2_BSTAGE;
#pragma unroll
        for (int j = 0; j < 2; j++) {
            int r = blr + j * 64;
            uint32_t d = swz((uint32_t)(r * 64 + blc * 16));
            CP16(so + d, B + (size_t)(n0 + r) * KPAD1 + k0 + blc * 8);
        }
        CP_COMMIT();
    };
    auto prefA = [&](int ci) {
        const int k0 = ci << 5;
#pragma unroll
        for (int j = 0; j < 4; j++) {
            int idx = tid + j * 256;
            int r = idx >> 3, c4 = idx & 7;
            int col = k0 + c4 * 4;
            const float* p = peA + (size_t)(m0 + r) * 514 + col;
            float4 v = make_float4(0.f, 0.f, 0.f, 0.f);
            if (col + 3 < 514) {
                float2 x = *reinterpret_cast<const float2*>(p);
                float2 y = *reinterpret_cast<const float2*>(p + 2);
                v = make_float4(x.x, x.y, y.x, y.y);
            } else {
                if (col + 0 < 514) v.x = p[0];
                if (col + 1 < 514) v.y = p[1];
                if (col + 2 < 514) v.z = p[2];
                if (col + 3 < 514) v.w = p[3];
            }
            a_r[j] = v;
        }
    };

    issueB(0, 0);
    issueB(1, 1);
    prefA(0);

    int s3 = 0;
    for (int ci = 0; ci < nch; ci++) {
        const int s2 = ci & 1;
        if (ci + 1 < nch) { CP_WAIT1(); } else { CP_WAIT0(); }
        __syncthreads();
        if (ci + 2 < nch) {
            int ns = s3 + 2; if (ns >= 3) ns -= 3;
            issueB(ci + 2, ns);
        }
#pragma unroll
        for (int j = 0; j < 4; j++) {
            int idx = tid + j * 256;
            int r = idx >> 3, c4 = idx & 7;
            uint32_t hh01, ll01, hh23, ll23;
            cvt_split2(a_r[j].x, a_r[j].y, hh01, ll01);
            cvt_split2(a_r[j].z, a_r[j].w, hh23, ll23);
            uint32_t o = (uint32_t)(r * SA + c4 * 4) * 2;
            *reinterpret_cast<uint2*>(smem + s2 * F2_ASTAGE + F2_AH + o) = make_uint2(hh01, hh23);
            *reinterpret_cast<uint2*>(smem + s2 * F2_ASTAGE + F2_AL + o) = make_uint2(ll01, ll23);
        }
        if (ci + 1 < nch) prefA(ci + 1);
        __syncthreads();
        fused_compute_chunk(sb + s2 * F2_ASTAGE, sb + F2_BOFF + s3 * F2_BSTAGE,
                            lane, wm, wn, acc);
        s3++; if (s3 == 3) s3 = 0;
    }

    fused_epilogue_split(bias, Ch, Cl, m0, n0, lane, wm, wn, acc);
}

// ======== alt2: dual-source GEMM =============================================
#define ALT2_KMP 8192
#define ALT2_SMEM (ALT2_KMP + F2_TOT)
__global__ __launch_bounds__(256, 2) void gemm_alt2(
    const float* __restrict__ pe,
    const __half* __restrict__ h1h, const __half* __restrict__ h1l,
    const float* __restrict__ kmP,
    const __half* __restrict__ B1, const __half* __restrict__ B2,
    __half* __restrict__ Ch, __half* __restrict__ Cl)
{
    extern __shared__ __align__(1024) char smem[];
    float* kmS = reinterpret_cast<float*>(smem);
    char* sdata = smem + ALT2_KMP;
    const uint32_t sb = smem_u32(smem) + ALT2_KMP;
    const int tid = threadIdx.x;
    const int lane = tid & 31;
    const int wid = tid >> 5;
    const int wm = wid & 3;
    const int wn = wid >> 2;
    const int m0 = blockIdx.y * 128;
    const int n0 = blockIdx.x * 128;
    const int nch = 24;   // 16 pe + 8 h1

    float acc[2][8][4] = {};
    float4 a_r[4];
    const int blr = tid >> 2;
    const int blc = tid & 3;

    auto issueB = [&](int ci, int s3) {
        const uint32_t so = sb + F2_BOFF + s3 * F2_BSTAGE;
#pragma unroll
        for (int j = 0; j < 2; j++) {
            int r = blr + j * 64;
            uint32_t d = swz((uint32_t)(r * 64 + blc * 16));
            if (ci < 16)
                CP16(so + d, B1 + (size_t)(n0 + r) * 512 + (ci << 5) + blc * 8);
            else
                CP16(so + d, B2 + (size_t)(n0 + r) * 256 + ((ci - 16) << 5) + blc * 8);
        }
        CP_COMMIT();
    };
    auto prefA = [&](int ci) {
#pragma unroll
        for (int j = 0; j < 4; j++) {
            int idx = tid + j * 256;
            int r = idx >> 3, c4 = idx & 7;
            if (ci < 16) {
                size_t ao = (size_t)(m0 + r) * 512 + (ci << 5) + c4 * 4;
                a_r[j] = *reinterpret_cast<const float4*>(pe + ao);
            } else {
                size_t ao = (size_t)(m0 + r) * 256 + ((ci - 16) << 5) + c4 * 4;
                uint2 vh = *reinterpret_cast<const uint2*>(h1h + ao);
                uint2 vl = *reinterpret_cast<const uint2*>(h1l + ao);
                a_r[j] = make_float4(__uint_as_float(vh.x), __uint_as_float(vh.y),
                                     __uint_as_float(vl.x), __uint_as_float(vl.y));
            }
        }
    };

    const int g0 = m0 >> 4;
    for (int i = tid; i < 2048; i += 256)
        kmS[i] = kmP[(size_t)(g0 + (i >> 8)) * 256 + (i & 255)];

    issueB(0, 0);
    issueB(1, 1);
    prefA(0);

    int s3 = 0;
    for (int ci = 0; ci < nch; ci++) {
        const int s2 = ci & 1;
        if (ci + 1 < nch) { CP_WAIT1(); } else { CP_WAIT0(); }
        __syncthreads();
        if (ci + 2 < nch) {
            int ns = s3 + 2; if (ns >= 3) ns -= 3;
            issueB(ci + 2, ns);
        }
        const bool cvt = (ci < 16);
#pragma unroll
        for (int j = 0; j < 4; j++) {
            int idx = tid + j * 256;
            int r = idx >> 3, c4 = idx & 7;
            uint32_t hh01, ll01, hh23, ll23;
            if (cvt) {
                cvt_split2(a_r[j].x, a_r[j].y, hh01, ll01);
                cvt_split2(a_r[j].z, a_r[j].w, hh23, ll23);
            } else {
                hh01 = __float_as_uint(a_r[j].x);
                hh23 = __float_as_uint(a_r[j].y);
                ll01 = __float_as_uint(a_r[j].z);
                ll23 = __float_as_uint(a_r[j].w);
            }
            uint32_t o = (uint32_t)(r * SA + c4 * 4) * 2;
            *reinterpret_cast<uint2*>(sdata + s2 * F2_ASTAGE + F2_AH + o) = make_uint2(hh01, hh23);
            *reinterpret_cast<uint2*>(sdata + s2 * F2_ASTAGE + F2_AL + o) = make_uint2(ll01, ll23);
        }
        if (ci + 1 < nch) prefA(ci + 1);
        __syncthreads();
        fused_compute_chunk(sb + s2 * F2_ASTAGE, sb + F2_BOFF + s3 * F2_BSTAGE,
                            lane, wm, wn, acc);
        s3++; if (s3 == 3) s3 = 0;
    }

    // epilogue: per-group kmP bias + elu + split store
#pragma unroll
    for (int i = 0; i < 2; i++) {
        int rl = wm * 32 + i * 16 + (lane >> 2);
        int row = m0 + rl;
#pragma unroll
        for (int j = 0; j < 8; j++) {
            int col = n0 + wn * 64 + j * 8 + (lane & 3) * 2;
            float b0a = kmS[(rl >> 4) * 256 + col];
            float b1a = kmS[(rl >> 4) * 256 + col + 1];
            float b0b = kmS[((rl + 8) >> 4) * 256 + col];
            float b1b = kmS[((rl + 8) >> 4) * 256 + col + 1];
            float v0 = elu1(acc[i][j][0] + b0a), v1 = elu1(acc[i][j][1] + b1a);
            float v2 = elu1(acc[i][j][2] + b0b), v3 = elu1(acc[i][j][3] + b1b);
            size_t o0 = (size_t)row * HIDC + col;
            size_t o1 = (size_t)(row + 8) * HIDC + col;
            uint32_t hi, lo;
            cvt_split2(v0, v1, hi, lo);
            *reinterpret_cast<uint32_t*>(Ch + o0) = hi;
            *reinterpret_cast<uint32_t*>(Cl + o0) = lo;
            cvt_split2(v2, v3, hi, lo);
            *reinterpret_cast<uint32_t*>(Ch + o1) = hi;
            *reinterpret_cast<uint32_t*>(Cl + o1) = lo;
        }
    }
}

// ---------------- multi-segment weight convert (single fp16, one launch) ----
#define MAXSEG 9
struct ConvSegs {
    const float* src[MAXSEG];
    int dstoff[MAXSEG];
    int C[MAXSEG];
    int Cp[MAXSEG];
    int rows[MAXSEG];
    int n;
};
__global__ __launch_bounds__(256) void conv_multi(
    ConvSegs p, __half* __restrict__ dst)
{
    const uint32_t stride = gridDim.x * 256u;
    const uint32_t base = blockIdx.x * 256u + threadIdx.x;
    for (int s = 0; s < p.n; s++) {
        const float* src = p.src[s];
        const int C = p.C[s], Cp = p.Cp[s], off = p.dstoff[s];
        const uint32_t tot = (uint32_t)p.rows[s] * Cp;
        for (uint32_t i = base; i < tot; i += stride) {
            uint32_t r = i / (uint32_t)Cp;
            int c = (int)(i - r * (uint32_t)Cp);
            float v = (c < C) ? src[(size_t)r * C + c] : 0.f;
            dst[off + i] = __float2half(v);
        }
    }
}

// ---------------- compose all: {Wqk, Wv01, P2W1} x W4 -----------------------
__global__ __launch_bounds__(256) void compose_all(
    const float* __restrict__ wqk, const float* __restrict__ wv01,
    const float* __restrict__ p2w1, const float* __restrict__ w4,
    const float* __restrict__ b4, const float* __restrict__ battn,
    const float* __restrict__ p2b1,
    __half* __restrict__ wp,
    float* __restrict__ bc, float* __restrict__ bv2, float* __restrict__ bb)
{
    __shared__ float wrow[512];
    const int blk = blockIdx.x;
    const int tid = threadIdx.x;
    const float* src;
    const float* bin;
    float* bout;
    float scale;
    int outoff, n;
    if (blk < 1024)      { src = wqk;  n = blk;        scale = 1.f;      outoff = OW_WC;  bin = battn;        bout = bc;  }
    else if (blk < 1536) { src = wv01; n = blk - 1024; scale = 1.f;      outoff = OW_WVC; bin = battn + 1024; bout = bv2; }
    else                 { src = p2w1; n = blk - 1536; scale = -0.0625f; outoff = OW_WC3; bin = p2b1;         bout = bb;  }
    wrow[tid] = src[(size_t)n * 512 + tid];
    wrow[tid + 256] = src[(size_t)n * 512 + tid + 256];
    __syncthreads();
    float acc = 0.f;
#pragma unroll 8
    for (int j = 0; j < 512; j++)
        acc += wrow[j] * w4[(size_t)j * 256 + tid];
    wp[outoff + (size_t)n * 256 + tid] = __float2half(acc * scale);
    if (tid < 32) {
        float s = 0.f;
        for (int j = tid; j < 512; j += 32) s += wrow[j] * b4[j];
#pragma unroll
        for (int o = 16; o > 0; o >>= 1) s += __shfl_xor_sync(0xffffffffu, s, o);
        if (tid == 0) bout[n] = s * scale + bin[n];
    }
}

// ---------------- zero output ----------------
__global__ __launch_bounds__(256) void zero_out(float* __restrict__ p, int n) {
    int i = blockIdx.x * 256 + threadIdx.x;
    if (i < n) p[i] = 0.f;
}

// ---------------- attention v4: mma scores, h1-based hw ---------------------
#define AROW 1032
__global__ __launch_bounds__(256) void attn4_kernel(
    const __half* __restrict__ qk,
    const __half* __restrict__ h1h, const __half* __restrict__ h1l,
    __half* __restrict__ hwh, __half* __restrict__ hwl)
{
    const int g = blockIdx.x;
    const int tid = threadIdx.x;
    const int lane = tid & 31;
    const int wid = tid >> 5;
    __shared__ __align__(16) __half qks[16 * AROW];
    __shared__ float sc[2][16][17];
    __shared__ float cw[2][16];
    const uint32_t sbq = smem_u32(qks);

    {
        const uint4* src = reinterpret_cast<const uint4*>(qk + (size_t)g * GSZ * 1024);
#pragma unroll
        for (int t = 0; t < 8; t++) {
            int idx = tid + t * 256;
            int row = idx >> 7;
            int c8 = idx & 127;
            *reinterpret_cast<uint4*>(qks + row * AROW + c8 * 8) = src[idx];
        }
    }
    __syncthreads();

    if (wid < 2) {
        const int h = wid;
        float accS[2][4] = {};
        const uint32_t qb = (uint32_t)(h * 256) * 2;
        const uint32_t kb = (uint32_t)(512 + h * 256) * 2;
#pragma unroll
        for (int ks = 0; ks < 16; ks++) {
            uint32_t a[4];
            {
                int ar = lane & 15;
                uint32_t addr = sbq + (uint32_t)(ar * AROW) * 2 + qb + ks * 32 + (lane >> 4) * 16;
                ldsm4(a[0], a[1], a[2], a[3], addr);
            }
            uint32_t b0[2], b1[2];
            {
                int br = (lane & 7) + ((lane >> 4) & 1) * 8;
                uint32_t addr = sbq + (uint32_t)(br * AROW) * 2 + kb + ks * 32 + ((lane >> 3) & 1) * 16;
                uint32_t r0, r1, r2, r3;
                ldsm4(r0, r1, r2, r3, addr);
                b0[0] = r0; b0[1] = r1;
                b1[0] = r2; b1[1] = r3;
            }
            mma16816(accS[0], a, b0);
            mma16816(accS[1], a, b1);
        }
        {
            int row = lane >> 2;
            int col = (lane & 3) * 2;
#pragma unroll
            for (int j = 0; j < 2; j++) {
                sc[h][row][j * 8 + col]     = accS[j][0] * 0.0625f;
                sc[h][row][j * 8 + col + 1] = accS[j][1] * 0.0625f;
                sc[h][row + 8][j * 8 + col]     = accS[j][2] * 0.0625f;
                sc[h][row + 8][j * 8 + col + 1] = accS[j][3] * 0.0625f;
            }
        }
    }
    __syncthreads();

    if (tid < 32) {
        int h = tid >> 4, tq = tid & 15;
        float mx = -1e30f;
#pragma unroll
        for (int tk = 0; tk < 16; tk++) mx = fmaxf(mx, sc[h][tq][tk]);
        float s = 0.f;
#pragma unroll
        for (int tk = 0; tk < 16; tk++) {
            float e = expf(sc[h][tq][tk] - mx);
            sc[h][tq][tk] = e;
            s += e;
        }
        float inv = 1.f / s;
#pragma unroll
        for (int tk = 0; tk < 16; tk++) sc[h][tq][tk] *= inv;
    }
    __syncthreads();
    if (tid < 32) {
        int h = tid >> 4, tk = tid & 15;
        float s = 0.f;
#pragma unroll
        for (int tq = 0; tq < 16; tq++) s += sc[h][tq][tk];
        cw[h][tk] = s * 0.0625f;
    }
    __syncthreads();

    if (tid < 128) {
        int d2 = tid * 2;
        const __half* xbh = h1h + (size_t)g * GSZ * 256 + d2;
        const __half* xbl = h1l + (size_t)g * GSZ * 256 + d2;
        float a0[2] = {}, a1[2] = {};
#pragma unroll
        for (int tk = 0; tk < 16; tk++) {
            uint32_t vh = *reinterpret_cast<const uint32_t*>(xbh + tk * 256);
            uint32_t vl = *reinterpret_cast<const uint32_t*>(xbl + tk * 256);
            float2 hh = h2f2(vh), ll = h2f2(vl);
            float x0 = hh.x + ll.x, x1 = hh.y + ll.y;
            float w0 = cw[0][tk], w1 = cw[1][tk];
            a0[0] += w0 * x0; a0[1] += w0 * x1;
            a1[0] += w1 * x0; a1[1] += w1 * x1;
        }
        uint32_t hi, lo;
        size_t o0 = (size_t)g * HIDC + d2;
        cvt_split2(a0[0], a0[1], hi, lo);
        *reinterpret_cast<uint32_t*>(hwh + o0) = hi;
        *reinterpret_cast<uint32_t*>(hwl + o0) = lo;
        size_t o1 = (size_t)NGR * HIDC + o0;
        cvt_split2(a1[0], a1[1], hi, lo);
        *reinterpret_cast<uint32_t*>(hwh + o1) = hi;
        *reinterpret_cast<uint32_t*>(hwl + o1) = lo;
    }
}

// ================================================================ host launch
extern "C" void kernel_launch(void* const* d_in, const int* in_sizes, int n_in,
                              void* d_out, int out_size)
{
    const float* pe       = (const float*)d_in[0];
    const float* peA      = (const float*)d_in[1];
    const float* attn_in_w  = (const float*)d_in[2];
    const float* attn_in_b  = (const float*)d_in[3];
    const float* attn_out_w = (const float*)d_in[4];
    const float* attn_out_b = (const float*)d_in[5];
    const float* p1w1 = (const float*)d_in[6];  const float* p1b1 = (const float*)d_in[7];
    const float* p1w2 = (const float*)d_in[8];  const float* p1b2 = (const float*)d_in[9];
    const float* p1w3 = (const float*)d_in[10]; const float* p1b3 = (const float*)d_in[11];
    const float* p1w4 = (const float*)d_in[12]; const float* p1b4 = (const float*)d_in[13];
    const float* gw1 = (const float*)d_in[14];  const float* gb1 = (const float*)d_in[15];
    const float* gw2 = (const float*)d_in[16];  const float* gb2 = (const float*)d_in[17];
    const float* gw3 = (const float*)d_in[18];  const float* gb3 = (const float*)d_in[19];
    const float* gw4 = (const float*)d_in[20];  const float* gb4 = (const float*)d_in[21];
    const float* p2w1 = (const float*)d_in[22]; const float* p2b1 = (const float*)d_in[23];
    const float* p2w2 = (const float*)d_in[24]; const float* p2b2 = (const float*)d_in[25];
    const float* p2w3 = (const float*)d_in[26]; const float* p2b3 = (const float*)d_in[27];
    float* out = (float*)d_out;

    #define SYM(T, v, s) T* v; cudaGetSymbolAddress((void**)&v, s)
    SYM(__half, h1h, g_h1h);   SYM(__half, h1l, g_h1l);
    SYM(__half, h2h, g_h2h);   SYM(__half, h2l, g_h2l);
    SYM(__half, qk, g_qk);
    SYM(__half, xwh, g_xwh);   SYM(__half, xwl, g_xwl);
    SYM(__half, omh, g_omh);   SYM(__half, oml, g_oml);
    SYM(float, km, g_km);
    SYM(__half, kmh, g_kmh);   SYM(__half, kml, g_kml);
    SYM(float, kmpf, g_kmp);
    SYM(__half, hgah, g_hgah); SYM(__half, hgal, g_hgal);
    SYM(__half, hgbh, g_hgbh); SYM(__half, hgbl, g_hgbl);
    SYM(__half, wp, g_wp);
    SYM(float, bc, g_bc);
    SYM(float, bv2, g_bv2);
    SYM(float, bb, g_bb);

    cudaFuncSetAttribute(gemm_2p<1,false,true>, cudaFuncAttributeMaxDynamicSharedMemorySize, SMEM_TOT);
    cudaFuncSetAttribute(gemm_2p<2,false,true>, cudaFuncAttributeMaxDynamicSharedMemorySize, SMEM_TOT);
    cudaFuncSetAttribute(gemm_2p<0,false,true>, cudaFuncAttributeMaxDynamicSharedMemorySize, SMEM_TOT);
    cudaFuncSetAttribute(gemm_2p<0,true,true>,  cudaFuncAttributeMaxDynamicSharedMemorySize, SMEM_TOT);
    cudaFuncSetAttribute(gemm_2p<0,true,false>, cudaFuncAttributeMaxDynamicSharedMemorySize, SMEM_TOT);
    cudaFuncSetAttribute(gemm_dot<1>, cudaFuncAttributeMaxDynamicSharedMemorySize, SMEM_TOT);
    cudaFuncSetAttribute(gemm_dot<2>, cudaFuncAttributeMaxDynamicSharedMemorySize, SMEM_TOT);
    cudaFuncSetAttribute(gemm_qk1p, cudaFuncAttributeMaxDynamicSharedMemorySize, QSMEM);
    cudaFuncSetAttribute(gemm_phi1a, cudaFuncAttributeMaxDynamicSharedMemorySize, P1A_SMEM);
    cudaFuncSetAttribute(gemm_alt2, cudaFuncAttributeMaxDynamicSharedMemorySize, ALT2_SMEM);

    const int TB = 256;
    #define GRID(Mv, Nv) dim3((Nv) / 128, (Mv) / 128)

    // #1: zero the output
    zero_out<<<(out_size + 255) / 256, TB>>>(out, out_size);

    // #2: phi1 weight converts
    {
        ConvSegs s = {};
        int n = 0;
        auto add = [&](const float* src, int off, int R, int C, int Cp) {
            s.src[n] = src; s.dstoff[n] = off; s.rows[n] = R; s.C[n] = C; s.Cp[n] = Cp; n++;
        };
        add(p1w1, OW_P1W1, 256, 514, KPAD1);
        add(p1w2, OW_P1W2, 256, 256, 256);
        add(p1w3, OW_P1W3, 256, 256, 256);
        s.n = n;
        conv_multi<<<512, TB>>>(s, wp);
    }
    // #3: remaining weight converts
    {
        ConvSegs s = {};
        int n = 0;
        auto add = [&](const float* src, int off, int R, int C, int Cp) {
            s.src[n] = src; s.dstoff[n] = off; s.rows[n] = R; s.C[n] = C; s.Cp[n] = Cp; n++;
        };
        add(attn_out_w, OW_WOUT, 512, 512, 512);
        add(gw1, OW_GW1, 256, 512, 512);
        add(gw2, OW_GW2, 256, 256, 256);
        add(gw3, OW_GW3, 256, 256, 256);
        add(p2w1, OW_P2W1, 256, 512, 512);
        add(p2w2, OW_P2W2, 256, 256, 256);
        s.n = n;
        conv_multi<<<512, TB>>>(s, wp);
    }

    // #4: phi1 L1 (profiled)
    gemm_phi1a<<<GRID(NTOK, 256), TB, P1A_SMEM>>>(
        peA, wp + OW_P1W1, p1b1, h1h, h1l);

    // #5: compose Wc, WVc, Wc3m + biases
    compose_all<<<1792, TB>>>(attn_in_w, attn_in_w + (size_t)1024 * 512, p2w1,
                              p1w4, p1b4, attn_in_b, p2b1,
                              wp, bc, bv2, bb);

    // phi1 chain (cont.)
    gemm_2p<2,false,true><<<GRID(NTOK, HIDC), TB, SMEM_TOT>>>(
        h1h, h1l, wp + OW_P1W2, p1b2, nullptr, h2h, h2l, HIDC, HIDC);
    gemm_2p<1,false,true><<<GRID(NTOK, HIDC), TB, SMEM_TOT>>>(
        h2h, h2l, wp + OW_P1W3, p1b3, nullptr, h1h, h1l, HIDC, HIDC);

    // qk = h1 @ Wc^T + bc (single-pass fp16, K=256)
    gemm_qk1p<<<GRID(NTOK, 1024), TB, QSMEM>>>(
        h1h, wp + OW_WC, bc, qk, HIDC, 1024);
    // attention -> hw (per head, 256-dim)
    attn4_kernel<<<NGR, TB>>>(qk, h1h, h1l, xwh, xwl);
    // o_mean per head via composed WVc (K=256)
    gemm_2p<0,false,true><<<GRID(NGR, 256), TB, SMEM_TOT>>>(
        xwh, xwl, wp + OW_WVC, bv2, nullptr, omh, oml, HIDC, EFULL);
    gemm_2p<0,false,true><<<GRID(NGR, 256), TB, SMEM_TOT>>>(
        xwh + (size_t)NGR * HIDC, xwl + (size_t)NGR * HIDC,
        wp + OW_WVC + 65536, bv2 + 256, nullptr, omh + 256, oml + 256, HIDC, EFULL);
    // km = omean @ Wo^T + bo
    gemm_2p<0,true,true><<<GRID(NGR, EFULL), TB, SMEM_TOT>>>(
        omh, oml, wp + OW_WOUT, attn_out_b, km, kmh, kml, EFULL, EFULL);
    // kmP = km @ P2W1^T + bb
    gemm_2p<0,true,false><<<GRID(NGR, 256), TB, SMEM_TOT>>>(
        kmh, kml, wp + OW_P2W1, bb, kmpf, nullptr, nullptr, EFULL, HIDC);

    // g head -> q_jt at out[0 .. 4096)
    gemm_2p<1,false,true><<<GRID(NGR, HIDC), TB, SMEM_TOT>>>(
        kmh, kml, wp + OW_GW1, gb1, nullptr, hgah, hgal, EFULL, HIDC);
    gemm_2p<1,false,true><<<GRID(NGR, HIDC), TB, SMEM_TOT>>>(
        hgah, hgal, wp + OW_GW2, gb2, nullptr, hgbh, hgbl, HIDC, HIDC);
    gemm_dot<1><<<GRID(NGR, HIDC), TB, SMEM_TOT>>>(
        hgbh, hgbl, wp + OW_GW3, gb3, gw4, gb4, out, HIDC);

    // alt path: hp = elu(pe@P2W1^T + h1@Wc3m^T + kmP[g]) -> p2w2 + dot
    gemm_alt2<<<GRID(NTOK, 256), TB, ALT2_SMEM>>>(
        pe, h1h, h1l, kmpf, wp + OW_P2W1, wp + OW_WC3, h2h, h2l);
    gemm_dot<2><<<GRID(NTOK, HIDC), TB, SMEM_TOT>>>(
        h2h, h2l, wp + OW_P2W2, p2b2, p2w3, p2b3, out + NGR, HIDC);
}